// round 2
// baseline (speedup 1.0000x reference)
#include <cuda_runtime.h>
#include <math.h>

#define BB 2
#define TT 2048
#define DD 3584
#define NHE 16
#define KHE 8
#define HDIM 256
#define WIN 1024
#define SCALE_F 0.0625f

__device__ float g_q[(size_t)BB * TT * NHE * HDIM];
__device__ float g_k[(size_t)BB * TT * KHE * HDIM];
__device__ float g_v[(size_t)BB * TT * KHE * HDIM];
__device__ float g_enc[(size_t)BB * TT * NHE * HDIM];
__device__ float g_ts[HDIM / 2];

__device__ __forceinline__ float tanh_acc(float x) {
    float ax = fabsf(x);
    float e  = __expf(2.0f * ax);
    float r  = 1.0f - 2.0f / (e + 1.0f);
    return x < 0.0f ? -r : r;
}

__global__ void ts_kernel() {
    int i = threadIdx.x;
    if (i < HDIM / 2)
        g_ts[i] = (float)pow(10000.0, (double)i / 128.0);
}

__global__ void rope_kernel(float* __restrict__ buf,
                            const int* __restrict__ segpos,
                            int heads, float scale, int total) {
    int idx = blockIdx.x * 256 + threadIdx.x;
    if (idx >= total) return;
    int i = idx & 127;
    int rest = idx >> 7;
    int head = rest % heads;
    int bt = rest / heads;
    int pos = segpos[bt];
    float ts = g_ts[i];
    float angf = __fdiv_rn((float)pos, ts);
    double sd, cd;
    sincos((double)angf, &sd, &cd);
    float s = (float)sd, c = (float)cd;
    float* p = buf + ((size_t)bt * heads + head) * HDIM;
    float first = p[i], second = p[i + 128];
    p[i]       = (first * c - second * s) * scale;
    p[i + 128] = (second * c + first * s) * scale;
}

__global__ void __launch_bounds__(256) gemm64_kernel(
    const float* __restrict__ A, int lda,
    const float* __restrict__ B, long long bStride, int ldb,
    float* __restrict__ C, long long cStride, int ldc,
    int Kd)
{
    __shared__ float As[16][65];
    __shared__ float Bs[16][64];

    const float* Bp = B + (long long)blockIdx.z * bStride;
    float* Cp = C + (long long)blockIdx.z * cStride;
    const int row0 = blockIdx.y * 64;
    const int col0 = blockIdx.x * 64;
    const int tid = threadIdx.x;
    const int ty = tid >> 4, tx = tid & 15;
    const int arow = tid >> 2, acol = (tid & 3) << 2;
    const int brow = tid >> 4, bcol = (tid & 15) << 2;

    const float* Ap  = A  + (long long)(row0 + arow) * lda + acol;
    const float* Bpp = Bp + (long long)brow * ldb + col0 + bcol;

    float acc[4][4];
#pragma unroll
    for (int i = 0; i < 4; i++)
#pragma unroll
        for (int j = 0; j < 4; j++) acc[i][j] = 0.0f;

    for (int k0 = 0; k0 < Kd; k0 += 16) {
        float4 av = *(const float4*)Ap;
        float4 bv = *(const float4*)Bpp;
        As[acol + 0][arow] = av.x;
        As[acol + 1][arow] = av.y;
        As[acol + 2][arow] = av.z;
        As[acol + 3][arow] = av.w;
        *(float4*)&Bs[brow][bcol] = bv;
        __syncthreads();
#pragma unroll
        for (int kk = 0; kk < 16; kk++) {
            float a0 = As[kk][ty * 4 + 0];
            float a1 = As[kk][ty * 4 + 1];
            float a2 = As[kk][ty * 4 + 2];
            float a3 = As[kk][ty * 4 + 3];
            float4 b = *(const float4*)&Bs[kk][tx * 4];
            acc[0][0] += a0 * b.x; acc[0][1] += a0 * b.y; acc[0][2] += a0 * b.z; acc[0][3] += a0 * b.w;
            acc[1][0] += a1 * b.x; acc[1][1] += a1 * b.y; acc[1][2] += a1 * b.z; acc[1][3] += a1 * b.w;
            acc[2][0] += a2 * b.x; acc[2][1] += a2 * b.y; acc[2][2] += a2 * b.z; acc[2][3] += a2 * b.w;
            acc[3][0] += a3 * b.x; acc[3][1] += a3 * b.y; acc[3][2] += a3 * b.z; acc[3][3] += a3 * b.w;
        }
        __syncthreads();
        Ap += 16;
        Bpp += (long long)16 * ldb;
    }
#pragma unroll
    for (int i = 0; i < 4; i++) {
        float4 o = make_float4(acc[i][0], acc[i][1], acc[i][2], acc[i][3]);
        *(float4*)&Cp[(long long)(row0 + ty * 4 + i) * ldc + col0 + tx * 4] = o;
    }
}

#define BQ 32
#define BK 32
#define QK_PAD 260
#define SPAD 36

__device__ __forceinline__ void put_score(float* s_s, const int* posq_s,
                                          const int* posk_s, int tq0, int s0,
                                          int qr, int jr, float dot) {
    float sc = tanh_acc(dot * (1.0f / 50.0f)) * 50.0f;
    int ti = tq0 + qr, si = s0 + jr;
    int pq = posq_s[qr], pk = posk_s[jr];
    bool valid = (si <= ti) && (pk > pq - WIN) && (pk < pq + WIN);
    s_s[qr * SPAD + jr] = valid ? sc : -1e30f;
}

__device__ __forceinline__ const float* kv_base(const float* p, int b, int s0, int kh) {
    return p + (((long long)b * TT + s0) * KHE + kh) * HDIM;
}

__global__ void __launch_bounds__(256) attn_kernel(
    const float* __restrict__ q, const float* __restrict__ k,
    const float* __restrict__ v, const int* __restrict__ segpos,
    float* __restrict__ enc)
{
    extern __shared__ float sm[];
    float* q_s = sm;
    float* k_s = q_s + BQ * QK_PAD;
    float* v_s = k_s + BK * QK_PAD;
    float* s_s = v_s + BK * HDIM;
    int* posq_s = (int*)(s_s + BQ * SPAD);
    int* posk_s = posq_s + BQ;

    const int tile = (gridDim.x - 1) - blockIdx.x;
    const int n = blockIdx.y;
    const int b = blockIdx.z;
    const int kh = n >> 1;
    const int tq0 = tile * BQ;
    const int tid = threadIdx.x;

    const float* qbase = q + (((long long)b * TT + tq0) * NHE + n) * HDIM;
    for (int i = tid; i < BQ * (HDIM / 4); i += 256) {
        int r = i >> 6, c = (i & 63) << 2;
        *(float4*)&q_s[r * QK_PAD + c] =
            *(const float4*)&qbase[(long long)r * NHE * HDIM + c];
    }
    if (tid < BQ) posq_s[tid] = segpos[b * TT + tq0 + tid];

    const int qi = tid >> 3, gi = tid & 7;
    const int qg = tid >> 4, jg = tid & 15;

    float m_run = -1e30f, l_run = 0.0f;
    float acc[32];
#pragma unroll
    for (int c = 0; c < 32; c++) acc[c] = 0.0f;

    int s_begin = tq0 - (WIN - 1);
    if (s_begin < 0) s_begin = 0;
    s_begin &= ~(BK - 1);
    const int s_end = tq0 + BQ;

    for (int s0 = s_begin; s0 < s_end; s0 += BK) {
        __syncthreads();
        const float* kbase = kv_base(k, b, s0, kh);
        const float* vbase = kv_base(v, b, s0, kh);
        for (int i = tid; i < BK * (HDIM / 4); i += 256) {
            int r = i >> 6, c = (i & 63) << 2;
            *(float4*)&k_s[r * QK_PAD + c] =
                *(const float4*)&kbase[(long long)r * KHE * HDIM + c];
            *(float4*)&v_s[r * HDIM + c] =
                *(const float4*)&vbase[(long long)r * KHE * HDIM + c];
        }
        if (tid < BK) posk_s[tid] = segpos[b * TT + s0 + tid];
        __syncthreads();

        float d00 = 0.f, d01 = 0.f, d10 = 0.f, d11 = 0.f;
        const float* qa = q_s + qg * QK_PAD;
        const float* qb = q_s + (qg + 16) * QK_PAD;
        const float* ka = k_s + jg * QK_PAD;
        const float* kb = k_s + (jg + 16) * QK_PAD;
#pragma unroll 16
        for (int d = 0; d < HDIM; d += 4) {
            float4 a0 = *(const float4*)(qa + d);
            float4 a1 = *(const float4*)(qb + d);
            float4 b0 = *(const float4*)(ka + d);
            float4 b1 = *(const float4*)(kb + d);
            d00 += a0.x * b0.x + a0.y * b0.y + a0.z * b0.z + a0.w * b0.w;
            d01 += a0.x * b1.x + a0.y * b1.y + a0.z * b1.z + a0.w * b1.w;
            d10 += a1.x * b0.x + a1.y * b0.y + a1.z * b0.z + a1.w * b0.w;
            d11 += a1.x * b1.x + a1.y * b1.y + a1.z * b1.z + a1.w * b1.w;
        }
        put_score(s_s, posq_s, posk_s, tq0, s0, qg,      jg,      d00);
        put_score(s_s, posq_s, posk_s, tq0, s0, qg,      jg + 16, d01);
        put_score(s_s, posq_s, posk_s, tq0, s0, qg + 16, jg,      d10);
        put_score(s_s, posq_s, posk_s, tq0, s0, qg + 16, jg + 16, d11);
        __syncthreads();

        float mx = m_run;
#pragma unroll
        for (int j = 0; j < BK; j++) mx = fmaxf(mx, s_s[qi * SPAD + j]);
        float corr = __expf(m_run - mx);
        l_run *= corr;
#pragma unroll
        for (int c = 0; c < 32; c++) acc[c] *= corr;
        float psum = 0.0f;
#pragma unroll
        for (int j = 0; j < BK; j++) {
            float sv = s_s[qi * SPAD + j];
            float pj = (sv < -1e29f) ? 0.0f : __expf(sv - mx);
            psum += pj;
            const float* vr = v_s + j * HDIM + gi * 4;
#pragma unroll
            for (int i8 = 0; i8 < 8; i8++) {
                float4 vv = *(const float4*)(vr + i8 * 32);
                acc[i8 * 4 + 0] += pj * vv.x;
                acc[i8 * 4 + 1] += pj * vv.y;
                acc[i8 * 4 + 2] += pj * vv.z;
                acc[i8 * 4 + 3] += pj * vv.w;
            }
        }
        l_run += psum;
        m_run = mx;
    }

    float invl = 1.0f / l_run;
    float* obase = enc + (((long long)b * TT + tq0 + qi) * NHE + n) * HDIM + gi * 4;
#pragma unroll
    for (int i8 = 0; i8 < 8; i8++) {
        float4 o = make_float4(acc[i8 * 4 + 0] * invl, acc[i8 * 4 + 1] * invl,
                               acc[i8 * 4 + 2] * invl, acc[i8 * 4 + 3] * invl);
        *(float4*)(obase + i8 * 32) = o;
    }
}

extern "C" void kernel_launch(void* const* d_in, const int* in_sizes, int n_in,
                              void* d_out, int out_size)
{
    const float* x      = (const float*)d_in[0];
    const int*   segpos = (const int*)d_in[1];
    const float* q_w    = (const float*)d_in[3];
    const float* kv_w   = (const float*)d_in[4];
    const float* out_w  = (const float*)d_in[5];
    float* out = (float*)d_out;

    float *qbuf, *kbuf, *vbuf, *encbuf;
    cudaGetSymbolAddress((void**)&qbuf,   g_q);
    cudaGetSymbolAddress((void**)&kbuf,   g_k);
    cudaGetSymbolAddress((void**)&vbuf,   g_v);
    cudaGetSymbolAddress((void**)&encbuf, g_enc);

    const int ATTN_SMEM = (BQ * QK_PAD + BK * QK_PAD + BK * HDIM + BQ * SPAD) * 4
                        + (BQ + BK) * 4;
    cudaFuncSetAttribute(attn_kernel,
                         cudaFuncAttributeMaxDynamicSharedMemorySize, ATTN_SMEM);

    const int M = BB * TT;

    gemm64_kernel<<<dim3(HDIM / 64, M / 64, NHE), 256>>>(
        x, DD, q_w, (long long)DD * HDIM, HDIM,
        qbuf, HDIM, NHE * HDIM, DD);
    gemm64_kernel<<<dim3(HDIM / 64, M / 64, KHE), 256>>>(
        x, DD, kv_w, (long long)DD * HDIM, HDIM,
        kbuf, HDIM, KHE * HDIM, DD);
    gemm64_kernel<<<dim3(HDIM / 64, M / 64, KHE), 256>>>(
        x, DD, kv_w + (long long)KHE * DD * HDIM, (long long)DD * HDIM, HDIM,
        vbuf, HDIM, KHE * HDIM, DD);

    ts_kernel<<<1, 128>>>();
    {
        int totq = BB * TT * NHE * (HDIM / 2);
        rope_kernel<<<totq / 256, 256>>>(qbuf, segpos, NHE, SCALE_F, totq);
        int totk = BB * TT * KHE * (HDIM / 2);
        rope_kernel<<<totk / 256, 256>>>(kbuf, segpos, KHE, 1.0f, totk);
    }

    attn_kernel<<<dim3(TT / BQ, NHE, BB), 256, ATTN_SMEM>>>(
        qbuf, kbuf, vbuf, segpos, encbuf);

    gemm64_kernel<<<dim3(DD / 64, M / 64, 1), 256>>>(
        encbuf, NHE * HDIM, out_w, 0, DD,
        out, 0, DD, (long long)NHE * HDIM);
}

// round 5
// speedup vs baseline: 2.1911x; 2.1911x over previous
#include <cuda_runtime.h>
#include <cuda_bf16.h>
#include <math.h>
#include <stdint.h>

#define BB 2
#define TT 2048
#define DD 3584
#define NHE 16
#define KHE 8
#define HDIM 256
#define WIN 1024
#define SCALE_F 0.0625f
#define MTOT (BB*TT)         /* 4096 */
#define QSTR 8192            /* row stride of fused qkv buffer */

/* ---------------- device globals (no allocations allowed) ---------------- */
__device__ __align__(128) __nv_bfloat16 g_wt_h[(size_t)8192 * DD];
__device__ __align__(128) __nv_bfloat16 g_wt_l[(size_t)8192 * DD];
__device__ __align__(128) __nv_bfloat16 g_owt_h[(size_t)DD * 4096];
__device__ __align__(128) __nv_bfloat16 g_owt_l[(size_t)DD * 4096];
__device__ __align__(128) __nv_bfloat16 g_xh[(size_t)MTOT * DD];
__device__ __align__(128) __nv_bfloat16 g_xl[(size_t)MTOT * DD];
__device__ __align__(128) __nv_bfloat16 g_ench[(size_t)MTOT * 4096];
__device__ __align__(128) __nv_bfloat16 g_encl[(size_t)MTOT * 4096];
__device__ __align__(128) float g_qkv[(size_t)MTOT * QSTR];
__device__ __align__(128) float g_enc[(size_t)MTOT * 4096];
__device__ float g_ts[128];

/* ---------------- small helpers ---------------- */
__device__ __forceinline__ float tanh_acc(float x) {
    float ax = fabsf(x);
    float e  = __expf(2.0f * ax);
    float r  = 1.0f - 2.0f / (e + 1.0f);
    return x < 0.0f ? -r : r;
}

__device__ __forceinline__ void split1(float f, unsigned short& h, unsigned short& l) {
    __nv_bfloat16 hb = __float2bfloat16(f);
    float res = f - __bfloat162float(hb);
    __nv_bfloat16 lb = __float2bfloat16(res);
    h = __bfloat16_as_ushort(hb);
    l = __bfloat16_as_ushort(lb);
}

__device__ __forceinline__ uint32_t smem_u32(const void* p) {
    uint32_t a;
    asm("{ .reg .u64 t; cvta.to.shared.u64 t, %1; cvt.u32.u64 %0, t; }" : "=r"(a) : "l"(p));
    return a;
}

__device__ __forceinline__ uint32_t swz(uint32_t off) {       /* SW128 */
    return off ^ ((off >> 3) & 0x70);
}

__device__ __forceinline__ void cp16(uint32_t saddr, const void* gaddr) {
    asm volatile("cp.async.cg.shared.global [%0], [%1], 16;" :: "r"(saddr), "l"(gaddr));
}
__device__ __forceinline__ void cp_commit() {
    asm volatile("cp.async.commit_group;" ::: "memory");
}
template <int N>
__device__ __forceinline__ void cp_wait() {
    asm volatile("cp.async.wait_group %0;" :: "n"(N) : "memory");
}

__device__ __forceinline__ void ldm4(uint32_t* r, uint32_t addr) {
    asm volatile("ldmatrix.sync.aligned.m8n8.x4.shared.b16 {%0,%1,%2,%3}, [%4];"
                 : "=r"(r[0]), "=r"(r[1]), "=r"(r[2]), "=r"(r[3]) : "r"(addr));
}

__device__ __forceinline__ void mma16816(float* d, const uint32_t* a,
                                         uint32_t b0, uint32_t b1) {
    asm volatile("mma.sync.aligned.m16n8k16.row.col.f32.bf16.bf16.f32 "
                 "{%0,%1,%2,%3}, {%4,%5,%6,%7}, {%8,%9}, {%0,%1,%2,%3};"
                 : "+f"(d[0]), "+f"(d[1]), "+f"(d[2]), "+f"(d[3])
                 : "r"(a[0]), "r"(a[1]), "r"(a[2]), "r"(a[3]), "r"(b0), "r"(b1));
}

/* ---------------- prep kernels ---------------- */
__global__ void ts_kernel() {
    int i = threadIdx.x;
    if (i < 128)
        g_ts[i] = (float)pow(10000.0, (double)i / 128.0);
}

/* transpose+split qkv weights into g_wt: row = global out col (head*256+h), col = d */
__global__ void __launch_bounds__(256) trans_qkv_w(const float* __restrict__ qw,
                                                   const float* __restrict__ kvw) {
    __shared__ float t[32][33];
    int c0 = blockIdx.x * 32, d0 = blockIdx.y * 32;
    int tx = threadIdx.x & 31, ty = threadIdx.x >> 5;
    int head = c0 >> 8, hb = c0 & 255;
    const float* src = (head < NHE) ? (qw + (size_t)head * DD * HDIM)
                                    : (kvw + (size_t)(head - NHE) * DD * HDIM);
#pragma unroll
    for (int i = 0; i < 4; i++)
        t[ty + 8 * i][tx] = src[(size_t)(d0 + ty + 8 * i) * HDIM + hb + tx];
    __syncthreads();
#pragma unroll
    for (int i = 0; i < 4; i++) {
        float f = t[tx][ty + 8 * i];
        unsigned short h, l; split1(f, h, l);
        size_t o = (size_t)(c0 + ty + 8 * i) * DD + d0 + tx;
        ((unsigned short*)g_wt_h)[o] = h;
        ((unsigned short*)g_wt_l)[o] = l;
    }
}

/* transpose+split out_w [4096][3584] -> g_owt [3584][4096] */
__global__ void __launch_bounds__(256) trans_ow(const float* __restrict__ ow) {
    __shared__ float t[32][33];
    int c0 = blockIdx.x * 32, r0 = blockIdx.y * 32;
    int tx = threadIdx.x & 31, ty = threadIdx.x >> 5;
#pragma unroll
    for (int i = 0; i < 4; i++)
        t[ty + 8 * i][tx] = ow[(size_t)(r0 + ty + 8 * i) * DD + c0 + tx];
    __syncthreads();
#pragma unroll
    for (int i = 0; i < 4; i++) {
        float f = t[tx][ty + 8 * i];
        unsigned short h, l; split1(f, h, l);
        size_t o = (size_t)(c0 + ty + 8 * i) * 4096 + r0 + tx;
        ((unsigned short*)g_owt_h)[o] = h;
        ((unsigned short*)g_owt_l)[o] = l;
    }
}

__global__ void convert_split(const float4* __restrict__ src, ushort4* __restrict__ h,
                              ushort4* __restrict__ l, int n4) {
    int i = blockIdx.x * 256 + threadIdx.x;
    if (i >= n4) return;
    float4 v = src[i];
    ushort4 uh, ul;
    split1(v.x, uh.x, ul.x);
    split1(v.y, uh.y, ul.y);
    split1(v.z, uh.z, ul.z);
    split1(v.w, uh.w, ul.w);
    h[i] = uh;
    l[i] = ul;
}

__global__ void rope_kernel(float* __restrict__ buf, const int* __restrict__ segpos,
                            int heads, float scale, int total) {
    int idx = blockIdx.x * 256 + threadIdx.x;
    if (idx >= total) return;
    int i = idx & 127;
    int rest = idx >> 7;
    int head = rest % heads;
    int bt = rest / heads;
    int pos = segpos[bt];
    float ts = g_ts[i];
    float angf = __fdiv_rn((float)pos, ts);
    double sd, cd;
    sincos((double)angf, &sd, &cd);
    float s = (float)sd, c = (float)cd;
    float* p = buf + (size_t)bt * QSTR + head * HDIM;
    float first = p[i], second = p[i + 128];
    p[i]       = (first * c - second * s) * scale;
    p[i + 128] = (second * c + first * s) * scale;
}

/* ---------------- mma.sync bf16-split GEMM ----------------
   C[M,N] = A[M,K] x B^T, B rows are output columns (K-major).
   CTA tile 128x128, 8 warps each 32x64, K-chunk 64, 2-stage cp.async pipe,
   3-way bf16 split: AhBh + AhBl + AlBh, fp32 accum. */
#define GK 64

__global__ void __launch_bounds__(256) gemm_mma(
    const __nv_bfloat16* __restrict__ Ah, const __nv_bfloat16* __restrict__ Al, int lda,
    const __nv_bfloat16* __restrict__ Bh, const __nv_bfloat16* __restrict__ Bl, int ldb,
    float* __restrict__ C, int ldc, int Kd)
{
    extern __shared__ __align__(1024) char smem[];
    const uint32_t sbase = smem_u32(smem);
    const int tid = threadIdx.x;
    const int wid = tid >> 5, lid = tid & 31;
    const int wm = wid & 3, wn = wid >> 2;
    const int row0 = blockIdx.y * 128;
    const int col0 = blockIdx.x * 128;
    const uint32_t TSZ = 16384, STAGE = 4 * TSZ;

    float acc[2][8][4];
#pragma unroll
    for (int i = 0; i < 2; i++)
#pragma unroll
        for (int j = 0; j < 8; j++)
#pragma unroll
            for (int kq = 0; kq < 4; kq++) acc[i][j][kq] = 0.0f;

    /* per-thread load mapping: 4 16B vectors per array */
    int lr[4], lc8[4];
#pragma unroll
    for (int t = 0; t < 4; t++) { int v = tid + 256 * t; lr[t] = v >> 3; lc8[t] = v & 7; }

    const int nch = Kd / GK;

    /* prologue: load chunk 0 into stage 0 */
    {
        const int k0 = 0;
        uint32_t sb = sbase;
#pragma unroll
        for (int t = 0; t < 4; t++) {
            int r = lr[t], c8 = lc8[t];
            uint32_t so = swz((uint32_t)(r * 128 + c8 * 16));
            size_t ga = (size_t)(row0 + r) * lda + k0 + c8 * 8;
            size_t gb = (size_t)(col0 + r) * ldb + k0 + c8 * 8;
            cp16(sb + 0 * TSZ + so, Ah + ga);
            cp16(sb + 1 * TSZ + so, Al + ga);
            cp16(sb + 2 * TSZ + so, Bh + gb);
            cp16(sb + 3 * TSZ + so, Bl + gb);
        }
        cp_commit();
    }

    const int rA  = wm * 32 + (lid & 15);
    const int cA  = lid >> 4;                    /* chunk-hi bit for A ldmatrix */
    const int rB  = wn * 64 + (lid & 7) + ((lid >> 4) & 1) * 8;
    const int cB  = (lid >> 3) & 1;

    for (int c = 0; c < nch; c++) {
        int s = c & 1;
        if (c + 1 < nch) {     /* prefetch next chunk into other stage */
            const int k0 = (c + 1) * GK;
            uint32_t sb = sbase + (uint32_t)((c + 1) & 1) * STAGE;
#pragma unroll
            for (int t = 0; t < 4; t++) {
                int r = lr[t], c8 = lc8[t];
                uint32_t so = swz((uint32_t)(r * 128 + c8 * 16));
                size_t ga = (size_t)(row0 + r) * lda + k0 + c8 * 8;
                size_t gb = (size_t)(col0 + r) * ldb + k0 + c8 * 8;
                cp16(sb + 0 * TSZ + so, Ah + ga);
                cp16(sb + 1 * TSZ + so, Al + ga);
                cp16(sb + 2 * TSZ + so, Bh + gb);
                cp16(sb + 3 * TSZ + so, Bl + gb);
            }
            cp_commit();
            cp_wait<1>();
        } else {
            cp_wait<0>();
        }
        __syncthreads();

        uint32_t sb = sbase + (uint32_t)s * STAGE;
#pragma unroll
        for (int ks = 0; ks < 4; ks++) {
            const int kc8 = ks * 2;
            uint32_t ah[2][4], al[2][4];
#pragma unroll
            for (int m2 = 0; m2 < 2; m2++) {
                uint32_t off = swz((uint32_t)((rA + m2 * 16) * 128 + (kc8 + cA) * 16));
                ldm4(ah[m2], sb + 0 * TSZ + off);
                ldm4(al[m2], sb + 1 * TSZ + off);
            }
            uint32_t bh[4][4], bl[4][4];
#pragma unroll
            for (int n16 = 0; n16 < 4; n16++) {
                uint32_t off = swz((uint32_t)((rB + n16 * 16) * 128 + (kc8 + cB) * 16));
                ldm4(bh[n16], sb + 2 * TSZ + off);
                ldm4(bl[n16], sb + 3 * TSZ + off);
            }
#pragma unroll
            for (int m2 = 0; m2 < 2; m2++)
#pragma unroll
                for (int n16 = 0; n16 < 4; n16++)
#pragma unroll
                    for (int h = 0; h < 2; h++) {
                        float* d = acc[m2][n16 * 2 + h];
                        mma16816(d, ah[m2], bh[n16][h * 2], bh[n16][h * 2 + 1]);
                        mma16816(d, ah[m2], bl[n16][h * 2], bl[n16][h * 2 + 1]);
                        mma16816(d, al[m2], bh[n16][h * 2], bh[n16][h * 2 + 1]);
                    }
        }
        __syncthreads();
    }

    /* epilogue: fragment rows (lid>>2, +8), cols (lid&3)*2 */
#pragma unroll
    for (int m2 = 0; m2 < 2; m2++)
#pragma unroll
        for (int n8 = 0; n8 < 8; n8++) {
            int r = row0 + wm * 32 + m2 * 16 + (lid >> 2);
            int cc = col0 + wn * 64 + n8 * 8 + (lid & 3) * 2;
            float* p0 = C + (size_t)r * ldc + cc;
            p0[0] = acc[m2][n8][0];
            p0[1] = acc[m2][n8][1];
            float* p1 = C + (size_t)(r + 8) * ldc + cc;
            p1[0] = acc[m2][n8][2];
            p1[1] = acc[m2][n8][3];
        }
}

/* ---------------- flash attention (fp32, windowed causal, soft-cap) ---------- */
#define BQ 32
#define BK 32
#define QK_PAD 260
#define SPAD 36

__device__ __forceinline__ void put_score(float* s_s, const int* posq_s,
                                          const int* posk_s, int tq0, int s0,
                                          int qr, int jr, float dot) {
    float sc = tanh_acc(dot * (1.0f / 50.0f)) * 50.0f;
    int ti = tq0 + qr, si = s0 + jr;
    int pq = posq_s[qr], pk = posk_s[jr];
    bool valid = (si <= ti) && (pk > pq - WIN) && (pk < pq + WIN);
    s_s[qr * SPAD + jr] = valid ? sc : -1e30f;
}

__global__ void __launch_bounds__(256) attn_kernel(
    const float* __restrict__ q, const float* __restrict__ k,
    const float* __restrict__ v, const int* __restrict__ segpos,
    float* __restrict__ enc)
{
    extern __shared__ float sm[];
    float* q_s = sm;
    float* k_s = q_s + BQ * QK_PAD;
    float* v_s = k_s + BK * QK_PAD;
    float* s_s = v_s + BK * HDIM;
    int* posq_s = (int*)(s_s + BQ * SPAD);
    int* posk_s = posq_s + BQ;

    const int tile = (gridDim.x - 1) - blockIdx.x;
    const int n = blockIdx.y;
    const int b = blockIdx.z;
    const int kh = n >> 1;
    const int tq0 = tile * BQ;
    const int tid = threadIdx.x;

    const float* qbase = q + (size_t)(b * TT + tq0) * QSTR + n * HDIM;
    for (int i = tid; i < BQ * (HDIM / 4); i += 256) {
        int r = i >> 6, c = (i & 63) << 2;
        *(float4*)&q_s[r * QK_PAD + c] = *(const float4*)&qbase[(size_t)r * QSTR + c];
    }
    if (tid < BQ) posq_s[tid] = segpos[b * TT + tq0 + tid];

    const int qi = tid >> 3, gi = tid & 7;
    const int qg = tid >> 4, jg = tid & 15;

    float m_run = -1e30f, l_run = 0.0f;
    float acc[32];
#pragma unroll
    for (int c = 0; c < 32; c++) acc[c] = 0.0f;

    int s_begin = tq0 - (WIN - 1);
    if (s_begin < 0) s_begin = 0;
    s_begin &= ~(BK - 1);
    const int s_end = tq0 + BQ;

    for (int s0 = s_begin; s0 < s_end; s0 += BK) {
        __syncthreads();
        const float* kbase = k + (size_t)(b * TT + s0) * QSTR + kh * HDIM;
        const float* vbase = v + (size_t)(b * TT + s0) * QSTR + kh * HDIM;
        for (int i = tid; i < BK * (HDIM / 4); i += 256) {
            int r = i >> 6, c = (i & 63) << 2;
            *(float4*)&k_s[r * QK_PAD + c] = *(const float4*)&kbase[(size_t)r * QSTR + c];
            *(float4*)&v_s[r * HDIM + c]   = *(const float4*)&vbase[(size_t)r * QSTR + c];
        }
        if (tid < BK) posk_s[tid] = segpos[b * TT + s0 + tid];
        __syncthreads();

        float d00 = 0.f, d01 = 0.f, d10 = 0.f, d11 = 0.f;
        const float* qa = q_s + qg * QK_PAD;
        const float* qb = q_s + (qg + 16) * QK_PAD;
        const float* ka = k_s + jg * QK_PAD;
        const float* kb = k_s + (jg + 16) * QK_PAD;
#pragma unroll 16
        for (int d = 0; d < HDIM; d += 4) {
            float4 a0 = *(const float4*)(qa + d);
            float4 a1 = *(const float4*)(qb + d);
            float4 b0 = *(const float4*)(ka + d);
            float4 b1 = *(const float4*)(kb + d);
            d00 += a0.x * b0.x + a0.y * b0.y + a0.z * b0.z + a0.w * b0.w;
            d01 += a0.x * b1.x + a0.y * b1.y + a0.z * b1.z + a0.w * b1.w;
            d10 += a1.x * b0.x + a1.y * b0.y + a1.z * b0.z + a1.w * b0.w;
            d11 += a1.x * b1.x + a1.y * b1.y + a1.z * b1.z + a1.w * b1.w;
        }
        put_score(s_s, posq_s, posk_s, tq0, s0, qg,      jg,      d00);
        put_score(s_s, posq_s, posk_s, tq0, s0, qg,      jg + 16, d01);
        put_score(s_s, posq_s, posk_s, tq0, s0, qg + 16, jg,      d10);
        put_score(s_s, posq_s, posk_s, tq0, s0, qg + 16, jg + 16, d11);
        __syncthreads();

        float mx = m_run;
#pragma unroll
        for (int j = 0; j < BK; j++) mx = fmaxf(mx, s_s[qi * SPAD + j]);
        float corr = __expf(m_run - mx);
        l_run *= corr;
#pragma unroll
        for (int c = 0; c < 32; c++) acc[c] *= corr;
        float psum = 0.0f;
#pragma unroll
        for (int j = 0; j < BK; j++) {
            float sv = s_s[qi * SPAD + j];
            float pj = (sv < -1e29f) ? 0.0f : __expf(sv - mx);
            psum += pj;
            const float* vr = v_s + j * HDIM + gi * 4;
#pragma unroll
            for (int i8 = 0; i8 < 8; i8++) {
                float4 vv = *(const float4*)(vr + i8 * 32);
                acc[i8 * 4 + 0] += pj * vv.x;
                acc[i8 * 4 + 1] += pj * vv.y;
                acc[i8 * 4 + 2] += pj * vv.z;
                acc[i8 * 4 + 3] += pj * vv.w;
            }
        }
        l_run += psum;
        m_run = mx;
    }

    float invl = 1.0f / l_run;
    float* obase = enc + (size_t)(b * TT + tq0 + qi) * (NHE * HDIM) + n * HDIM + gi * 4;
#pragma unroll
    for (int i8 = 0; i8 < 8; i8++) {
        float4 o = make_float4(acc[i8 * 4 + 0] * invl, acc[i8 * 4 + 1] * invl,
                               acc[i8 * 4 + 2] * invl, acc[i8 * 4 + 3] * invl);
        *(float4*)(obase + i8 * 32) = o;
    }
}

/* ---------------- host launcher ---------------- */
extern "C" void kernel_launch(void* const* d_in, const int* in_sizes, int n_in,
                              void* d_out, int out_size)
{
    const float* x      = (const float*)d_in[0];
    const int*   segpos = (const int*)d_in[1];
    const float* q_w    = (const float*)d_in[3];
    const float* kv_w   = (const float*)d_in[4];
    const float* out_w  = (const float*)d_in[5];
    float* out = (float*)d_out;

    void *wth, *wtl, *owth, *owtl, *xh, *xl, *ench, *encl, *qkv, *encb;
    cudaGetSymbolAddress(&wth,  g_wt_h);
    cudaGetSymbolAddress(&wtl,  g_wt_l);
    cudaGetSymbolAddress(&owth, g_owt_h);
    cudaGetSymbolAddress(&owtl, g_owt_l);
    cudaGetSymbolAddress(&xh,   g_xh);
    cudaGetSymbolAddress(&xl,   g_xl);
    cudaGetSymbolAddress(&ench, g_ench);
    cudaGetSymbolAddress(&encl, g_encl);
    cudaGetSymbolAddress(&qkv,  g_qkv);
    cudaGetSymbolAddress(&encb, g_enc);

    float* qkvf = (float*)qkv;
    float* encf = (float*)encb;

    const int GSMEM = 2 * 4 * 16384;   /* 131072 */
    cudaFuncSetAttribute(gemm_mma, cudaFuncAttributeMaxDynamicSharedMemorySize, GSMEM);
    const int ATTN_SMEM = (BQ * QK_PAD + BK * QK_PAD + BK * HDIM + BQ * SPAD) * 4
                        + (BQ + BK) * 4;
    cudaFuncSetAttribute(attn_kernel, cudaFuncAttributeMaxDynamicSharedMemorySize, ATTN_SMEM);

    /* prep: rope table, weight transpose+split, x split */
    ts_kernel<<<1, 128>>>();
    trans_qkv_w<<<dim3(8192 / 32, DD / 32), 256>>>(q_w, kv_w);
    trans_ow<<<dim3(DD / 32, 4096 / 32), 256>>>(out_w);
    {
        int n4 = MTOT * DD / 4;
        convert_split<<<(n4 + 255) / 256, 256>>>((const float4*)x, (ushort4*)xh, (ushort4*)xl, n4);
    }

    /* GEMM1: qkv = x @ [q_w | k_w | v_w]   (M=4096, N=8192, K=3584) */
    gemm_mma<<<dim3(8192 / 128, MTOT / 128), 256, GSMEM>>>(
        (const __nv_bfloat16*)xh, (const __nv_bfloat16*)xl, DD,
        (const __nv_bfloat16*)wth, (const __nv_bfloat16*)wtl, DD,
        qkvf, QSTR, DD);

    /* RoPE (q gets SCALE folded in) */
    {
        int totq = MTOT * NHE * 128;
        rope_kernel<<<totq / 256, 256>>>(qkvf, segpos, NHE, SCALE_F, totq);
        int totk = MTOT * KHE * 128;
        rope_kernel<<<totk / 256, 256>>>(qkvf + 4096, segpos, KHE, 1.0f, totk);
    }

    /* attention -> g_enc [4096][4096] */
    attn_kernel<<<dim3(TT / BQ, NHE, BB), 256, ATTN_SMEM>>>(
        qkvf, qkvf + 4096, qkvf + 6144, segpos, encf);

    /* split enc, then GEMM2: out = enc @ out_w  (M=4096, N=3584, K=4096) */
    {
        int n4 = MTOT * 4096 / 4;
        convert_split<<<(n4 + 255) / 256, 256>>>((const float4*)encf, (ushort4*)ench, (ushort4*)encl, n4);
    }
    gemm_mma<<<dim3(DD / 128, MTOT / 128), 256, GSMEM>>>(
        (const __nv_bfloat16*)ench, (const __nv_bfloat16*)encl, 4096,
        (const __nv_bfloat16*)owth, (const __nv_bfloat16*)owtl, 4096,
        out, DD, 4096);
}

// round 6
// speedup vs baseline: 3.4058x; 1.5543x over previous
#include <cuda_runtime.h>
#include <cuda_bf16.h>
#include <math.h>
#include <stdint.h>

#define BB 2
#define TT 2048
#define DD 3584
#define NHE 16
#define KHE 8
#define HDIM 256
#define WIN 1024
#define SCALE_F 0.0625f
#define MTOT (BB*TT)         /* 4096 */
#define QSTR 8192            /* row stride of fused qkv fp32 buffer */

/* ---------------- device globals (no allocations allowed) ---------------- */
__device__ __align__(128) __nv_bfloat16 g_wt_h[(size_t)8192 * DD];
__device__ __align__(128) __nv_bfloat16 g_wt_l[(size_t)8192 * DD];
__device__ __align__(128) __nv_bfloat16 g_owt_h[(size_t)DD * 4096];
__device__ __align__(128) __nv_bfloat16 g_owt_l[(size_t)DD * 4096];
__device__ __align__(128) __nv_bfloat16 g_xh[(size_t)MTOT * DD];
__device__ __align__(128) __nv_bfloat16 g_xl[(size_t)MTOT * DD];
__device__ __align__(128) __nv_bfloat16 g_ench[(size_t)MTOT * 4096];
__device__ __align__(128) __nv_bfloat16 g_encl[(size_t)MTOT * 4096];
__device__ __align__(128) __nv_bfloat16 g_qh[(size_t)MTOT * 4096];
__device__ __align__(128) __nv_bfloat16 g_ql[(size_t)MTOT * 4096];
__device__ __align__(128) __nv_bfloat16 g_kh[(size_t)MTOT * 2048];
__device__ __align__(128) __nv_bfloat16 g_kl[(size_t)MTOT * 2048];
__device__ __align__(128) __nv_bfloat16 g_vh[(size_t)MTOT * 2048];
__device__ __align__(128) __nv_bfloat16 g_vl[(size_t)MTOT * 2048];
__device__ __align__(128) float g_qkv[(size_t)MTOT * QSTR];
__device__ float g_ts[128];

/* ---------------- small helpers ---------------- */
__device__ __forceinline__ float tanh_acc(float x) {
    float ax = fabsf(x);
    float e  = __expf(2.0f * ax);
    float r  = 1.0f - 2.0f / (e + 1.0f);
    return x < 0.0f ? -r : r;
}

__device__ __forceinline__ void split1(float f, unsigned short& h, unsigned short& l) {
    __nv_bfloat16 hb = __float2bfloat16(f);
    float res = f - __bfloat162float(hb);
    __nv_bfloat16 lb = __float2bfloat16(res);
    h = __bfloat16_as_ushort(hb);
    l = __bfloat16_as_ushort(lb);
}

__device__ __forceinline__ uint32_t smem_u32(const void* p) {
    uint32_t a;
    asm("{ .reg .u64 t; cvta.to.shared.u64 t, %1; cvt.u32.u64 %0, t; }" : "=r"(a) : "l"(p));
    return a;
}
__device__ __forceinline__ uint32_t swz(uint32_t off) {       /* SW128 */
    return off ^ ((off >> 3) & 0x70);
}
__device__ __forceinline__ void cp16(uint32_t saddr, const void* gaddr) {
    asm volatile("cp.async.cg.shared.global [%0], [%1], 16;" :: "r"(saddr), "l"(gaddr));
}
__device__ __forceinline__ void cp4(uint32_t saddr, const void* gaddr) {
    asm volatile("cp.async.ca.shared.global [%0], [%1], 4;" :: "r"(saddr), "l"(gaddr));
}
__device__ __forceinline__ void cp_commit() {
    asm volatile("cp.async.commit_group;" ::: "memory");
}
template <int N>
__device__ __forceinline__ void cp_wait() {
    asm volatile("cp.async.wait_group %0;" :: "n"(N) : "memory");
}
__device__ __forceinline__ void ldm4(uint32_t* r, uint32_t addr) {
    asm volatile("ldmatrix.sync.aligned.m8n8.x4.shared.b16 {%0,%1,%2,%3}, [%4];"
                 : "=r"(r[0]), "=r"(r[1]), "=r"(r[2]), "=r"(r[3]) : "r"(addr));
}
__device__ __forceinline__ void ldm4t(uint32_t* r, uint32_t addr) {
    asm volatile("ldmatrix.sync.aligned.m8n8.x4.trans.shared.b16 {%0,%1,%2,%3}, [%4];"
                 : "=r"(r[0]), "=r"(r[1]), "=r"(r[2]), "=r"(r[3]) : "r"(addr));
}
__device__ __forceinline__ void mma16816(float* d, const uint32_t* a,
                                         uint32_t b0, uint32_t b1) {
    asm volatile("mma.sync.aligned.m16n8k16.row.col.f32.bf16.bf16.f32 "
                 "{%0,%1,%2,%3}, {%4,%5,%6,%7}, {%8,%9}, {%0,%1,%2,%3};"
                 : "+f"(d[0]), "+f"(d[1]), "+f"(d[2]), "+f"(d[3])
                 : "r"(a[0]), "r"(a[1]), "r"(a[2]), "r"(a[3]), "r"(b0), "r"(b1));
}

/* ---------------- prep kernels ---------------- */
__global__ void ts_kernel() {
    int i = threadIdx.x;
    if (i < 128)
        g_ts[i] = (float)pow(10000.0, (double)i / 128.0);
}

__global__ void __launch_bounds__(256) trans_qkv_w(const float* __restrict__ qw,
                                                   const float* __restrict__ kvw) {
    __shared__ float t[32][33];
    int c0 = blockIdx.x * 32, d0 = blockIdx.y * 32;
    int tx = threadIdx.x & 31, ty = threadIdx.x >> 5;
    int head = c0 >> 8, hb = c0 & 255;
    const float* src = (head < NHE) ? (qw + (size_t)head * DD * HDIM)
                                    : (kvw + (size_t)(head - NHE) * DD * HDIM);
#pragma unroll
    for (int i = 0; i < 4; i++)
        t[ty + 8 * i][tx] = src[(size_t)(d0 + ty + 8 * i) * HDIM + hb + tx];
    __syncthreads();
#pragma unroll
    for (int i = 0; i < 4; i++) {
        float f = t[tx][ty + 8 * i];
        unsigned short h, l; split1(f, h, l);
        size_t o = (size_t)(c0 + ty + 8 * i) * DD + d0 + tx;
        ((unsigned short*)g_wt_h)[o] = h;
        ((unsigned short*)g_wt_l)[o] = l;
    }
}

__global__ void __launch_bounds__(256) trans_ow(const float* __restrict__ ow) {
    __shared__ float t[32][33];
    int c0 = blockIdx.x * 32, r0 = blockIdx.y * 32;
    int tx = threadIdx.x & 31, ty = threadIdx.x >> 5;
#pragma unroll
    for (int i = 0; i < 4; i++)
        t[ty + 8 * i][tx] = ow[(size_t)(r0 + ty + 8 * i) * DD + c0 + tx];
    __syncthreads();
#pragma unroll
    for (int i = 0; i < 4; i++) {
        float f = t[tx][ty + 8 * i];
        unsigned short h, l; split1(f, h, l);
        size_t o = (size_t)(c0 + ty + 8 * i) * 4096 + r0 + tx;
        ((unsigned short*)g_owt_h)[o] = h;
        ((unsigned short*)g_owt_l)[o] = l;
    }
}

__global__ void convert_split(const float4* __restrict__ src, ushort4* __restrict__ h,
                              ushort4* __restrict__ l, int n4) {
    int i = blockIdx.x * 256 + threadIdx.x;
    if (i >= n4) return;
    float4 v = src[i];
    ushort4 uh, ul;
    split1(v.x, uh.x, ul.x);
    split1(v.y, uh.y, ul.y);
    split1(v.z, uh.z, ul.z);
    split1(v.w, uh.w, ul.w);
    h[i] = uh;
    l[i] = ul;
}

/* rope + bf16-split writeout (Q: scale folded; K: scale=1) */
__global__ void rope_split(const float* __restrict__ qkv, const int* __restrict__ segpos,
                           int heads, int colbase, float scale,
                           unsigned short* __restrict__ oh, unsigned short* __restrict__ ol,
                           int ostride, int total) {
    int idx = blockIdx.x * 256 + threadIdx.x;
    if (idx >= total) return;
    int i = idx & 127;
    int rest = idx >> 7;
    int head = rest % heads;
    int bt = rest / heads;
    int pos = segpos[bt];
    float ts = g_ts[i];
    float angf = __fdiv_rn((float)pos, ts);
    double sd, cd;
    sincos((double)angf, &sd, &cd);
    float s = (float)sd, c = (float)cd;
    const float* p = qkv + (size_t)bt * QSTR + colbase + head * HDIM;
    float first = p[i], second = p[i + 128];
    float o1 = (first * c - second * s) * scale;
    float o2 = (second * c + first * s) * scale;
    size_t ob = (size_t)bt * ostride + head * HDIM;
    unsigned short h, l;
    split1(o1, h, l); oh[ob + i] = h;       ol[ob + i] = l;
    split1(o2, h, l); oh[ob + i + 128] = h; ol[ob + i + 128] = l;
}

/* split V region of qkv into g_vh/g_vl */
__global__ void vsplit(const float4* __restrict__ qkv4, ushort4* __restrict__ vh,
                       ushort4* __restrict__ vl) {
    int idx = blockIdx.x * 256 + threadIdx.x;     /* MTOT*512 */
    int bt = idx >> 9, c = idx & 511;
    float4 v = qkv4[(size_t)bt * 2048 + 1536 + c];
    ushort4 uh, ul;
    split1(v.x, uh.x, ul.x);
    split1(v.y, uh.y, ul.y);
    split1(v.z, uh.z, ul.z);
    split1(v.w, uh.w, ul.w);
    vh[(size_t)bt * 512 + c] = uh;
    vl[(size_t)bt * 512 + c] = ul;
}

/* ---------------- mma.sync bf16-split GEMM (unchanged, validated R5) -------- */
#define GK 64

__global__ void __launch_bounds__(256) gemm_mma(
    const __nv_bfloat16* __restrict__ Ah, const __nv_bfloat16* __restrict__ Al, int lda,
    const __nv_bfloat16* __restrict__ Bh, const __nv_bfloat16* __restrict__ Bl, int ldb,
    float* __restrict__ C, int ldc, int Kd)
{
    extern __shared__ __align__(1024) char smem[];
    const uint32_t sbase = smem_u32(smem);
    const int tid = threadIdx.x;
    const int wid = tid >> 5, lid = tid & 31;
    const int wm = wid & 3, wn = wid >> 2;
    const int row0 = blockIdx.y * 128;
    const int col0 = blockIdx.x * 128;
    const uint32_t TSZ = 16384, STAGE = 4 * TSZ;

    float acc[2][8][4];
#pragma unroll
    for (int i = 0; i < 2; i++)
#pragma unroll
        for (int j = 0; j < 8; j++)
#pragma unroll
            for (int kq = 0; kq < 4; kq++) acc[i][j][kq] = 0.0f;

    int lr[4], lc8[4];
#pragma unroll
    for (int t = 0; t < 4; t++) { int v = tid + 256 * t; lr[t] = v >> 3; lc8[t] = v & 7; }

    const int nch = Kd / GK;

    {
        uint32_t sb = sbase;
#pragma unroll
        for (int t = 0; t < 4; t++) {
            int r = lr[t], c8 = lc8[t];
            uint32_t so = swz((uint32_t)(r * 128 + c8 * 16));
            size_t ga = (size_t)(row0 + r) * lda + c8 * 8;
            size_t gb = (size_t)(col0 + r) * ldb + c8 * 8;
            cp16(sb + 0 * TSZ + so, Ah + ga);
            cp16(sb + 1 * TSZ + so, Al + ga);
            cp16(sb + 2 * TSZ + so, Bh + gb);
            cp16(sb + 3 * TSZ + so, Bl + gb);
        }
        cp_commit();
    }

    const int rA  = wm * 32 + (lid & 15);
    const int cA  = lid >> 4;
    const int rB  = wn * 64 + (lid & 7) + ((lid >> 4) & 1) * 8;
    const int cB  = (lid >> 3) & 1;

    for (int c = 0; c < nch; c++) {
        int s = c & 1;
        if (c + 1 < nch) {
            const int k0 = (c + 1) * GK;
            uint32_t sb = sbase + (uint32_t)((c + 1) & 1) * STAGE;
#pragma unroll
            for (int t = 0; t < 4; t++) {
                int r = lr[t], c8 = lc8[t];
                uint32_t so = swz((uint32_t)(r * 128 + c8 * 16));
                size_t ga = (size_t)(row0 + r) * lda + k0 + c8 * 8;
                size_t gb = (size_t)(col0 + r) * ldb + k0 + c8 * 8;
                cp16(sb + 0 * TSZ + so, Ah + ga);
                cp16(sb + 1 * TSZ + so, Al + ga);
                cp16(sb + 2 * TSZ + so, Bh + gb);
                cp16(sb + 3 * TSZ + so, Bl + gb);
            }
            cp_commit();
            cp_wait<1>();
        } else {
            cp_wait<0>();
        }
        __syncthreads();

        uint32_t sb = sbase + (uint32_t)s * STAGE;
#pragma unroll
        for (int ks = 0; ks < 4; ks++) {
            const int kc8 = ks * 2;
            uint32_t ah[2][4], al[2][4];
#pragma unroll
            for (int m2 = 0; m2 < 2; m2++) {
                uint32_t off = swz((uint32_t)((rA + m2 * 16) * 128 + (kc8 + cA) * 16));
                ldm4(ah[m2], sb + 0 * TSZ + off);
                ldm4(al[m2], sb + 1 * TSZ + off);
            }
            uint32_t bh[4][4], bl[4][4];
#pragma unroll
            for (int n16 = 0; n16 < 4; n16++) {
                uint32_t off = swz((uint32_t)((rB + n16 * 16) * 128 + (kc8 + cB) * 16));
                ldm4(bh[n16], sb + 2 * TSZ + off);
                ldm4(bl[n16], sb + 3 * TSZ + off);
            }
#pragma unroll
            for (int m2 = 0; m2 < 2; m2++)
#pragma unroll
                for (int n16 = 0; n16 < 4; n16++)
#pragma unroll
                    for (int h = 0; h < 2; h++) {
                        float* d = acc[m2][n16 * 2 + h];
                        mma16816(d, ah[m2], bh[n16][h * 2], bh[n16][h * 2 + 1]);
                        mma16816(d, ah[m2], bl[n16][h * 2], bl[n16][h * 2 + 1]);
                        mma16816(d, al[m2], bh[n16][h * 2], bh[n16][h * 2 + 1]);
                    }
        }
        __syncthreads();
    }

#pragma unroll
    for (int m2 = 0; m2 < 2; m2++)
#pragma unroll
        for (int n8 = 0; n8 < 8; n8++) {
            int r = row0 + wm * 32 + m2 * 16 + (lid >> 2);
            int cc = col0 + wn * 64 + n8 * 8 + (lid & 3) * 2;
            float* p0 = C + (size_t)r * ldc + cc;
            p0[0] = acc[m2][n8][0];
            p0[1] = acc[m2][n8][1];
            float* p1 = C + (size_t)(r + 8) * ldc + cc;
            p1[0] = acc[m2][n8][2];
            p1[1] = acc[m2][n8][3];
        }
}

/* ---------------- tensor-core flash attention ----------------
   CTA = (32 queries) x (2 heads of one kv group) = 64 rows.
   BK=32 keys/iter. Q resident; K/V 2-stage cp.async.
   QK and PV via mma.sync with full bf16 splits (3 products each).
   S -> smem fp32 softmax -> P bf16 h/l -> PV with ldmatrix.trans V. */
#define AQ 32
#define ABK 32
#define ASPAD 36

#define QHOFF   0u
#define QLOFF   32768u
#define KHOFF   65536u
#define KLOFF   98304u
#define VHOFF   131072u
#define VLOFF   163840u
#define SSOFF   196608u
#define PHOFF   205824u
#define PLOFF   214016u
#define POSQOFF 222208u
#define POSKOFF 222336u
#define MOFF    222592u
#define LOFF    222848u
#define CORROFF 223104u
#define ASMEM   223360

__device__ __forceinline__ void attn_load_stage(
    uint32_t sbase, char* smemc, int st, int s0, int b, int khead,
    const __nv_bfloat16* kh, const __nv_bfloat16* kl,
    const __nv_bfloat16* vh, const __nv_bfloat16* vl,
    const int* segpos, int tid)
{
    size_t gbase = ((size_t)(b * TT + s0)) * 2048 + khead * HDIM;
#pragma unroll
    for (int t = 0; t < 8; t++) {
        int idx = t * 256 + tid;                 /* 0..2047 */
        int split = idx >> 10, rem = idx & 1023;
        int p = rem >> 8, r = (rem >> 3) & 31, ch = rem & 7;
        size_t g = gbase + (size_t)r * 2048 + p * 64 + ch * 8;
        uint32_t so = swz((uint32_t)(r * 128 + ch * 16));
        cp16(sbase + (split ? KLOFF : KHOFF) + st * 16384 + p * 4096 + so,
             (split ? kl : kh) + g);
        cp16(sbase + (split ? VLOFF : VHOFF) + st * 16384 + p * 4096 + so,
             (split ? vl : vh) + g);
    }
    if (tid < ABK)
        cp4(sbase + POSKOFF + st * 128 + tid * 4, segpos + b * TT + s0 + tid);
}

__global__ void __launch_bounds__(256) attn_mma(
    const __nv_bfloat16* __restrict__ qh, const __nv_bfloat16* __restrict__ ql,
    const __nv_bfloat16* __restrict__ kh, const __nv_bfloat16* __restrict__ kl,
    const __nv_bfloat16* __restrict__ vh, const __nv_bfloat16* __restrict__ vl,
    const int* __restrict__ segpos,
    __nv_bfloat16* __restrict__ ench, __nv_bfloat16* __restrict__ encl)
{
    extern __shared__ __align__(1024) char smemc[];
    const uint32_t sbase = smem_u32(smemc);
    const int tid = threadIdx.x;
    const int wid = tid >> 5, lid = tid & 31;
    const int tile = (int)(gridDim.x - 1) - (int)blockIdx.x;
    const int khead = blockIdx.y;
    const int b = blockIdx.z;
    const int tq0 = tile * AQ;

    float* s_s    = (float*)(smemc + SSOFF);
    int*   posq   = (int*)(smemc + POSQOFF);
    int*   posk   = (int*)(smemc + POSKOFF);
    float* m_sm   = (float*)(smemc + MOFF);
    float* l_sm   = (float*)(smemc + LOFF);
    float* corr_s = (float*)(smemc + CORROFF);

    int s_begin = tq0 - (WIN - 1);
    if (s_begin < 0) s_begin = 0;
    s_begin &= ~(ABK - 1);
    const int nit = (tq0 + AQ - s_begin) / ABK;

    /* prologue: Q tile + stage0 K/V + positions, one commit group */
    {
#pragma unroll
        for (int t = 0; t < 16; t++) {
            int idx = t * 256 + tid;            /* 0..4095 */
            int split = idx >> 11, rem = idx & 2047;
            int p = rem >> 9, r = (rem >> 3) & 63, ch = rem & 7;
            int tq = tq0 + (r & 31);
            int n = khead * 2 + (r >> 5);
            size_t g = ((size_t)(b * TT + tq)) * 4096 + n * HDIM + p * 64 + ch * 8;
            uint32_t so = swz((uint32_t)(r * 128 + ch * 16));
            cp16(sbase + (split ? QLOFF : QHOFF) + p * 8192 + so, (split ? ql : qh) + g);
        }
        if (tid < AQ) cp4(sbase + POSQOFF + tid * 4, segpos + b * TT + tq0 + tid);
        attn_load_stage(sbase, smemc, 0, s_begin, b, khead, kh, kl, vh, vl, segpos, tid);
        cp_commit();
    }
    if (tid < 64) { m_sm[tid] = -1e30f; l_sm[tid] = 0.0f; }

    float acc_o[2][8][4];
#pragma unroll
    for (int mt = 0; mt < 2; mt++)
#pragma unroll
        for (int nt = 0; nt < 8; nt++)
#pragma unroll
            for (int q = 0; q < 4; q++) acc_o[mt][nt][q] = 0.0f;

    const int wm = wid & 3, wn = wid >> 2;                      /* QK layout 4x2 */
    const int rA = wm * 16 + (lid & 15);
    const int cA = lid >> 4;
    const int rB = wn * 16 + (lid & 7) + ((lid >> 4) & 1) * 8;
    const int cB = (lid >> 3) & 1;
    const int wm2 = wid & 1, wn2 = wid >> 1;                    /* PV layout 2x4 */

    for (int it = 0; it < nit; it++) {
        const int st = it & 1;
        const int s0 = s_begin + it * ABK;
        cp_wait<0>();
        __syncthreads();                                        /* sync A */

        if (it + 1 < nit) {   /* prefetch next stage; overlaps QK/softmax/PV */
            attn_load_stage(sbase, smemc, st ^ 1, s0 + ABK, b, khead, kh, kl, vh, vl,
                            segpos, tid);
            cp_commit();
        }

        /* ---- QK: S[64x32] ---- */
        {
            float acc_s[2][4] = {{0,0,0,0},{0,0,0,0}};
            uint32_t khb = sbase + KHOFF + st * 16384;
            uint32_t klb = sbase + KLOFF + st * 16384;
#pragma unroll
            for (int ks = 0; ks < 16; ks++) {
                int p = ks >> 2, c2 = (ks & 3) * 2;
                uint32_t ah[4], al[4], bh[4], bl[4];
                uint32_t ao = swz((uint32_t)(rA * 128 + (c2 + cA) * 16));
                ldm4(ah, sbase + QHOFF + p * 8192 + ao);
                ldm4(al, sbase + QLOFF + p * 8192 + ao);
                uint32_t bo = swz((uint32_t)(rB * 128 + (c2 + cB) * 16));
                ldm4(bh, khb + p * 4096 + bo);
                ldm4(bl, klb + p * 4096 + bo);
                mma16816(acc_s[0], ah, bh[0], bh[1]);
                mma16816(acc_s[0], ah, bl[0], bl[1]);
                mma16816(acc_s[0], al, bh[0], bh[1]);
                mma16816(acc_s[1], ah, bh[2], bh[3]);
                mma16816(acc_s[1], ah, bl[2], bl[3]);
                mma16816(acc_s[1], al, bh[2], bh[3]);
            }
            int sr = wm * 16 + (lid >> 2);
            int sc = wn * 16 + (lid & 3) * 2;
#pragma unroll
            for (int nt = 0; nt < 2; nt++) {
                s_s[sr * ASPAD + sc + nt * 8]       = acc_s[nt][0];
                s_s[sr * ASPAD + sc + nt * 8 + 1]   = acc_s[nt][1];
                s_s[(sr + 8) * ASPAD + sc + nt * 8]     = acc_s[nt][2];
                s_s[(sr + 8) * ASPAD + sc + nt * 8 + 1] = acc_s[nt][3];
            }
        }
        __syncthreads();                                        /* sync B */

        /* ---- softmax: thread t handles row t>>2, cols (t&3)*8..+7 ---- */
        {
            int row = tid >> 2, qq = tid & 3;
            int ti = tq0 + (row & 31);
            int pq = posq[row & 31];
            const int* pks = posk + st * 32;
            float sc[8];
            float bmax = -1e30f;
#pragma unroll
            for (int j = 0; j < 8; j++) {
                int col = qq * 8 + j;
                float raw = s_s[row * ASPAD + col];
                float cap = tanh_acc(raw * 0.02f) * 50.0f;
                int si = s0 + col;
                int pk = pks[col];
                bool valid = (si <= ti) && (pk > pq - WIN) && (pk < pq + WIN);
                sc[j] = valid ? cap : -1e30f;
                bmax = fmaxf(bmax, sc[j]);
            }
            bmax = fmaxf(bmax, __shfl_xor_sync(0xffffffffu, bmax, 1));
            bmax = fmaxf(bmax, __shfl_xor_sync(0xffffffffu, bmax, 2));
            float m_old = m_sm[row];
            float m_new = fmaxf(m_old, bmax);
            float corr = __expf(m_old - m_new);
            float psum = 0.0f;
#pragma unroll
            for (int jp = 0; jp < 4; jp++) {
                float p0 = (sc[jp*2]   < -1e29f) ? 0.0f : __expf(sc[jp*2]   - m_new);
                float p1 = (sc[jp*2+1] < -1e29f) ? 0.0f : __expf(sc[jp*2+1] - m_new);
                psum += p0 + p1;
                unsigned short h0, l0, h1, l1;
                split1(p0, h0, l0);
                split1(p1, h1, l1);
                uint32_t byteoff = (uint32_t)(row * 128 + (qq * 8 + jp * 2) * 2);
                uint32_t sw = byteoff ^ ((byteoff >> 3) & 0x70);
                *(uint32_t*)(smemc + PHOFF + sw) = (uint32_t)h0 | ((uint32_t)h1 << 16);
                *(uint32_t*)(smemc + PLOFF + sw) = (uint32_t)l0 | ((uint32_t)l1 << 16);
            }
            psum += __shfl_xor_sync(0xffffffffu, psum, 1);
            psum += __shfl_xor_sync(0xffffffffu, psum, 2);
            if ((tid & 3) == 0) {
                l_sm[row] = l_sm[row] * corr + psum;
                m_sm[row] = m_new;
                corr_s[row] = corr;
            }
        }
        __syncthreads();                                        /* sync C */

        /* ---- rescale accumulators + PV ---- */
        {
#pragma unroll
            for (int mt = 0; mt < 2; mt++) {
                int r0 = wm2 * 32 + mt * 16 + (lid >> 2);
                float c0 = corr_s[r0], c1 = corr_s[r0 + 8];
#pragma unroll
                for (int nt = 0; nt < 8; nt++) {
                    acc_o[mt][nt][0] *= c0; acc_o[mt][nt][1] *= c0;
                    acc_o[mt][nt][2] *= c1; acc_o[mt][nt][3] *= c1;
                }
            }
            uint32_t vhb = sbase + VHOFF + st * 16384 + wn2 * 4096;
            uint32_t vlb = sbase + VLOFF + st * 16384 + wn2 * 4096;
#pragma unroll
            for (int ks2 = 0; ks2 < 2; ks2++) {
                uint32_t pa_h[2][4], pa_l[2][4];
#pragma unroll
                for (int mt = 0; mt < 2; mt++) {
                    int rA2 = wm2 * 32 + mt * 16 + (lid & 15);
                    uint32_t bo = swz((uint32_t)(rA2 * 128 + (ks2 * 2 + (lid >> 4)) * 16));
                    ldm4(pa_h[mt], sbase + PHOFF + bo);
                    ldm4(pa_l[mt], sbase + PLOFF + bo);
                }
#pragma unroll
                for (int nn = 0; nn < 4; nn++) {
                    int tl = lid >> 3;
                    int srow = (tl & 1) * 8 + (lid & 7) + ks2 * 16;
                    uint32_t bo = swz((uint32_t)(srow * 128 + (nn * 16 + (tl >> 1) * 8) * 2));
                    uint32_t bvh[4], bvl[4];
                    ldm4t(bvh, vhb + bo);
                    ldm4t(bvl, vlb + bo);
#pragma unroll
                    for (int mt = 0; mt < 2; mt++)
#pragma unroll
                        for (int h = 0; h < 2; h++) {
                            float* d = acc_o[mt][nn * 2 + h];
                            mma16816(d, pa_h[mt], bvh[h * 2], bvh[h * 2 + 1]);
                            mma16816(d, pa_h[mt], bvl[h * 2], bvl[h * 2 + 1]);
                            mma16816(d, pa_l[mt], bvh[h * 2], bvh[h * 2 + 1]);
                        }
                }
            }
        }
    }
    __syncthreads();

    /* ---- epilogue: normalize, split, store bf16 h/l ---- */
#pragma unroll
    for (int mt = 0; mt < 2; mt++) {
        int rb = wm2 * 32 + mt * 16 + (lid >> 2);
#pragma unroll
        for (int sub = 0; sub < 2; sub++) {
            int r = rb + sub * 8;
            float inv = 1.0f / l_sm[r];
            int tq = tq0 + (r & 31);
            int n = khead * 2 + (r >> 5);
            size_t base = ((size_t)(b * TT + tq)) * 4096 + n * HDIM
                        + wn2 * 64 + (lid & 3) * 2;
#pragma unroll
            for (int nt = 0; nt < 8; nt++) {
                float o0 = acc_o[mt][nt][sub * 2 + 0] * inv;
                float o1 = acc_o[mt][nt][sub * 2 + 1] * inv;
                unsigned short h0, l0, h1, l1;
                split1(o0, h0, l0);
                split1(o1, h1, l1);
                *(uint32_t*)(ench + base + nt * 8) = (uint32_t)h0 | ((uint32_t)h1 << 16);
                *(uint32_t*)(encl + base + nt * 8) = (uint32_t)l0 | ((uint32_t)l1 << 16);
            }
        }
    }
}

/* ---------------- host launcher ---------------- */
extern "C" void kernel_launch(void* const* d_in, const int* in_sizes, int n_in,
                              void* d_out, int out_size)
{
    const float* x      = (const float*)d_in[0];
    const int*   segpos = (const int*)d_in[1];
    const float* q_w    = (const float*)d_in[3];
    const float* kv_w   = (const float*)d_in[4];
    const float* out_w  = (const float*)d_in[5];
    float* out = (float*)d_out;

    void *wth, *wtl, *owth, *owtl, *xh, *xl, *ench, *encl, *qkv;
    void *qhb, *qlb, *khb, *klb, *vhb, *vlb;
    cudaGetSymbolAddress(&wth,  g_wt_h);
    cudaGetSymbolAddress(&wtl,  g_wt_l);
    cudaGetSymbolAddress(&owth, g_owt_h);
    cudaGetSymbolAddress(&owtl, g_owt_l);
    cudaGetSymbolAddress(&xh,   g_xh);
    cudaGetSymbolAddress(&xl,   g_xl);
    cudaGetSymbolAddress(&ench, g_ench);
    cudaGetSymbolAddress(&encl, g_encl);
    cudaGetSymbolAddress(&qkv,  g_qkv);
    cudaGetSymbolAddress(&qhb,  g_qh);
    cudaGetSymbolAddress(&qlb,  g_ql);
    cudaGetSymbolAddress(&khb,  g_kh);
    cudaGetSymbolAddress(&klb,  g_kl);
    cudaGetSymbolAddress(&vhb,  g_vh);
    cudaGetSymbolAddress(&vlb,  g_vl);

    float* qkvf = (float*)qkv;

    const int GSMEM = 2 * 4 * 16384;
    cudaFuncSetAttribute(gemm_mma, cudaFuncAttributeMaxDynamicSharedMemorySize, GSMEM);
    cudaFuncSetAttribute(attn_mma, cudaFuncAttributeMaxDynamicSharedMemorySize, ASMEM);

    /* prep */
    ts_kernel<<<1, 128>>>();
    trans_qkv_w<<<dim3(8192 / 32, DD / 32), 256>>>(q_w, kv_w);
    trans_ow<<<dim3(DD / 32, 4096 / 32), 256>>>(out_w);
    {
        int n4 = MTOT * DD / 4;
        convert_split<<<(n4 + 255) / 256, 256>>>((const float4*)x, (ushort4*)xh, (ushort4*)xl, n4);
    }

    /* GEMM1: qkv = x @ [q_w | k_w | v_w] */
    gemm_mma<<<dim3(8192 / 128, MTOT / 128), 256, GSMEM>>>(
        (const __nv_bfloat16*)xh, (const __nv_bfloat16*)xl, DD,
        (const __nv_bfloat16*)wth, (const __nv_bfloat16*)wtl, DD,
        qkvf, QSTR, DD);

    /* RoPE + bf16 split of Q (scale folded) and K */
    {
        int totq = MTOT * NHE * 128;
        rope_split<<<totq / 256, 256>>>(qkvf, segpos, NHE, 0, SCALE_F,
                                        (unsigned short*)qhb, (unsigned short*)qlb,
                                        4096, totq);
        int totk = MTOT * KHE * 128;
        rope_split<<<totk / 256, 256>>>(qkvf, segpos, KHE, 4096, 1.0f,
                                        (unsigned short*)khb, (unsigned short*)klb,
                                        2048, totk);
    }
    /* split V */
    vsplit<<<MTOT * 512 / 256, 256>>>((const float4*)qkvf, (ushort4*)vhb, (ushort4*)vlb);

    /* attention -> ench/encl (bf16 splits, ready for GEMM2) */
    attn_mma<<<dim3(TT / AQ, KHE, BB), 256, ASMEM>>>(
        (const __nv_bfloat16*)qhb, (const __nv_bfloat16*)qlb,
        (const __nv_bfloat16*)khb, (const __nv_bfloat16*)klb,
        (const __nv_bfloat16*)vhb, (const __nv_bfloat16*)vlb,
        segpos,
        (__nv_bfloat16*)ench, (__nv_bfloat16*)encl);

    /* GEMM2: out = enc @ out_w */
    gemm_mma<<<dim3(DD / 128, MTOT / 128), 256, GSMEM>>>(
        (const __nv_bfloat16*)ench, (const __nv_bfloat16*)encl, 4096,
        (const __nv_bfloat16*)owth, (const __nv_bfloat16*)owtl, 4096,
        out, DD, 4096);
}

// round 7
// speedup vs baseline: 4.3511x; 1.2776x over previous
#include <cuda_runtime.h>
#include <cuda_bf16.h>
#include <math.h>
#include <stdint.h>

#define BB 2
#define TT 2048
#define DD 3584
#define NHE 16
#define KHE 8
#define HDIM 256
#define WIN 1024
#define SCALE_F 0.0625f
#define MTOT (BB*TT)         /* 4096 */
#define QSTR 8192            /* row stride of fused qkv fp32 buffer */

/* ---------------- device globals (no allocations allowed) ---------------- */
__device__ __align__(128) __nv_bfloat16 g_wt_h[(size_t)8192 * DD];
__device__ __align__(128) __nv_bfloat16 g_wt_l[(size_t)8192 * DD];
__device__ __align__(128) __nv_bfloat16 g_owt_h[(size_t)DD * 4096];
__device__ __align__(128) __nv_bfloat16 g_owt_l[(size_t)DD * 4096];
__device__ __align__(128) __nv_bfloat16 g_xh[(size_t)MTOT * DD];
__device__ __align__(128) __nv_bfloat16 g_xl[(size_t)MTOT * DD];
__device__ __align__(128) __nv_bfloat16 g_ench[(size_t)MTOT * 4096];
__device__ __align__(128) __nv_bfloat16 g_encl[(size_t)MTOT * 4096];
__device__ __align__(128) __nv_bfloat16 g_qh[(size_t)MTOT * 4096];
__device__ __align__(128) __nv_bfloat16 g_ql[(size_t)MTOT * 4096];
__device__ __align__(128) __nv_bfloat16 g_kh[(size_t)MTOT * 2048];
__device__ __align__(128) __nv_bfloat16 g_kl[(size_t)MTOT * 2048];
__device__ __align__(128) __nv_bfloat16 g_vh[(size_t)MTOT * 2048];
__device__ __align__(128) __nv_bfloat16 g_vl[(size_t)MTOT * 2048];
__device__ __align__(128) float g_qkv[(size_t)MTOT * QSTR];
__device__ __align__(128) float2 g_sc[(size_t)MTOT * 128];
__device__ float g_ts[128];

/* ---------------- small helpers ---------------- */
__device__ __forceinline__ float rcp_fast(float x) {
    float r;
    asm("rcp.approx.f32 %0, %1;" : "=f"(r) : "f"(x));
    return r;
}
__device__ __forceinline__ float tanh_acc(float x) {
    float ax = fabsf(x);
    float e  = __expf(2.0f * ax);
    float r  = 1.0f - 2.0f * rcp_fast(e + 1.0f);   /* e=inf -> rcp=0 -> r=1 */
    return x < 0.0f ? -r : r;
}

__device__ __forceinline__ void split1(float f, unsigned short& h, unsigned short& l) {
    __nv_bfloat16 hb = __float2bfloat16(f);
    float res = f - __bfloat162float(hb);
    __nv_bfloat16 lb = __float2bfloat16(res);
    h = __bfloat16_as_ushort(hb);
    l = __bfloat16_as_ushort(lb);
}

__device__ __forceinline__ uint32_t smem_u32(const void* p) {
    uint32_t a;
    asm("{ .reg .u64 t; cvta.to.shared.u64 t, %1; cvt.u32.u64 %0, t; }" : "=r"(a) : "l"(p));
    return a;
}
__device__ __forceinline__ uint32_t swz(uint32_t off) {       /* SW128 */
    return off ^ ((off >> 3) & 0x70);
}
__device__ __forceinline__ void cp16(uint32_t saddr, const void* gaddr) {
    asm volatile("cp.async.cg.shared.global [%0], [%1], 16;" :: "r"(saddr), "l"(gaddr));
}
__device__ __forceinline__ void cp4(uint32_t saddr, const void* gaddr) {
    asm volatile("cp.async.ca.shared.global [%0], [%1], 4;" :: "r"(saddr), "l"(gaddr));
}
__device__ __forceinline__ void cp_commit() {
    asm volatile("cp.async.commit_group;" ::: "memory");
}
template <int N>
__device__ __forceinline__ void cp_wait() {
    asm volatile("cp.async.wait_group %0;" :: "n"(N) : "memory");
}
__device__ __forceinline__ void ldm4(uint32_t* r, uint32_t addr) {
    asm volatile("ldmatrix.sync.aligned.m8n8.x4.shared.b16 {%0,%1,%2,%3}, [%4];"
                 : "=r"(r[0]), "=r"(r[1]), "=r"(r[2]), "=r"(r[3]) : "r"(addr));
}
__device__ __forceinline__ void ldm4t(uint32_t* r, uint32_t addr) {
    asm volatile("ldmatrix.sync.aligned.m8n8.x4.trans.shared.b16 {%0,%1,%2,%3}, [%4];"
                 : "=r"(r[0]), "=r"(r[1]), "=r"(r[2]), "=r"(r[3]) : "r"(addr));
}
__device__ __forceinline__ void mma16816(float* d, const uint32_t* a,
                                         uint32_t b0, uint32_t b1) {
    asm volatile("mma.sync.aligned.m16n8k16.row.col.f32.bf16.bf16.f32 "
                 "{%0,%1,%2,%3}, {%4,%5,%6,%7}, {%8,%9}, {%0,%1,%2,%3};"
                 : "+f"(d[0]), "+f"(d[1]), "+f"(d[2]), "+f"(d[3])
                 : "r"(a[0]), "r"(a[1]), "r"(a[2]), "r"(a[3]), "r"(b0), "r"(b1));
}

/* ---------------- prep kernels ---------------- */
__global__ void ts_kernel() {
    int i = threadIdx.x;
    if (i < 128)
        g_ts[i] = (float)pow(10000.0, (double)i / 128.0);
}

/* per-(bt,i) sin/cos table; one double sincos per entry */
__global__ void sc_kernel(const int* __restrict__ segpos) {
    int idx = blockIdx.x * 256 + threadIdx.x;          /* MTOT*128 */
    int bt = idx >> 7, i = idx & 127;
    int pos = segpos[bt];
    float ts = g_ts[i];
    float angf = __fdiv_rn((float)pos, ts);
    double sd, cd;
    sincos((double)angf, &sd, &cd);
    g_sc[idx] = make_float2((float)sd, (float)cd);
}

__global__ void __launch_bounds__(256) trans_qkv_w(const float* __restrict__ qw,
                                                   const float* __restrict__ kvw) {
    __shared__ float t[32][33];
    int c0 = blockIdx.x * 32, d0 = blockIdx.y * 32;
    int tx = threadIdx.x & 31, ty = threadIdx.x >> 5;
    int head = c0 >> 8, hb = c0 & 255;
    const float* src = (head < NHE) ? (qw + (size_t)head * DD * HDIM)
                                    : (kvw + (size_t)(head - NHE) * DD * HDIM);
#pragma unroll
    for (int i = 0; i < 4; i++)
        t[ty + 8 * i][tx] = src[(size_t)(d0 + ty + 8 * i) * HDIM + hb + tx];
    __syncthreads();
#pragma unroll
    for (int i = 0; i < 4; i++) {
        float f = t[tx][ty + 8 * i];
        unsigned short h, l; split1(f, h, l);
        size_t o = (size_t)(c0 + ty + 8 * i) * DD + d0 + tx;
        ((unsigned short*)g_wt_h)[o] = h;
        ((unsigned short*)g_wt_l)[o] = l;
    }
}

__global__ void __launch_bounds__(256) trans_ow(const float* __restrict__ ow) {
    __shared__ float t[32][33];
    int c0 = blockIdx.x * 32, r0 = blockIdx.y * 32;
    int tx = threadIdx.x & 31, ty = threadIdx.x >> 5;
#pragma unroll
    for (int i = 0; i < 4; i++)
        t[ty + 8 * i][tx] = ow[(size_t)(r0 + ty + 8 * i) * DD + c0 + tx];
    __syncthreads();
#pragma unroll
    for (int i = 0; i < 4; i++) {
        float f = t[tx][ty + 8 * i];
        unsigned short h, l; split1(f, h, l);
        size_t o = (size_t)(c0 + ty + 8 * i) * 4096 + r0 + tx;
        ((unsigned short*)g_owt_h)[o] = h;
        ((unsigned short*)g_owt_l)[o] = l;
    }
}

__global__ void convert_split(const float4* __restrict__ src, ushort4* __restrict__ h,
                              ushort4* __restrict__ l, int n4) {
    int i = blockIdx.x * 256 + threadIdx.x;
    if (i >= n4) return;
    float4 v = src[i];
    ushort4 uh, ul;
    split1(v.x, uh.x, ul.x);
    split1(v.y, uh.y, ul.y);
    split1(v.z, uh.z, ul.z);
    split1(v.w, uh.w, ul.w);
    h[i] = uh;
    l[i] = ul;
}

/* rope (table-driven) + bf16-split writeout */
__global__ void rope_split(const float* __restrict__ qkv, int heads, int colbase,
                           float scale, unsigned short* __restrict__ oh,
                           unsigned short* __restrict__ ol, int ostride, int total) {
    int idx = blockIdx.x * 256 + threadIdx.x;
    if (idx >= total) return;
    int i = idx & 127;
    int rest = idx >> 7;
    int head = rest % heads;
    int bt = rest / heads;
    float2 sc = g_sc[(size_t)bt * 128 + i];
    float s = sc.x, c = sc.y;
    const float* p = qkv + (size_t)bt * QSTR + colbase + head * HDIM;
    float first = p[i], second = p[i + 128];
    float o1 = (first * c - second * s) * scale;
    float o2 = (second * c + first * s) * scale;
    size_t ob = (size_t)bt * ostride + head * HDIM;
    unsigned short h, l;
    split1(o1, h, l); oh[ob + i] = h;       ol[ob + i] = l;
    split1(o2, h, l); oh[ob + i + 128] = h; ol[ob + i + 128] = l;
}

/* split V region of qkv into g_vh/g_vl */
__global__ void vsplit(const float4* __restrict__ qkv4, ushort4* __restrict__ vh,
                       ushort4* __restrict__ vl) {
    int idx = blockIdx.x * 256 + threadIdx.x;     /* MTOT*512 */
    int bt = idx >> 9, c = idx & 511;
    float4 v = qkv4[(size_t)bt * 2048 + 1536 + c];
    ushort4 uh, ul;
    split1(v.x, uh.x, ul.x);
    split1(v.y, uh.y, ul.y);
    split1(v.z, uh.z, ul.z);
    split1(v.w, uh.w, ul.w);
    vh[(size_t)bt * 512 + c] = uh;
    vl[(size_t)bt * 512 + c] = ul;
}

/* ---------------- mma.sync bf16-split GEMM, 256x128 tile ----------------
   C[M,N] = A[M,K] x B^T, B rows are output columns (K-major).
   8 warps as 4(m) x 2(n), each 64x64. K-chunk 64, 2-stage cp.async.
   3-way bf16 split: AhBh + AhBl + AlBh, fp32 accum. */
#define GK 64
#define G_AH 0u
#define G_AL 32768u
#define G_BH 65536u
#define G_BL 81920u
#define GSTAGE 98304u
#define GSMEM  196608

__device__ __forceinline__ void gemm_load(
    uint32_t sbase, int st, int k0, int row0, int col0,
    const __nv_bfloat16* Ah, const __nv_bfloat16* Al, int lda,
    const __nv_bfloat16* Bh, const __nv_bfloat16* Bl, int ldb, int tid)
{
    uint32_t sb = sbase + (uint32_t)st * GSTAGE;
#pragma unroll
    for (int t = 0; t < 16; t++) {             /* A: 256 rows x 128B, h+l */
        int idx = t * 256 + tid;
        int split = idx >> 11, rem = idx & 2047;
        int r = rem >> 3, c8 = rem & 7;
        uint32_t so = swz((uint32_t)(r * 128 + c8 * 16));
        size_t g = (size_t)(row0 + r) * lda + k0 + c8 * 8;
        cp16(sb + (split ? G_AL : G_AH) + so, (split ? Al : Ah) + g);
    }
#pragma unroll
    for (int t = 0; t < 8; t++) {              /* B: 128 rows x 128B, h+l */
        int idx = t * 256 + tid;
        int split = idx >> 10, rem = idx & 1023;
        int r = rem >> 3, c8 = rem & 7;
        uint32_t so = swz((uint32_t)(r * 128 + c8 * 16));
        size_t g = (size_t)(col0 + r) * ldb + k0 + c8 * 8;
        cp16(sb + (split ? G_BL : G_BH) + so, (split ? Bl : Bh) + g);
    }
}

__global__ void __launch_bounds__(256, 1) gemm_mma(
    const __nv_bfloat16* __restrict__ Ah, const __nv_bfloat16* __restrict__ Al, int lda,
    const __nv_bfloat16* __restrict__ Bh, const __nv_bfloat16* __restrict__ Bl, int ldb,
    float* __restrict__ C, int ldc, int Kd)
{
    extern __shared__ __align__(1024) char smem[];
    const uint32_t sbase = smem_u32(smem);
    const int tid = threadIdx.x;
    const int wid = tid >> 5, lid = tid & 31;
    const int wm = wid & 3, wn = wid >> 2;
    const int row0 = blockIdx.y * 256;
    const int col0 = blockIdx.x * 128;

    float acc[4][8][4];
#pragma unroll
    for (int i = 0; i < 4; i++)
#pragma unroll
        for (int j = 0; j < 8; j++)
#pragma unroll
            for (int kq = 0; kq < 4; kq++) acc[i][j][kq] = 0.0f;

    const int nch = Kd / GK;

    gemm_load(sbase, 0, 0, row0, col0, Ah, Al, lda, Bh, Bl, ldb, tid);
    cp_commit();

    const int rAl = lid & 15;                 /* row-within-frag for A */
    const int cA  = lid >> 4;
    const int rBl = (lid & 7) + ((lid >> 4) & 1) * 8;
    const int cB  = (lid >> 3) & 1;

    for (int c = 0; c < nch; c++) {
        const int st = c & 1;
        if (c + 1 < nch) {
            gemm_load(sbase, st ^ 1, (c + 1) * GK, row0, col0, Ah, Al, lda, Bh, Bl, ldb, tid);
            cp_commit();
            cp_wait<1>();
        } else {
            cp_wait<0>();
        }
        __syncthreads();

        uint32_t sb = sbase + (uint32_t)st * GSTAGE;
#pragma unroll
        for (int ks = 0; ks < 4; ks++) {
            const int kc8 = ks * 2;
            uint32_t ah[4][4], al[4][4];
#pragma unroll
            for (int m4 = 0; m4 < 4; m4++) {
                uint32_t off = swz((uint32_t)((wm * 64 + m4 * 16 + rAl) * 128 + (kc8 + cA) * 16));
                ldm4(ah[m4], sb + G_AH + off);
                ldm4(al[m4], sb + G_AL + off);
            }
#pragma unroll
            for (int n16 = 0; n16 < 4; n16++) {
                uint32_t bh[4], bl[4];
                uint32_t off = swz((uint32_t)((wn * 64 + n16 * 16 + rBl) * 128 + (kc8 + cB) * 16));
                ldm4(bh, sb + G_BH + off);
                ldm4(bl, sb + G_BL + off);
#pragma unroll
                for (int m4 = 0; m4 < 4; m4++)
#pragma unroll
                    for (int h = 0; h < 2; h++) {
                        float* d = acc[m4][n16 * 2 + h];
                        mma16816(d, ah[m4], bh[h * 2], bh[h * 2 + 1]);
                        mma16816(d, ah[m4], bl[h * 2], bl[h * 2 + 1]);
                        mma16816(d, al[m4], bh[h * 2], bh[h * 2 + 1]);
                    }
            }
        }
        __syncthreads();
    }

#pragma unroll
    for (int m4 = 0; m4 < 4; m4++)
#pragma unroll
        for (int nt = 0; nt < 8; nt++) {
            int r = row0 + wm * 64 + m4 * 16 + (lid >> 2);
            int cc = col0 + wn * 64 + nt * 8 + (lid & 3) * 2;
            float* p0 = C + (size_t)r * ldc + cc;
            p0[0] = acc[m4][nt][0];
            p0[1] = acc[m4][nt][1];
            float* p1 = C + (size_t)(r + 8) * ldc + cc;
            p1[0] = acc[m4][nt][2];
            p1[1] = acc[m4][nt][3];
        }
}

/* ---------------- tensor-core flash attention (validated R6 structure) ------ */
#define AQ 32
#define ABK 32
#define ASPAD 36

#define QHOFF   0u
#define QLOFF   32768u
#define KHOFF   65536u
#define KLOFF   98304u
#define VHOFF   131072u
#define VLOFF   163840u
#define SSOFF   196608u
#define PHOFF   205824u
#define PLOFF   214016u
#define POSQOFF 222208u
#define POSKOFF 222336u
#define MOFF    222592u
#define LOFF    222848u
#define CORROFF 223104u
#define ASMEM   223360

__device__ __forceinline__ void attn_load_stage(
    uint32_t sbase, int st, int s0, int b, int khead,
    const __nv_bfloat16* kh, const __nv_bfloat16* kl,
    const __nv_bfloat16* vh, const __nv_bfloat16* vl,
    const int* segpos, int tid)
{
    size_t gbase = ((size_t)(b * TT + s0)) * 2048 + khead * HDIM;
#pragma unroll
    for (int t = 0; t < 8; t++) {
        int idx = t * 256 + tid;
        int split = idx >> 10, rem = idx & 1023;
        int p = rem >> 8, r = (rem >> 3) & 31, ch = rem & 7;
        size_t g = gbase + (size_t)r * 2048 + p * 64 + ch * 8;
        uint32_t so = swz((uint32_t)(r * 128 + ch * 16));
        cp16(sbase + (split ? KLOFF : KHOFF) + st * 16384 + p * 4096 + so,
             (split ? kl : kh) + g);
        cp16(sbase + (split ? VLOFF : VHOFF) + st * 16384 + p * 4096 + so,
             (split ? vl : vh) + g);
    }
    if (tid < ABK)
        cp4(sbase + POSKOFF + st * 128 + tid * 4, segpos + b * TT + s0 + tid);
}

__global__ void __launch_bounds__(256) attn_mma(
    const __nv_bfloat16* __restrict__ qh, const __nv_bfloat16* __restrict__ ql,
    const __nv_bfloat16* __restrict__ kh, const __nv_bfloat16* __restrict__ kl,
    const __nv_bfloat16* __restrict__ vh, const __nv_bfloat16* __restrict__ vl,
    const int* __restrict__ segpos,
    __nv_bfloat16* __restrict__ ench, __nv_bfloat16* __restrict__ encl)
{
    extern __shared__ __align__(1024) char smemc[];
    const uint32_t sbase = smem_u32(smemc);
    const int tid = threadIdx.x;
    const int wid = tid >> 5, lid = tid & 31;
    const int tile = (int)(gridDim.x - 1) - (int)blockIdx.x;
    const int khead = blockIdx.y;
    const int b = blockIdx.z;
    const int tq0 = tile * AQ;

    float* s_s    = (float*)(smemc + SSOFF);
    int*   posq   = (int*)(smemc + POSQOFF);
    int*   posk   = (int*)(smemc + POSKOFF);
    float* m_sm   = (float*)(smemc + MOFF);
    float* l_sm   = (float*)(smemc + LOFF);
    float* corr_s = (float*)(smemc + CORROFF);

    int s_begin = tq0 - (WIN - 1);
    if (s_begin < 0) s_begin = 0;
    s_begin &= ~(ABK - 1);
    const int nit = (tq0 + AQ - s_begin) / ABK;

    {
#pragma unroll
        for (int t = 0; t < 16; t++) {
            int idx = t * 256 + tid;
            int split = idx >> 11, rem = idx & 2047;
            int p = rem >> 9, r = (rem >> 3) & 63, ch = rem & 7;
            int tq = tq0 + (r & 31);
            int n = khead * 2 + (r >> 5);
            size_t g = ((size_t)(b * TT + tq)) * 4096 + n * HDIM + p * 64 + ch * 8;
            uint32_t so = swz((uint32_t)(r * 128 + ch * 16));
            cp16(sbase + (split ? QLOFF : QHOFF) + p * 8192 + so, (split ? ql : qh) + g);
        }
        if (tid < AQ) cp4(sbase + POSQOFF + tid * 4, segpos + b * TT + tq0 + tid);
        attn_load_stage(sbase, 0, s_begin, b, khead, kh, kl, vh, vl, segpos, tid);
        cp_commit();
    }
    if (tid < 64) { m_sm[tid] = -1e30f; l_sm[tid] = 0.0f; }

    float acc_o[2][8][4];
#pragma unroll
    for (int mt = 0; mt < 2; mt++)
#pragma unroll
        for (int nt = 0; nt < 8; nt++)
#pragma unroll
            for (int q = 0; q < 4; q++) acc_o[mt][nt][q] = 0.0f;

    const int wm = wid & 3, wn = wid >> 2;
    const int rA = wm * 16 + (lid & 15);
    const int cA = lid >> 4;
    const int rB = wn * 16 + (lid & 7) + ((lid >> 4) & 1) * 8;
    const int cB = (lid >> 3) & 1;
    const int wm2 = wid & 1, wn2 = wid >> 1;

    for (int it = 0; it < nit; it++) {
        const int st = it & 1;
        const int s0 = s_begin + it * ABK;
        cp_wait<0>();
        __syncthreads();

        if (it + 1 < nit) {
            attn_load_stage(sbase, st ^ 1, s0 + ABK, b, khead, kh, kl, vh, vl, segpos, tid);
            cp_commit();
        }

        /* ---- QK ---- */
        {
            float acc_s[2][4] = {{0,0,0,0},{0,0,0,0}};
            uint32_t khb = sbase + KHOFF + st * 16384;
            uint32_t klb = sbase + KLOFF + st * 16384;
#pragma unroll
            for (int ks = 0; ks < 16; ks++) {
                int p = ks >> 2, c2 = (ks & 3) * 2;
                uint32_t ah[4], al[4], bh[4], bl[4];
                uint32_t ao = swz((uint32_t)(rA * 128 + (c2 + cA) * 16));
                ldm4(ah, sbase + QHOFF + p * 8192 + ao);
                ldm4(al, sbase + QLOFF + p * 8192 + ao);
                uint32_t bo = swz((uint32_t)(rB * 128 + (c2 + cB) * 16));
                ldm4(bh, khb + p * 4096 + bo);
                ldm4(bl, klb + p * 4096 + bo);
                mma16816(acc_s[0], ah, bh[0], bh[1]);
                mma16816(acc_s[0], ah, bl[0], bl[1]);
                mma16816(acc_s[0], al, bh[0], bh[1]);
                mma16816(acc_s[1], ah, bh[2], bh[3]);
                mma16816(acc_s[1], ah, bl[2], bl[3]);
                mma16816(acc_s[1], al, bh[2], bh[3]);
            }
            int sr = wm * 16 + (lid >> 2);
            int sc = wn * 16 + (lid & 3) * 2;
#pragma unroll
            for (int nt = 0; nt < 2; nt++) {
                s_s[sr * ASPAD + sc + nt * 8]       = acc_s[nt][0];
                s_s[sr * ASPAD + sc + nt * 8 + 1]   = acc_s[nt][1];
                s_s[(sr + 8) * ASPAD + sc + nt * 8]     = acc_s[nt][2];
                s_s[(sr + 8) * ASPAD + sc + nt * 8 + 1] = acc_s[nt][3];
            }
        }
        __syncthreads();

        /* ---- softmax ---- */
        {
            int row = tid >> 2, qq = tid & 3;
            int ti = tq0 + (row & 31);
            int pq = posq[row & 31];
            const int* pks = posk + st * 32;
            float sc[8];
            float bmax = -1e30f;
#pragma unroll
            for (int j = 0; j < 8; j++) {
                int col = qq * 8 + j;
                float raw = s_s[row * ASPAD + col];
                float cap = tanh_acc(raw * 0.02f) * 50.0f;
                int si = s0 + col;
                int pk = pks[col];
                bool valid = (si <= ti) && (pk > pq - WIN) && (pk < pq + WIN);
                sc[j] = valid ? cap : -1e30f;
                bmax = fmaxf(bmax, sc[j]);
            }
            bmax = fmaxf(bmax, __shfl_xor_sync(0xffffffffu, bmax, 1));
            bmax = fmaxf(bmax, __shfl_xor_sync(0xffffffffu, bmax, 2));
            float m_old = m_sm[row];
            float m_new = fmaxf(m_old, bmax);
            float corr = __expf(m_old - m_new);
            float psum = 0.0f;
#pragma unroll
            for (int jp = 0; jp < 4; jp++) {
                float p0 = (sc[jp*2]   < -1e29f) ? 0.0f : __expf(sc[jp*2]   - m_new);
                float p1 = (sc[jp*2+1] < -1e29f) ? 0.0f : __expf(sc[jp*2+1] - m_new);
                psum += p0 + p1;
                unsigned short h0, l0, h1, l1;
                split1(p0, h0, l0);
                split1(p1, h1, l1);
                uint32_t byteoff = (uint32_t)(row * 128 + (qq * 8 + jp * 2) * 2);
                uint32_t sw = byteoff ^ ((byteoff >> 3) & 0x70);
                *(uint32_t*)(smemc + PHOFF + sw) = (uint32_t)h0 | ((uint32_t)h1 << 16);
                *(uint32_t*)(smemc + PLOFF + sw) = (uint32_t)l0 | ((uint32_t)l1 << 16);
            }
            psum += __shfl_xor_sync(0xffffffffu, psum, 1);
            psum += __shfl_xor_sync(0xffffffffu, psum, 2);
            if ((tid & 3) == 0) {
                l_sm[row] = l_sm[row] * corr + psum;
                m_sm[row] = m_new;
                corr_s[row] = corr;
            }
        }
        __syncthreads();

        /* ---- rescale + PV ---- */
        {
#pragma unroll
            for (int mt = 0; mt < 2; mt++) {
                int r0 = wm2 * 32 + mt * 16 + (lid >> 2);
                float c0 = corr_s[r0], c1 = corr_s[r0 + 8];
#pragma unroll
                for (int nt = 0; nt < 8; nt++) {
                    acc_o[mt][nt][0] *= c0; acc_o[mt][nt][1] *= c0;
                    acc_o[mt][nt][2] *= c1; acc_o[mt][nt][3] *= c1;
                }
            }
            uint32_t vhb = sbase + VHOFF + st * 16384 + wn2 * 4096;
            uint32_t vlb = sbase + VLOFF + st * 16384 + wn2 * 4096;
#pragma unroll
            for (int ks2 = 0; ks2 < 2; ks2++) {
                uint32_t pa_h[2][4], pa_l[2][4];
#pragma unroll
                for (int mt = 0; mt < 2; mt++) {
                    int rA2 = wm2 * 32 + mt * 16 + (lid & 15);
                    uint32_t bo = swz((uint32_t)(rA2 * 128 + (ks2 * 2 + (lid >> 4)) * 16));
                    ldm4(pa_h[mt], sbase + PHOFF + bo);
                    ldm4(pa_l[mt], sbase + PLOFF + bo);
                }
#pragma unroll
                for (int nn = 0; nn < 4; nn++) {
                    int tl = lid >> 3;
                    int srow = (tl & 1) * 8 + (lid & 7) + ks2 * 16;
                    uint32_t bo = swz((uint32_t)(srow * 128 + (nn * 16 + (tl >> 1) * 8) * 2));
                    uint32_t bvh[4], bvl[4];
                    ldm4t(bvh, vhb + bo);
                    ldm4t(bvl, vlb + bo);
#pragma unroll
                    for (int mt = 0; mt < 2; mt++)
#pragma unroll
                        for (int h = 0; h < 2; h++) {
                            float* d = acc_o[mt][nn * 2 + h];
                            mma16816(d, pa_h[mt], bvh[h * 2], bvh[h * 2 + 1]);
                            mma16816(d, pa_h[mt], bvl[h * 2], bvl[h * 2 + 1]);
                            mma16816(d, pa_l[mt], bvh[h * 2], bvh[h * 2 + 1]);
                        }
                }
            }
        }
    }
    __syncthreads();

    /* ---- epilogue ---- */
#pragma unroll
    for (int mt = 0; mt < 2; mt++) {
        int rb = wm2 * 32 + mt * 16 + (lid >> 2);
#pragma unroll
        for (int sub = 0; sub < 2; sub++) {
            int r = rb + sub * 8;
            float inv = 1.0f / l_sm[r];
            int tq = tq0 + (r & 31);
            int n = khead * 2 + (r >> 5);
            size_t base = ((size_t)(b * TT + tq)) * 4096 + n * HDIM
                        + wn2 * 64 + (lid & 3) * 2;
#pragma unroll
            for (int nt = 0; nt < 8; nt++) {
                float o0 = acc_o[mt][nt][sub * 2 + 0] * inv;
                float o1 = acc_o[mt][nt][sub * 2 + 1] * inv;
                unsigned short h0, l0, h1, l1;
                split1(o0, h0, l0);
                split1(o1, h1, l1);
                *(uint32_t*)(ench + base + nt * 8) = (uint32_t)h0 | ((uint32_t)h1 << 16);
                *(uint32_t*)(encl + base + nt * 8) = (uint32_t)l0 | ((uint32_t)l1 << 16);
            }
        }
    }
}

/* ---------------- host launcher ---------------- */
extern "C" void kernel_launch(void* const* d_in, const int* in_sizes, int n_in,
                              void* d_out, int out_size)
{
    const float* x      = (const float*)d_in[0];
    const int*   segpos = (const int*)d_in[1];
    const float* q_w    = (const float*)d_in[3];
    const float* kv_w   = (const float*)d_in[4];
    const float* out_w  = (const float*)d_in[5];
    float* out = (float*)d_out;

    void *wth, *wtl, *owth, *owtl, *xh, *xl, *ench, *encl, *qkv;
    void *qhb, *qlb, *khb, *klb, *vhb, *vlb;
    cudaGetSymbolAddress(&wth,  g_wt_h);
    cudaGetSymbolAddress(&wtl,  g_wt_l);
    cudaGetSymbolAddress(&owth, g_owt_h);
    cudaGetSymbolAddress(&owtl, g_owt_l);
    cudaGetSymbolAddress(&xh,   g_xh);
    cudaGetSymbolAddress(&xl,   g_xl);
    cudaGetSymbolAddress(&ench, g_ench);
    cudaGetSymbolAddress(&encl, g_encl);
    cudaGetSymbolAddress(&qkv,  g_qkv);
    cudaGetSymbolAddress(&qhb,  g_qh);
    cudaGetSymbolAddress(&qlb,  g_ql);
    cudaGetSymbolAddress(&khb,  g_kh);
    cudaGetSymbolAddress(&klb,  g_kl);
    cudaGetSymbolAddress(&vhb,  g_vh);
    cudaGetSymbolAddress(&vlb,  g_vl);

    float* qkvf = (float*)qkv;

    cudaFuncSetAttribute(gemm_mma, cudaFuncAttributeMaxDynamicSharedMemorySize, GSMEM);
    cudaFuncSetAttribute(attn_mma, cudaFuncAttributeMaxDynamicSharedMemorySize, ASMEM);

    /* prep */
    ts_kernel<<<1, 128>>>();
    sc_kernel<<<MTOT * 128 / 256, 256>>>(segpos);
    trans_qkv_w<<<dim3(8192 / 32, DD / 32), 256>>>(q_w, kv_w);
    trans_ow<<<dim3(DD / 32, 4096 / 32), 256>>>(out_w);
    {
        int n4 = MTOT * DD / 4;
        convert_split<<<(n4 + 255) / 256, 256>>>((const float4*)x, (ushort4*)xh, (ushort4*)xl, n4);
    }

    /* GEMM1: qkv = x @ [q_w | k_w | v_w]  (M=4096, N=8192, K=3584) */
    gemm_mma<<<dim3(8192 / 128, MTOT / 256), 256, GSMEM>>>(
        (const __nv_bfloat16*)xh, (const __nv_bfloat16*)xl, DD,
        (const __nv_bfloat16*)wth, (const __nv_bfloat16*)wtl, DD,
        qkvf, QSTR, DD);

    /* RoPE + bf16 split of Q (scale folded) and K */
    {
        int totq = MTOT * NHE * 128;
        rope_split<<<totq / 256, 256>>>(qkvf, NHE, 0, SCALE_F,
                                        (unsigned short*)qhb, (unsigned short*)qlb,
                                        4096, totq);
        int totk = MTOT * KHE * 128;
        rope_split<<<totk / 256, 256>>>(qkvf, KHE, 4096, 1.0f,
                                        (unsigned short*)khb, (unsigned short*)klb,
                                        2048, totk);
    }
    /* split V */
    vsplit<<<MTOT * 512 / 256, 256>>>((const float4*)qkvf, (ushort4*)vhb, (ushort4*)vlb);

    /* attention -> ench/encl (bf16 splits, ready for GEMM2) */
    attn_mma<<<dim3(TT / AQ, KHE, BB), 256, ASMEM>>>(
        (const __nv_bfloat16*)qhb, (const __nv_bfloat16*)qlb,
        (const __nv_bfloat16*)khb, (const __nv_bfloat16*)klb,
        (const __nv_bfloat16*)vhb, (const __nv_bfloat16*)vlb,
        segpos,
        (__nv_bfloat16*)ench, (__nv_bfloat16*)encl);

    /* GEMM2: out = enc @ out_w  (M=4096, N=3584, K=4096) */
    gemm_mma<<<dim3(DD / 128, MTOT / 256), 256, GSMEM>>>(
        (const __nv_bfloat16*)ench, (const __nv_bfloat16*)encl, 4096,
        (const __nv_bfloat16*)owth, (const __nv_bfloat16*)owtl, 4096,
        out, DD, 4096);
}

// round 8
// speedup vs baseline: 5.9169x; 1.3599x over previous
#include <cuda_runtime.h>
#include <cuda_fp16.h>
#include <math.h>
#include <stdint.h>

#define BB 2
#define TT 2048
#define DD 3584
#define NHE 16
#define KHE 8
#define HDIM 256
#define WIN 1024
#define SCALE_F 0.0625f
#define MTOT (BB*TT)         /* 4096 */
#define QSTR 8192            /* row stride of fused qkv fp32 buffer */

/* ---------------- device globals (no allocations allowed) ---------------- */
__device__ __align__(128) __half g_wt[(size_t)8192 * DD];      /* single fp16 */
__device__ __align__(128) __half g_owt[(size_t)DD * 4096];     /* single fp16 */
__device__ __align__(128) __half g_xh[(size_t)MTOT * DD];
__device__ __align__(128) __half g_xl[(size_t)MTOT * DD];
__device__ __align__(128) __half g_ench[(size_t)MTOT * 4096];
__device__ __align__(128) __half g_encl[(size_t)MTOT * 4096];
__device__ __align__(128) __half g_qh[(size_t)MTOT * 4096];
__device__ __align__(128) __half g_ql[(size_t)MTOT * 4096];
__device__ __align__(128) __half g_kh[(size_t)MTOT * 2048];    /* single */
__device__ __align__(128) __half g_vh[(size_t)MTOT * 2048];    /* single */
__device__ __align__(128) float g_qkv[(size_t)MTOT * QSTR];
__device__ __align__(128) float2 g_sc[(size_t)MTOT * 128];
__device__ float g_ts[128];

/* ---------------- small helpers ---------------- */
__device__ __forceinline__ float rcp_fast(float x) {
    float r;
    asm("rcp.approx.f32 %0, %1;" : "=f"(r) : "f"(x));
    return r;
}
__device__ __forceinline__ float tanh_acc(float x) {
    float ax = fabsf(x);
    float e  = __expf(2.0f * ax);
    float r  = 1.0f - 2.0f * rcp_fast(e + 1.0f);   /* e=inf -> rcp=0 -> r=1 */
    return x < 0.0f ? -r : r;
}

__device__ __forceinline__ void split1h(float f, unsigned short& h, unsigned short& l) {
    __half hb = __float2half_rn(f);
    float res = f - __half2float(hb);               /* exact */
    __half lb = __float2half_rn(res);
    h = __half_as_ushort(hb);
    l = __half_as_ushort(lb);
}
__device__ __forceinline__ unsigned short h_rn(float f) {
    return __half_as_ushort(__float2half_rn(f));
}

__device__ __forceinline__ uint32_t smem_u32(const void* p) {
    uint32_t a;
    asm("{ .reg .u64 t; cvta.to.shared.u64 t, %1; cvt.u32.u64 %0, t; }" : "=r"(a) : "l"(p));
    return a;
}
__device__ __forceinline__ uint32_t swz(uint32_t off) {       /* SW128 */
    return off ^ ((off >> 3) & 0x70);
}
__device__ __forceinline__ void cp16(uint32_t saddr, const void* gaddr) {
    asm volatile("cp.async.cg.shared.global [%0], [%1], 16;" :: "r"(saddr), "l"(gaddr));
}
__device__ __forceinline__ void cp4(uint32_t saddr, const void* gaddr) {
    asm volatile("cp.async.ca.shared.global [%0], [%1], 4;" :: "r"(saddr), "l"(gaddr));
}
__device__ __forceinline__ void cp_commit() {
    asm volatile("cp.async.commit_group;" ::: "memory");
}
template <int N>
__device__ __forceinline__ void cp_wait() {
    asm volatile("cp.async.wait_group %0;" :: "n"(N) : "memory");
}
__device__ __forceinline__ void ldm4(uint32_t* r, uint32_t addr) {
    asm volatile("ldmatrix.sync.aligned.m8n8.x4.shared.b16 {%0,%1,%2,%3}, [%4];"
                 : "=r"(r[0]), "=r"(r[1]), "=r"(r[2]), "=r"(r[3]) : "r"(addr));
}
__device__ __forceinline__ void ldm4t(uint32_t* r, uint32_t addr) {
    asm volatile("ldmatrix.sync.aligned.m8n8.x4.trans.shared.b16 {%0,%1,%2,%3}, [%4];"
                 : "=r"(r[0]), "=r"(r[1]), "=r"(r[2]), "=r"(r[3]) : "r"(addr));
}
__device__ __forceinline__ void mma16816(float* d, const uint32_t* a,
                                         uint32_t b0, uint32_t b1) {
    asm volatile("mma.sync.aligned.m16n8k16.row.col.f32.f16.f16.f32 "
                 "{%0,%1,%2,%3}, {%4,%5,%6,%7}, {%8,%9}, {%0,%1,%2,%3};"
                 : "+f"(d[0]), "+f"(d[1]), "+f"(d[2]), "+f"(d[3])
                 : "r"(a[0]), "r"(a[1]), "r"(a[2]), "r"(a[3]), "r"(b0), "r"(b1));
}

/* ---------------- prep kernels ---------------- */
__global__ void ts_kernel() {
    int i = threadIdx.x;
    if (i < 128)
        g_ts[i] = (float)pow(10000.0, (double)i / 128.0);
}

__global__ void sc_kernel(const int* __restrict__ segpos) {
    int idx = blockIdx.x * 256 + threadIdx.x;          /* MTOT*128 */
    int bt = idx >> 7, i = idx & 127;
    int pos = segpos[bt];
    float ts = g_ts[i];
    float angf = __fdiv_rn((float)pos, ts);
    double sd, cd;
    sincos((double)angf, &sd, &cd);
    g_sc[idx] = make_float2((float)sd, (float)cd);
}

__global__ void __launch_bounds__(256) trans_qkv_w(const float* __restrict__ qw,
                                                   const float* __restrict__ kvw) {
    __shared__ float t[32][33];
    int c0 = blockIdx.x * 32, d0 = blockIdx.y * 32;
    int tx = threadIdx.x & 31, ty = threadIdx.x >> 5;
    int head = c0 >> 8, hb = c0 & 255;
    const float* src = (head < NHE) ? (qw + (size_t)head * DD * HDIM)
                                    : (kvw + (size_t)(head - NHE) * DD * HDIM);
#pragma unroll
    for (int i = 0; i < 4; i++)
        t[ty + 8 * i][tx] = src[(size_t)(d0 + ty + 8 * i) * HDIM + hb + tx];
    __syncthreads();
#pragma unroll
    for (int i = 0; i < 4; i++) {
        size_t o = (size_t)(c0 + ty + 8 * i) * DD + d0 + tx;
        ((unsigned short*)g_wt)[o] = h_rn(t[tx][ty + 8 * i]);
    }
}

__global__ void __launch_bounds__(256) trans_ow(const float* __restrict__ ow) {
    __shared__ float t[32][33];
    int c0 = blockIdx.x * 32, r0 = blockIdx.y * 32;
    int tx = threadIdx.x & 31, ty = threadIdx.x >> 5;
#pragma unroll
    for (int i = 0; i < 4; i++)
        t[ty + 8 * i][tx] = ow[(size_t)(r0 + ty + 8 * i) * DD + c0 + tx];
    __syncthreads();
#pragma unroll
    for (int i = 0; i < 4; i++) {
        size_t o = (size_t)(c0 + ty + 8 * i) * 4096 + r0 + tx;
        ((unsigned short*)g_owt)[o] = h_rn(t[tx][ty + 8 * i]);
    }
}

__global__ void convert_split(const float4* __restrict__ src, ushort4* __restrict__ h,
                              ushort4* __restrict__ l, int n4) {
    int i = blockIdx.x * 256 + threadIdx.x;
    if (i >= n4) return;
    float4 v = src[i];
    ushort4 uh, ul;
    split1h(v.x, uh.x, ul.x);
    split1h(v.y, uh.y, ul.y);
    split1h(v.z, uh.z, ul.z);
    split1h(v.w, uh.w, ul.w);
    h[i] = uh;
    l[i] = ul;
}

/* rope (table-driven); Q: h+l split; K: single fp16 */
__global__ void rope_split(const float* __restrict__ qkv, int heads, int colbase,
                           float scale, unsigned short* __restrict__ oh,
                           unsigned short* __restrict__ ol, int ostride,
                           int single, int total) {
    int idx = blockIdx.x * 256 + threadIdx.x;
    if (idx >= total) return;
    int i = idx & 127;
    int rest = idx >> 7;
    int head = rest % heads;
    int bt = rest / heads;
    float2 sc = g_sc[(size_t)bt * 128 + i];
    float s = sc.x, c = sc.y;
    const float* p = qkv + (size_t)bt * QSTR + colbase + head * HDIM;
    float first = p[i], second = p[i + 128];
    float o1 = (first * c - second * s) * scale;
    float o2 = (second * c + first * s) * scale;
    size_t ob = (size_t)bt * ostride + head * HDIM;
    if (single) {
        oh[ob + i]       = h_rn(o1);
        oh[ob + i + 128] = h_rn(o2);
    } else {
        unsigned short h, l;
        split1h(o1, h, l); oh[ob + i] = h;       ol[ob + i] = l;
        split1h(o2, h, l); oh[ob + i + 128] = h; ol[ob + i + 128] = l;
    }
}

/* V region of qkv -> g_vh (single fp16) */
__global__ void vsplit(const float4* __restrict__ qkv4, ushort4* __restrict__ vh) {
    int idx = blockIdx.x * 256 + threadIdx.x;     /* MTOT*512 */
    int bt = idx >> 9, c = idx & 511;
    float4 v = qkv4[(size_t)bt * 2048 + 1536 + c];
    ushort4 uh;
    uh.x = h_rn(v.x); uh.y = h_rn(v.y); uh.z = h_rn(v.z); uh.w = h_rn(v.w);
    vh[(size_t)bt * 512 + c] = uh;
}

/* ---------------- fp16 2-product GEMM, 256x128 tile ----------------
   C = A x B^T; A split h+l (exact), B single fp16.
   8 warps 4(m)x2(n), each 64x64; K-chunk 64; 2-stage cp.async. */
#define GK 64
#define G_AH 0u
#define G_AL 32768u
#define G_BH 65536u
#define GSTAGE 81920u
#define GSMEM  163840

__device__ __forceinline__ void gemm_load(
    uint32_t sbase, int st, int k0, int row0, int col0,
    const __half* Ah, const __half* Al, int lda,
    const __half* Bh, int ldb, int tid)
{
    uint32_t sb = sbase + (uint32_t)st * GSTAGE;
#pragma unroll
    for (int t = 0; t < 16; t++) {             /* A: 256 rows x 128B, h+l */
        int idx = t * 256 + tid;
        int split = idx >> 11, rem = idx & 2047;
        int r = rem >> 3, c8 = rem & 7;
        uint32_t so = swz((uint32_t)(r * 128 + c8 * 16));
        size_t g = (size_t)(row0 + r) * lda + k0 + c8 * 8;
        cp16(sb + (split ? G_AL : G_AH) + so, (split ? Al : Ah) + g);
    }
#pragma unroll
    for (int t = 0; t < 4; t++) {              /* B: 128 rows x 128B, single */
        int idx = t * 256 + tid;
        int r = idx >> 3, c8 = idx & 7;
        uint32_t so = swz((uint32_t)(r * 128 + c8 * 16));
        size_t g = (size_t)(col0 + r) * ldb + k0 + c8 * 8;
        cp16(sb + G_BH + so, Bh + g);
    }
}

__global__ void __launch_bounds__(256, 1) gemm_mma(
    const __half* __restrict__ Ah, const __half* __restrict__ Al, int lda,
    const __half* __restrict__ Bh, int ldb,
    float* __restrict__ C, int ldc, int Kd)
{
    extern __shared__ __align__(1024) char smem[];
    const uint32_t sbase = smem_u32(smem);
    const int tid = threadIdx.x;
    const int wid = tid >> 5, lid = tid & 31;
    const int wm = wid & 3, wn = wid >> 2;
    const int row0 = blockIdx.y * 256;
    const int col0 = blockIdx.x * 128;

    float acc[4][8][4];
#pragma unroll
    for (int i = 0; i < 4; i++)
#pragma unroll
        for (int j = 0; j < 8; j++)
#pragma unroll
            for (int kq = 0; kq < 4; kq++) acc[i][j][kq] = 0.0f;

    const int nch = Kd / GK;

    gemm_load(sbase, 0, 0, row0, col0, Ah, Al, lda, Bh, ldb, tid);
    cp_commit();

    const int rAl = lid & 15;
    const int cA  = lid >> 4;
    const int rBl = (lid & 7) + ((lid >> 4) & 1) * 8;
    const int cB  = (lid >> 3) & 1;

    for (int c = 0; c < nch; c++) {
        const int st = c & 1;
        if (c + 1 < nch) {
            gemm_load(sbase, st ^ 1, (c + 1) * GK, row0, col0, Ah, Al, lda, Bh, ldb, tid);
            cp_commit();
            cp_wait<1>();
        } else {
            cp_wait<0>();
        }
        __syncthreads();

        uint32_t sb = sbase + (uint32_t)st * GSTAGE;
#pragma unroll
        for (int ks = 0; ks < 4; ks++) {
            const int kc8 = ks * 2;
            uint32_t ah[4][4], al[4][4];
#pragma unroll
            for (int m4 = 0; m4 < 4; m4++) {
                uint32_t off = swz((uint32_t)((wm * 64 + m4 * 16 + rAl) * 128 + (kc8 + cA) * 16));
                ldm4(ah[m4], sb + G_AH + off);
                ldm4(al[m4], sb + G_AL + off);
            }
#pragma unroll
            for (int n16 = 0; n16 < 4; n16++) {
                uint32_t bh[4];
                uint32_t off = swz((uint32_t)((wn * 64 + n16 * 16 + rBl) * 128 + (kc8 + cB) * 16));
                ldm4(bh, sb + G_BH + off);
#pragma unroll
                for (int m4 = 0; m4 < 4; m4++)
#pragma unroll
                    for (int h = 0; h < 2; h++) {
                        float* d = acc[m4][n16 * 2 + h];
                        mma16816(d, ah[m4], bh[h * 2], bh[h * 2 + 1]);
                        mma16816(d, al[m4], bh[h * 2], bh[h * 2 + 1]);
                    }
            }
        }
        __syncthreads();
    }

#pragma unroll
    for (int m4 = 0; m4 < 4; m4++)
#pragma unroll
        for (int nt = 0; nt < 8; nt++) {
            int r = row0 + wm * 64 + m4 * 16 + (lid >> 2);
            int cc = col0 + wn * 64 + nt * 8 + (lid & 3) * 2;
            float* p0 = C + (size_t)r * ldc + cc;
            p0[0] = acc[m4][nt][0];
            p0[1] = acc[m4][nt][1];
            float* p1 = C + (size_t)(r + 8) * ldc + cc;
            p1[0] = acc[m4][nt][2];
            p1[1] = acc[m4][nt][3];
        }
}

/* ---------------- tensor-core flash attention (fp16, 2-product) ------------- */
#define AQ 32
#define ABK 32
#define ASPAD 36

#define QHOFF   0u
#define QLOFF   32768u
#define KHOFF   65536u        /* 2 stages x 16KB */
#define VHOFF   98304u        /* 2 stages x 16KB */
#define SSOFF   131072u       /* 64*36*4 = 9216 */
#define PHOFF   140288u       /* 8KB */
#define PLOFF   148480u       /* 8KB */
#define POSQOFF 156672u
#define POSKOFF 156800u
#define MOFF    157056u
#define LOFF    157312u
#define CORROFF 157568u
#define ASMEM   157824

__device__ __forceinline__ void attn_load_stage(
    uint32_t sbase, int st, int s0, int b, int khead,
    const __half* kh, const __half* vh, const int* segpos, int tid)
{
    size_t gbase = ((size_t)(b * TT + s0)) * 2048 + khead * HDIM;
#pragma unroll
    for (int t = 0; t < 8; t++) {
        int idx = t * 256 + tid;                /* 0..2047: K then V, 1024 each */
        int isv = idx >> 10, rem = idx & 1023;
        int p = rem >> 8, r = (rem >> 3) & 31, ch = rem & 7;
        size_t g = gbase + (size_t)r * 2048 + p * 64 + ch * 8;
        uint32_t so = swz((uint32_t)(r * 128 + ch * 16));
        cp16(sbase + (isv ? VHOFF : KHOFF) + st * 16384 + p * 4096 + so,
             (isv ? vh : kh) + g);
    }
    if (tid < ABK)
        cp4(sbase + POSKOFF + st * 128 + tid * 4, segpos + b * TT + s0 + tid);
}

__global__ void __launch_bounds__(256) attn_mma(
    const __half* __restrict__ qh, const __half* __restrict__ ql,
    const __half* __restrict__ kh, const __half* __restrict__ vh,
    const int* __restrict__ segpos,
    __half* __restrict__ ench, __half* __restrict__ encl)
{
    extern __shared__ __align__(1024) char smemc[];
    const uint32_t sbase = smem_u32(smemc);
    const int tid = threadIdx.x;
    const int wid = tid >> 5, lid = tid & 31;
    const int tile = (int)(gridDim.x - 1) - (int)blockIdx.x;
    const int khead = blockIdx.y;
    const int b = blockIdx.z;
    const int tq0 = tile * AQ;

    float* s_s    = (float*)(smemc + SSOFF);
    int*   posq   = (int*)(smemc + POSQOFF);
    int*   posk   = (int*)(smemc + POSKOFF);
    float* m_sm   = (float*)(smemc + MOFF);
    float* l_sm   = (float*)(smemc + LOFF);
    float* corr_s = (float*)(smemc + CORROFF);

    int s_begin = tq0 - (WIN - 1);
    if (s_begin < 0) s_begin = 0;
    s_begin &= ~(ABK - 1);
    const int nit = (tq0 + AQ - s_begin) / ABK;

    {
#pragma unroll
        for (int t = 0; t < 16; t++) {
            int idx = t * 256 + tid;
            int split = idx >> 11, rem = idx & 2047;
            int p = rem >> 9, r = (rem >> 3) & 63, ch = rem & 7;
            int tq = tq0 + (r & 31);
            int n = khead * 2 + (r >> 5);
            size_t g = ((size_t)(b * TT + tq)) * 4096 + n * HDIM + p * 64 + ch * 8;
            uint32_t so = swz((uint32_t)(r * 128 + ch * 16));
            cp16(sbase + (split ? QLOFF : QHOFF) + p * 8192 + so, (split ? ql : qh) + g);
        }
        if (tid < AQ) cp4(sbase + POSQOFF + tid * 4, segpos + b * TT + tq0 + tid);
        attn_load_stage(sbase, 0, s_begin, b, khead, kh, vh, segpos, tid);
        cp_commit();
    }
    if (tid < 64) { m_sm[tid] = -1e30f; l_sm[tid] = 0.0f; }

    float acc_o[2][8][4];
#pragma unroll
    for (int mt = 0; mt < 2; mt++)
#pragma unroll
        for (int nt = 0; nt < 8; nt++)
#pragma unroll
            for (int q = 0; q < 4; q++) acc_o[mt][nt][q] = 0.0f;

    const int wm = wid & 3, wn = wid >> 2;
    const int rA = wm * 16 + (lid & 15);
    const int cA = lid >> 4;
    const int rB = wn * 16 + (lid & 7) + ((lid >> 4) & 1) * 8;
    const int cB = (lid >> 3) & 1;
    const int wm2 = wid & 1, wn2 = wid >> 1;

    for (int it = 0; it < nit; it++) {
        const int st = it & 1;
        const int s0 = s_begin + it * ABK;
        cp_wait<0>();
        __syncthreads();

        if (it + 1 < nit) {
            attn_load_stage(sbase, st ^ 1, s0 + ABK, b, khead, kh, vh, segpos, tid);
            cp_commit();
        }

        /* ---- QK: Qh*K + Ql*K ---- */
        {
            float acc_s[2][4] = {{0,0,0,0},{0,0,0,0}};
            uint32_t khb = sbase + KHOFF + st * 16384;
#pragma unroll
            for (int ks = 0; ks < 16; ks++) {
                int p = ks >> 2, c2 = (ks & 3) * 2;
                uint32_t ah[4], al[4], bh[4];
                uint32_t ao = swz((uint32_t)(rA * 128 + (c2 + cA) * 16));
                ldm4(ah, sbase + QHOFF + p * 8192 + ao);
                ldm4(al, sbase + QLOFF + p * 8192 + ao);
                uint32_t bo = swz((uint32_t)(rB * 128 + (c2 + cB) * 16));
                ldm4(bh, khb + p * 4096 + bo);
                mma16816(acc_s[0], ah, bh[0], bh[1]);
                mma16816(acc_s[0], al, bh[0], bh[1]);
                mma16816(acc_s[1], ah, bh[2], bh[3]);
                mma16816(acc_s[1], al, bh[2], bh[3]);
            }
            int sr = wm * 16 + (lid >> 2);
            int sc = wn * 16 + (lid & 3) * 2;
#pragma unroll
            for (int nt = 0; nt < 2; nt++) {
                s_s[sr * ASPAD + sc + nt * 8]       = acc_s[nt][0];
                s_s[sr * ASPAD + sc + nt * 8 + 1]   = acc_s[nt][1];
                s_s[(sr + 8) * ASPAD + sc + nt * 8]     = acc_s[nt][2];
                s_s[(sr + 8) * ASPAD + sc + nt * 8 + 1] = acc_s[nt][3];
            }
        }
        __syncthreads();

        /* ---- softmax ---- */
        {
            int row = tid >> 2, qq = tid & 3;
            int ti = tq0 + (row & 31);
            int pq = posq[row & 31];
            const int* pks = posk + st * 32;
            float sc[8];
            float bmax = -1e30f;
#pragma unroll
            for (int j = 0; j < 8; j++) {
                int col = qq * 8 + j;
                float raw = s_s[row * ASPAD + col];
                float cap = tanh_acc(raw * 0.02f) * 50.0f;
                int si = s0 + col;
                int pk = pks[col];
                bool valid = (si <= ti) && (pk > pq - WIN) && (pk < pq + WIN);
                sc[j] = valid ? cap : -1e30f;
                bmax = fmaxf(bmax, sc[j]);
            }
            bmax = fmaxf(bmax, __shfl_xor_sync(0xffffffffu, bmax, 1));
            bmax = fmaxf(bmax, __shfl_xor_sync(0xffffffffu, bmax, 2));
            float m_old = m_sm[row];
            float m_new = fmaxf(m_old, bmax);
            float corr = __expf(m_old - m_new);
            float psum = 0.0f;
#pragma unroll
            for (int jp = 0; jp < 4; jp++) {
                float p0 = (sc[jp*2]   < -1e29f) ? 0.0f : __expf(sc[jp*2]   - m_new);
                float p1 = (sc[jp*2+1] < -1e29f) ? 0.0f : __expf(sc[jp*2+1] - m_new);
                psum += p0 + p1;
                unsigned short h0, l0, h1, l1;
                split1h(p0, h0, l0);
                split1h(p1, h1, l1);
                uint32_t byteoff = (uint32_t)(row * 128 + (qq * 8 + jp * 2) * 2);
                uint32_t sw = byteoff ^ ((byteoff >> 3) & 0x70);
                *(uint32_t*)(smemc + PHOFF + sw) = (uint32_t)h0 | ((uint32_t)h1 << 16);
                *(uint32_t*)(smemc + PLOFF + sw) = (uint32_t)l0 | ((uint32_t)l1 << 16);
            }
            psum += __shfl_xor_sync(0xffffffffu, psum, 1);
            psum += __shfl_xor_sync(0xffffffffu, psum, 2);
            if ((tid & 3) == 0) {
                l_sm[row] = l_sm[row] * corr + psum;
                m_sm[row] = m_new;
                corr_s[row] = corr;
            }
        }
        __syncthreads();

        /* ---- rescale + PV: (Ph + Pl) * V ---- */
        {
#pragma unroll
            for (int mt = 0; mt < 2; mt++) {
                int r0 = wm2 * 32 + mt * 16 + (lid >> 2);
                float c0 = corr_s[r0], c1 = corr_s[r0 + 8];
#pragma unroll
                for (int nt = 0; nt < 8; nt++) {
                    acc_o[mt][nt][0] *= c0; acc_o[mt][nt][1] *= c0;
                    acc_o[mt][nt][2] *= c1; acc_o[mt][nt][3] *= c1;
                }
            }
            uint32_t vhb = sbase + VHOFF + st * 16384 + wn2 * 4096;
#pragma unroll
            for (int ks2 = 0; ks2 < 2; ks2++) {
                uint32_t pa_h[2][4], pa_l[2][4];
#pragma unroll
                for (int mt = 0; mt < 2; mt++) {
                    int rA2 = wm2 * 32 + mt * 16 + (lid & 15);
                    uint32_t bo = swz((uint32_t)(rA2 * 128 + (ks2 * 2 + (lid >> 4)) * 16));
                    ldm4(pa_h[mt], sbase + PHOFF + bo);
                    ldm4(pa_l[mt], sbase + PLOFF + bo);
                }
#pragma unroll
                for (int nn = 0; nn < 4; nn++) {
                    int tl = lid >> 3;
                    int srow = (tl & 1) * 8 + (lid & 7) + ks2 * 16;
                    uint32_t bo = swz((uint32_t)(srow * 128 + (nn * 16 + (tl >> 1) * 8) * 2));
                    uint32_t bvh[4];
                    ldm4t(bvh, vhb + bo);
#pragma unroll
                    for (int mt = 0; mt < 2; mt++)
#pragma unroll
                        for (int h = 0; h < 2; h++) {
                            float* d = acc_o[mt][nn * 2 + h];
                            mma16816(d, pa_h[mt], bvh[h * 2], bvh[h * 2 + 1]);
                            mma16816(d, pa_l[mt], bvh[h * 2], bvh[h * 2 + 1]);
                        }
                }
            }
        }
    }
    __syncthreads();

    /* ---- epilogue: normalize, split h+l (enc is A-side of GEMM2) ---- */
#pragma unroll
    for (int mt = 0; mt < 2; mt++) {
        int rb = wm2 * 32 + mt * 16 + (lid >> 2);
#pragma unroll
        for (int sub = 0; sub < 2; sub++) {
            int r = rb + sub * 8;
            float inv = 1.0f / l_sm[r];
            int tq = tq0 + (r & 31);
            int n = khead * 2 + (r >> 5);
            size_t base = ((size_t)(b * TT + tq)) * 4096 + n * HDIM
                        + wn2 * 64 + (lid & 3) * 2;
#pragma unroll
            for (int nt = 0; nt < 8; nt++) {
                float o0 = acc_o[mt][nt][sub * 2 + 0] * inv;
                float o1 = acc_o[mt][nt][sub * 2 + 1] * inv;
                unsigned short h0, l0, h1, l1;
                split1h(o0, h0, l0);
                split1h(o1, h1, l1);
                *(uint32_t*)(ench + base + nt * 8) = (uint32_t)h0 | ((uint32_t)h1 << 16);
                *(uint32_t*)(encl + base + nt * 8) = (uint32_t)l0 | ((uint32_t)l1 << 16);
            }
        }
    }
}

/* ---------------- host launcher ---------------- */
extern "C" void kernel_launch(void* const* d_in, const int* in_sizes, int n_in,
                              void* d_out, int out_size)
{
    const float* x      = (const float*)d_in[0];
    const int*   segpos = (const int*)d_in[1];
    const float* q_w    = (const float*)d_in[3];
    const float* kv_w   = (const float*)d_in[4];
    const float* out_w  = (const float*)d_in[5];
    float* out = (float*)d_out;

    void *wt, *owt, *xh, *xl, *ench, *encl, *qkv;
    void *qhb, *qlb, *khb, *vhb;
    cudaGetSymbolAddress(&wt,   g_wt);
    cudaGetSymbolAddress(&owt,  g_owt);
    cudaGetSymbolAddress(&xh,   g_xh);
    cudaGetSymbolAddress(&xl,   g_xl);
    cudaGetSymbolAddress(&ench, g_ench);
    cudaGetSymbolAddress(&encl, g_encl);
    cudaGetSymbolAddress(&qkv,  g_qkv);
    cudaGetSymbolAddress(&qhb,  g_qh);
    cudaGetSymbolAddress(&qlb,  g_ql);
    cudaGetSymbolAddress(&khb,  g_kh);
    cudaGetSymbolAddress(&vhb,  g_vh);

    float* qkvf = (float*)qkv;

    cudaFuncSetAttribute(gemm_mma, cudaFuncAttributeMaxDynamicSharedMemorySize, GSMEM);
    cudaFuncSetAttribute(attn_mma, cudaFuncAttributeMaxDynamicSharedMemorySize, ASMEM);

    /* prep */
    ts_kernel<<<1, 128>>>();
    sc_kernel<<<MTOT * 128 / 256, 256>>>(segpos);
    trans_qkv_w<<<dim3(8192 / 32, DD / 32), 256>>>(q_w, kv_w);
    trans_ow<<<dim3(DD / 32, 4096 / 32), 256>>>(out_w);
    {
        int n4 = MTOT * DD / 4;
        convert_split<<<(n4 + 255) / 256, 256>>>((const float4*)x, (ushort4*)xh, (ushort4*)xl, n4);
    }

    /* GEMM1: qkv = x @ [q_w | k_w | v_w]  (M=4096, N=8192, K=3584) */
    gemm_mma<<<dim3(8192 / 128, MTOT / 256), 256, GSMEM>>>(
        (const __half*)xh, (const __half*)xl, DD,
        (const __half*)wt, DD,
        qkvf, QSTR, DD);

    /* RoPE: Q h+l (scale folded), K single */
    {
        int totq = MTOT * NHE * 128;
        rope_split<<<totq / 256, 256>>>(qkvf, NHE, 0, SCALE_F,
                                        (unsigned short*)qhb, (unsigned short*)qlb,
                                        4096, 0, totq);
        int totk = MTOT * KHE * 128;
        rope_split<<<totk / 256, 256>>>(qkvf, KHE, 4096, 1.0f,
                                        (unsigned short*)khb, (unsigned short*)0,
                                        2048, 1, totk);
    }
    /* V single fp16 */
    vsplit<<<MTOT * 512 / 256, 256>>>((const float4*)qkvf, (ushort4*)vhb);

    /* attention -> ench/encl */
    attn_mma<<<dim3(TT / AQ, KHE, BB), 256, ASMEM>>>(
        (const __half*)qhb, (const __half*)qlb,
        (const __half*)khb, (const __half*)vhb,
        segpos,
        (__half*)ench, (__half*)encl);

    /* GEMM2: out = enc @ out_w  (M=4096, N=3584, K=4096) */
    gemm_mma<<<dim3(DD / 128, MTOT / 256), 256, GSMEM>>>(
        (const __half*)ench, (const __half*)encl, 4096,
        (const __half*)owt, 4096,
        out, DD, 4096);
}

// round 10
// speedup vs baseline: 6.2454x; 1.0555x over previous
#include <cuda_runtime.h>
#include <cuda_fp16.h>
#include <math.h>
#include <stdint.h>

#define BB 2
#define TT 2048
#define DD 3584
#define NHE 16
#define KHE 8
#define HDIM 256
#define WIN 1024
#define SCALE_F 0.0625f
#define MTOT (BB*TT)         /* 4096 */
#define QSTR 8192            /* row stride of fused qkv fp32 buffer */

/* ---------------- device globals (no allocations allowed) ---------------- */
__device__ __align__(128) __half g_wt[(size_t)8192 * DD];      /* single fp16 */
__device__ __align__(128) __half g_owt[(size_t)DD * 4096];     /* single fp16 */
__device__ __align__(128) __half g_xh[(size_t)MTOT * DD];
__device__ __align__(128) __half g_xl[(size_t)MTOT * DD];
__device__ __align__(128) __half g_ench[(size_t)MTOT * 4096];
__device__ __align__(128) __half g_encl[(size_t)MTOT * 4096];
__device__ __align__(128) __half g_qh[(size_t)MTOT * 4096];    /* single */
__device__ __align__(128) __half g_kh[(size_t)MTOT * 2048];    /* single */
__device__ __align__(128) __half g_vh[(size_t)MTOT * 2048];    /* single */
__device__ __align__(128) float g_qkv[(size_t)MTOT * QSTR];
__device__ __align__(128) float2 g_sc[(size_t)MTOT * 128];
__device__ float g_ts[128];

/* ---------------- small helpers ---------------- */
__device__ __forceinline__ float rcp_fast(float x) {
    float r;
    asm("rcp.approx.f32 %0, %1;" : "=f"(r) : "f"(x));
    return r;
}
__device__ __forceinline__ float tanh_acc(float x) {
    float ax = fabsf(x);
    float e  = __expf(2.0f * ax);
    float r  = 1.0f - 2.0f * rcp_fast(e + 1.0f);   /* e=inf -> rcp=0 -> r=1 */
    return x < 0.0f ? -r : r;
}

__device__ __forceinline__ void split1h(float f, unsigned short& h, unsigned short& l) {
    __half hb = __float2half_rn(f);
    float res = f - __half2float(hb);               /* exact */
    __half lb = __float2half_rn(res);
    h = __half_as_ushort(hb);
    l = __half_as_ushort(lb);
}
__device__ __forceinline__ unsigned short h_rn(float f) {
    return __half_as_ushort(__float2half_rn(f));
}

__device__ __forceinline__ uint32_t smem_u32(const void* p) {
    uint32_t a;
    asm("{ .reg .u64 t; cvta.to.shared.u64 t, %1; cvt.u32.u64 %0, t; }" : "=r"(a) : "l"(p));
    return a;
}
__device__ __forceinline__ uint32_t swz(uint32_t off) {       /* SW128 */
    return off ^ ((off >> 3) & 0x70);
}
__device__ __forceinline__ void cp16(uint32_t saddr, const void* gaddr) {
    asm volatile("cp.async.cg.shared.global [%0], [%1], 16;" :: "r"(saddr), "l"(gaddr));
}
__device__ __forceinline__ void cp4(uint32_t saddr, const void* gaddr) {
    asm volatile("cp.async.ca.shared.global [%0], [%1], 4;" :: "r"(saddr), "l"(gaddr));
}
__device__ __forceinline__ void cp_commit() {
    asm volatile("cp.async.commit_group;" ::: "memory");
}
template <int N>
__device__ __forceinline__ void cp_wait() {
    asm volatile("cp.async.wait_group %0;" :: "n"(N) : "memory");
}
__device__ __forceinline__ void ldm4(uint32_t* r, uint32_t addr) {
    asm volatile("ldmatrix.sync.aligned.m8n8.x4.shared.b16 {%0,%1,%2,%3}, [%4];"
                 : "=r"(r[0]), "=r"(r[1]), "=r"(r[2]), "=r"(r[3]) : "r"(addr));
}
__device__ __forceinline__ void ldm4t(uint32_t* r, uint32_t addr) {
    asm volatile("ldmatrix.sync.aligned.m8n8.x4.trans.shared.b16 {%0,%1,%2,%3}, [%4];"
                 : "=r"(r[0]), "=r"(r[1]), "=r"(r[2]), "=r"(r[3]) : "r"(addr));
}
__device__ __forceinline__ void mma16816(float* d, const uint32_t* a,
                                         uint32_t b0, uint32_t b1) {
    asm volatile("mma.sync.aligned.m16n8k16.row.col.f32.f16.f16.f32 "
                 "{%0,%1,%2,%3}, {%4,%5,%6,%7}, {%8,%9}, {%0,%1,%2,%3};"
                 : "+f"(d[0]), "+f"(d[1]), "+f"(d[2]), "+f"(d[3])
                 : "r"(a[0]), "r"(a[1]), "r"(a[2]), "r"(a[3]), "r"(b0), "r"(b1));
}

/* ---------------- prep kernels ---------------- */
__global__ void ts_kernel() {
    int i = threadIdx.x;
    if (i < 128)
        g_ts[i] = (float)pow(10000.0, (double)i / 128.0);
}

__global__ void sc_kernel(const int* __restrict__ segpos) {
    int idx = blockIdx.x * 256 + threadIdx.x;          /* MTOT*128 */
    int bt = idx >> 7, i = idx & 127;
    int pos = segpos[bt];
    float ts = g_ts[i];
    float angf = __fdiv_rn((float)pos, ts);
    double sd, cd;
    sincos((double)angf, &sd, &cd);
    g_sc[idx] = make_float2((float)sd, (float)cd);
}

__global__ void __launch_bounds__(256) trans_qkv_w(const float* __restrict__ qw,
                                                   const float* __restrict__ kvw) {
    __shared__ float t[32][33];
    int c0 = blockIdx.x * 32, d0 = blockIdx.y * 32;
    int tx = threadIdx.x & 31, ty = threadIdx.x >> 5;
    int head = c0 >> 8, hb = c0 & 255;
    const float* src = (head < NHE) ? (qw + (size_t)head * DD * HDIM)
                                    : (kvw + (size_t)(head - NHE) * DD * HDIM);
#pragma unroll
    for (int i = 0; i < 4; i++)
        t[ty + 8 * i][tx] = src[(size_t)(d0 + ty + 8 * i) * HDIM + hb + tx];
    __syncthreads();
#pragma unroll
    for (int i = 0; i < 4; i++) {
        size_t o = (size_t)(c0 + ty + 8 * i) * DD + d0 + tx;
        ((unsigned short*)g_wt)[o] = h_rn(t[tx][ty + 8 * i]);
    }
}

__global__ void __launch_bounds__(256) trans_ow(const float* __restrict__ ow) {
    __shared__ float t[32][33];
    int c0 = blockIdx.x * 32, r0 = blockIdx.y * 32;
    int tx = threadIdx.x & 31, ty = threadIdx.x >> 5;
#pragma unroll
    for (int i = 0; i < 4; i++)
        t[ty + 8 * i][tx] = ow[(size_t)(r0 + ty + 8 * i) * DD + c0 + tx];
    __syncthreads();
#pragma unroll
    for (int i = 0; i < 4; i++) {
        size_t o = (size_t)(c0 + ty + 8 * i) * 4096 + r0 + tx;
        ((unsigned short*)g_owt)[o] = h_rn(t[tx][ty + 8 * i]);
    }
}

__global__ void convert_split(const float4* __restrict__ src, ushort4* __restrict__ h,
                              ushort4* __restrict__ l, int n4) {
    int i = blockIdx.x * 256 + threadIdx.x;
    if (i >= n4) return;
    float4 v = src[i];
    ushort4 uh, ul;
    split1h(v.x, uh.x, ul.x);
    split1h(v.y, uh.y, ul.y);
    split1h(v.z, uh.z, ul.z);
    split1h(v.w, uh.w, ul.w);
    h[i] = uh;
    l[i] = ul;
}

/* rope (table-driven), single-fp16 writeout (Q: scale folded; K: scale=1) */
__global__ void rope_single(const float* __restrict__ qkv, int heads, int colbase,
                            float scale, unsigned short* __restrict__ oh,
                            int ostride, int total) {
    int idx = blockIdx.x * 256 + threadIdx.x;
    if (idx >= total) return;
    int i = idx & 127;
    int rest = idx >> 7;
    int head = rest % heads;
    int bt = rest / heads;
    float2 sc = g_sc[(size_t)bt * 128 + i];
    float s = sc.x, c = sc.y;
    const float* p = qkv + (size_t)bt * QSTR + colbase + head * HDIM;
    float first = p[i], second = p[i + 128];
    size_t ob = (size_t)bt * ostride + head * HDIM;
    oh[ob + i]       = h_rn((first * c - second * s) * scale);
    oh[ob + i + 128] = h_rn((second * c + first * s) * scale);
}

/* ---------------- fp16 2-product GEMM, 256x128 tile ----------------
   C = A x B^T; A split h+l (exact), B single fp16.
   V-region tiles (col0 >= 6144 when Vout set) write fp16 directly. */
#define GK 64
#define G_AH 0u
#define G_AL 32768u
#define G_BH 65536u
#define GSTAGE 81920u
#define GSMEM  163840

__device__ __forceinline__ void gemm_load(
    uint32_t sbase, int st, int k0, int row0, int col0,
    const __half* Ah, const __half* Al, int lda,
    const __half* Bh, int ldb, int tid)
{
    uint32_t sb = sbase + (uint32_t)st * GSTAGE;
#pragma unroll
    for (int t = 0; t < 16; t++) {             /* A: 256 rows x 128B, h+l */
        int idx = t * 256 + tid;
        int split = idx >> 11, rem = idx & 2047;
        int r = rem >> 3, c8 = rem & 7;
        uint32_t so = swz((uint32_t)(r * 128 + c8 * 16));
        size_t g = (size_t)(row0 + r) * lda + k0 + c8 * 8;
        cp16(sb + (split ? G_AL : G_AH) + so, (split ? Al : Ah) + g);
    }
#pragma unroll
    for (int t = 0; t < 4; t++) {              /* B: 128 rows x 128B, single */
        int idx = t * 256 + tid;
        int r = idx >> 3, c8 = idx & 7;
        uint32_t so = swz((uint32_t)(r * 128 + c8 * 16));
        size_t g = (size_t)(col0 + r) * ldb + k0 + c8 * 8;
        cp16(sb + G_BH + so, Bh + g);
    }
}

__global__ void __launch_bounds__(256, 1) gemm_mma(
    const __half* __restrict__ Ah, const __half* __restrict__ Al, int lda,
    const __half* __restrict__ Bh, int ldb,
    float* __restrict__ C, int ldc, int Kd,
    __half* __restrict__ Vout)
{
    extern __shared__ __align__(1024) char smem[];
    const uint32_t sbase = smem_u32(smem);
    const int tid = threadIdx.x;
    const int wid = tid >> 5, lid = tid & 31;
    const int wm = wid & 3, wn = wid >> 2;
    const int row0 = blockIdx.y * 256;
    const int col0 = blockIdx.x * 128;

    float acc[4][8][4];
#pragma unroll
    for (int i = 0; i < 4; i++)
#pragma unroll
        for (int j = 0; j < 8; j++)
#pragma unroll
            for (int kq = 0; kq < 4; kq++) acc[i][j][kq] = 0.0f;

    const int nch = Kd / GK;

    gemm_load(sbase, 0, 0, row0, col0, Ah, Al, lda, Bh, ldb, tid);
    cp_commit();

    const int rAl = lid & 15;
    const int cA  = lid >> 4;
    const int rBl = (lid & 7) + ((lid >> 4) & 1) * 8;
    const int cB  = (lid >> 3) & 1;

    for (int c = 0; c < nch; c++) {
        const int st = c & 1;
        if (c + 1 < nch) {
            gemm_load(sbase, st ^ 1, (c + 1) * GK, row0, col0, Ah, Al, lda, Bh, ldb, tid);
            cp_commit();
            cp_wait<1>();
        } else {
            cp_wait<0>();
        }
        __syncthreads();

        uint32_t sb = sbase + (uint32_t)st * GSTAGE;
#pragma unroll
        for (int ks = 0; ks < 4; ks++) {
            const int kc8 = ks * 2;
            uint32_t ah[4][4], al[4][4];
#pragma unroll
            for (int m4 = 0; m4 < 4; m4++) {
                uint32_t off = swz((uint32_t)((wm * 64 + m4 * 16 + rAl) * 128 + (kc8 + cA) * 16));
                ldm4(ah[m4], sb + G_AH + off);
                ldm4(al[m4], sb + G_AL + off);
            }
#pragma unroll
            for (int n16 = 0; n16 < 4; n16++) {
                uint32_t bh[4];
                uint32_t off = swz((uint32_t)((wn * 64 + n16 * 16 + rBl) * 128 + (kc8 + cB) * 16));
                ldm4(bh, sb + G_BH + off);
#pragma unroll
                for (int m4 = 0; m4 < 4; m4++)
#pragma unroll
                    for (int h = 0; h < 2; h++) {
                        float* d = acc[m4][n16 * 2 + h];
                        mma16816(d, ah[m4], bh[h * 2], bh[h * 2 + 1]);
                        mma16816(d, al[m4], bh[h * 2], bh[h * 2 + 1]);
                    }
            }
        }
        __syncthreads();
    }

    if (Vout != 0 && col0 >= 6144) {
        /* V tiles: fp16 direct to g_vh [bt][2048] */
#pragma unroll
        for (int m4 = 0; m4 < 4; m4++)
#pragma unroll
            for (int nt = 0; nt < 8; nt++) {
                int r = row0 + wm * 64 + m4 * 16 + (lid >> 2);
                int cc = (col0 - 6144) + wn * 64 + nt * 8 + (lid & 3) * 2;
                unsigned short a0 = h_rn(acc[m4][nt][0]);
                unsigned short a1 = h_rn(acc[m4][nt][1]);
                *(uint32_t*)((unsigned short*)Vout + (size_t)r * 2048 + cc)
                    = (uint32_t)a0 | ((uint32_t)a1 << 16);
                unsigned short b0 = h_rn(acc[m4][nt][2]);
                unsigned short b1 = h_rn(acc[m4][nt][3]);
                *(uint32_t*)((unsigned short*)Vout + (size_t)(r + 8) * 2048 + cc)
                    = (uint32_t)b0 | ((uint32_t)b1 << 16);
            }
    } else {
#pragma unroll
        for (int m4 = 0; m4 < 4; m4++)
#pragma unroll
            for (int nt = 0; nt < 8; nt++) {
                int r = row0 + wm * 64 + m4 * 16 + (lid >> 2);
                int cc = col0 + wn * 64 + nt * 8 + (lid & 3) * 2;
                float* p0 = C + (size_t)r * ldc + cc;
                p0[0] = acc[m4][nt][0];
                p0[1] = acc[m4][nt][1];
                float* p1 = C + (size_t)(r + 8) * ldc + cc;
                p1[0] = acc[m4][nt][2];
                p1[1] = acc[m4][nt][3];
            }
    }
}

/* ---------------- tensor-core flash attention (fp16, 1-product) -------------
   Q single, K single, P single, V single. 2 CTAs/SM target. */
#define AQ 32
#define ABK 32
#define ASPAD 33

#define QHOFF   0u            /* 32KB  (64 rows x 256 dim fp16, 4 panels) */
#define KHOFF   32768u        /* 2 stages x 16KB */
#define VHOFF   65536u        /* 2 stages x 16KB */
#define SSOFF   98304u        /* 64*33*4 = 8448 */
#define PHOFF   106752u       /* 8KB */
#define POSQOFF 114944u
#define POSKOFF 115072u
#define MOFF    115328u
#define LOFF    115584u
#define CORROFF 115840u
#define ASMEM   116096

__device__ __forceinline__ void attn_load_stage(
    uint32_t sbase, int st, int s0, int b, int khead,
    const __half* kh, const __half* vh, const int* segpos, int tid)
{
    size_t gbase = ((size_t)(b * TT + s0)) * 2048 + khead * HDIM;
#pragma unroll
    for (int t = 0; t < 8; t++) {
        int idx = t * 256 + tid;                /* 0..2047: K then V, 1024 each */
        int isv = idx >> 10, rem = idx & 1023;
        int p = rem >> 8, r = (rem >> 3) & 31, ch = rem & 7;
        size_t g = gbase + (size_t)r * 2048 + p * 64 + ch * 8;
        uint32_t so = swz((uint32_t)(r * 128 + ch * 16));
        cp16(sbase + (isv ? VHOFF : KHOFF) + st * 16384 + p * 4096 + so,
             (isv ? vh : kh) + g);
    }
    if (tid < ABK)
        cp4(sbase + POSKOFF + st * 128 + tid * 4, segpos + b * TT + s0 + tid);
}

__global__ void __launch_bounds__(256, 2) attn_mma(
    const __half* __restrict__ qh,
    const __half* __restrict__ kh, const __half* __restrict__ vh,
    const int* __restrict__ segpos,
    __half* __restrict__ ench, __half* __restrict__ encl)
{
    extern __shared__ __align__(1024) char smemc[];
    const uint32_t sbase = smem_u32(smemc);
    const int tid = threadIdx.x;
    const int wid = tid >> 5, lid = tid & 31;
    const int tile = (int)(gridDim.x - 1) - (int)blockIdx.x;
    const int khead = blockIdx.y;
    const int b = blockIdx.z;
    const int tq0 = tile * AQ;

    float* s_s    = (float*)(smemc + SSOFF);
    int*   posq   = (int*)(smemc + POSQOFF);
    int*   posk   = (int*)(smemc + POSKOFF);
    float* m_sm   = (float*)(smemc + MOFF);
    float* l_sm   = (float*)(smemc + LOFF);
    float* corr_s = (float*)(smemc + CORROFF);

    int s_begin = tq0 - (WIN - 1);
    if (s_begin < 0) s_begin = 0;
    s_begin &= ~(ABK - 1);
    const int nit = (tq0 + AQ - s_begin) / ABK;

    {
#pragma unroll
        for (int t = 0; t < 8; t++) {           /* Q single: 2048 vectors */
            int idx = t * 256 + tid;
            int p = idx >> 9, r = (idx >> 3) & 63, ch = idx & 7;
            int tq = tq0 + (r & 31);
            int n = khead * 2 + (r >> 5);
            size_t g = ((size_t)(b * TT + tq)) * 4096 + n * HDIM + p * 64 + ch * 8;
            uint32_t so = swz((uint32_t)(r * 128 + ch * 16));
            cp16(sbase + QHOFF + p * 8192 + so, qh + g);
        }
        if (tid < AQ) cp4(sbase + POSQOFF + tid * 4, segpos + b * TT + tq0 + tid);
        attn_load_stage(sbase, 0, s_begin, b, khead, kh, vh, segpos, tid);
        cp_commit();
    }
    if (tid < 64) { m_sm[tid] = -1e30f; l_sm[tid] = 0.0f; }

    float acc_o[2][8][4];
#pragma unroll
    for (int mt = 0; mt < 2; mt++)
#pragma unroll
        for (int nt = 0; nt < 8; nt++)
#pragma unroll
            for (int q = 0; q < 4; q++) acc_o[mt][nt][q] = 0.0f;

    const int wm = wid & 3, wn = wid >> 2;
    const int rA = wm * 16 + (lid & 15);
    const int cA = lid >> 4;
    const int rB = wn * 16 + (lid & 7) + ((lid >> 4) & 1) * 8;
    const int cB = (lid >> 3) & 1;
    const int wm2 = wid & 1, wn2 = wid >> 1;

    for (int it = 0; it < nit; it++) {
        const int st = it & 1;
        const int s0 = s_begin + it * ABK;
        cp_wait<0>();
        __syncthreads();

        if (it + 1 < nit) {
            attn_load_stage(sbase, st ^ 1, s0 + ABK, b, khead, kh, vh, segpos, tid);
            cp_commit();
        }

        /* ---- QK: Q*K, 1 product ---- */
        {
            float acc_s[2][4] = {{0,0,0,0},{0,0,0,0}};
            uint32_t khb = sbase + KHOFF + st * 16384;
#pragma unroll
            for (int ks = 0; ks < 16; ks++) {
                int p = ks >> 2, c2 = (ks & 3) * 2;
                uint32_t ah[4], bh[4];
                uint32_t ao = swz((uint32_t)(rA * 128 + (c2 + cA) * 16));
                ldm4(ah, sbase + QHOFF + p * 8192 + ao);
                uint32_t bo = swz((uint32_t)(rB * 128 + (c2 + cB) * 16));
                ldm4(bh, khb + p * 4096 + bo);
                mma16816(acc_s[0], ah, bh[0], bh[1]);
                mma16816(acc_s[1], ah, bh[2], bh[3]);
            }
            int sr = wm * 16 + (lid >> 2);
            int sc = wn * 16 + (lid & 3) * 2;
#pragma unroll
            for (int nt = 0; nt < 2; nt++) {
                s_s[sr * ASPAD + sc + nt * 8]       = acc_s[nt][0];
                s_s[sr * ASPAD + sc + nt * 8 + 1]   = acc_s[nt][1];
                s_s[(sr + 8) * ASPAD + sc + nt * 8]     = acc_s[nt][2];
                s_s[(sr + 8) * ASPAD + sc + nt * 8 + 1] = acc_s[nt][3];
            }
        }
        __syncthreads();

        /* ---- softmax ---- */
        {
            int row = tid >> 2, qq = tid & 3;
            int ti = tq0 + (row & 31);
            int pq = posq[row & 31];
            const int* pks = posk + st * 32;
            float sc[8];
            float bmax = -1e30f;
#pragma unroll
            for (int j = 0; j < 8; j++) {
                int col = qq * 8 + j;
                float raw = s_s[row * ASPAD + col];
                float cap = tanh_acc(raw * 0.02f) * 50.0f;
                int si = s0 + col;
                int pk = pks[col];
                bool valid = (si <= ti) && (pk > pq - WIN) && (pk < pq + WIN);
                sc[j] = valid ? cap : -1e30f;
                bmax = fmaxf(bmax, sc[j]);
            }
            bmax = fmaxf(bmax, __shfl_xor_sync(0xffffffffu, bmax, 1));
            bmax = fmaxf(bmax, __shfl_xor_sync(0xffffffffu, bmax, 2));
            float m_old = m_sm[row];
            float m_new = fmaxf(m_old, bmax);
            float corr = __expf(m_old - m_new);
            float psum = 0.0f;
#pragma unroll
            for (int jp = 0; jp < 4; jp++) {
                float p0 = (sc[jp*2]   < -1e29f) ? 0.0f : __expf(sc[jp*2]   - m_new);
                float p1 = (sc[jp*2+1] < -1e29f) ? 0.0f : __expf(sc[jp*2+1] - m_new);
                psum += p0 + p1;
                uint32_t byteoff = (uint32_t)(row * 128 + (qq * 8 + jp * 2) * 2);
                uint32_t sw = byteoff ^ ((byteoff >> 3) & 0x70);
                *(uint32_t*)(smemc + PHOFF + sw)
                    = (uint32_t)h_rn(p0) | ((uint32_t)h_rn(p1) << 16);
            }
            psum += __shfl_xor_sync(0xffffffffu, psum, 1);
            psum += __shfl_xor_sync(0xffffffffu, psum, 2);
            if ((tid & 3) == 0) {
                l_sm[row] = l_sm[row] * corr + psum;
                m_sm[row] = m_new;
                corr_s[row] = corr;
            }
        }
        __syncthreads();

        /* ---- rescale + PV: P*V, 1 product ---- */
        {
#pragma unroll
            for (int mt = 0; mt < 2; mt++) {
                int r0 = wm2 * 32 + mt * 16 + (lid >> 2);
                float c0 = corr_s[r0], c1 = corr_s[r0 + 8];
#pragma unroll
                for (int nt = 0; nt < 8; nt++) {
                    acc_o[mt][nt][0] *= c0; acc_o[mt][nt][1] *= c0;
                    acc_o[mt][nt][2] *= c1; acc_o[mt][nt][3] *= c1;
                }
            }
            uint32_t vhb = sbase + VHOFF + st * 16384 + wn2 * 4096;
#pragma unroll
            for (int ks2 = 0; ks2 < 2; ks2++) {
                uint32_t pa_h[2][4];
#pragma unroll
                for (int mt = 0; mt < 2; mt++) {
                    int rA2 = wm2 * 32 + mt * 16 + (lid & 15);
                    uint32_t bo = swz((uint32_t)(rA2 * 128 + (ks2 * 2 + (lid >> 4)) * 16));
                    ldm4(pa_h[mt], sbase + PHOFF + bo);
                }
#pragma unroll
                for (int nn = 0; nn < 4; nn++) {
                    int tl = lid >> 3;
                    int srow = (tl & 1) * 8 + (lid & 7) + ks2 * 16;
                    uint32_t bo = swz((uint32_t)(srow * 128 + (nn * 16 + (tl >> 1) * 8) * 2));
                    uint32_t bvh[4];
                    ldm4t(bvh, vhb + bo);
#pragma unroll
                    for (int mt = 0; mt < 2; mt++)
#pragma unroll
                        for (int h = 0; h < 2; h++) {
                            float* d = acc_o[mt][nn * 2 + h];
                            mma16816(d, pa_h[mt], bvh[h * 2], bvh[h * 2 + 1]);
                        }
                }
            }
        }
    }
    __syncthreads();

    /* ---- epilogue: normalize, split h+l (enc is A-side of GEMM2) ---- */
#pragma unroll
    for (int mt = 0; mt < 2; mt++) {
        int rb = wm2 * 32 + mt * 16 + (lid >> 2);
#pragma unroll
        for (int sub = 0; sub < 2; sub++) {
            int r = rb + sub * 8;
            float inv = 1.0f / l_sm[r];
            int tq = tq0 + (r & 31);
            int n = khead * 2 + (r >> 5);
            size_t base = ((size_t)(b * TT + tq)) * 4096 + n * HDIM
                        + wn2 * 64 + (lid & 3) * 2;
#pragma unroll
            for (int nt = 0; nt < 8; nt++) {
                float o0 = acc_o[mt][nt][sub * 2 + 0] * inv;
                float o1 = acc_o[mt][nt][sub * 2 + 1] * inv;
                unsigned short h0, l0, h1, l1;
                split1h(o0, h0, l0);
                split1h(o1, h1, l1);
                *(uint32_t*)(ench + base + nt * 8) = (uint32_t)h0 | ((uint32_t)h1 << 16);
                *(uint32_t*)(encl + base + nt * 8) = (uint32_t)l0 | ((uint32_t)l1 << 16);
            }
        }
    }
}

/* ---------------- host launcher ---------------- */
extern "C" void kernel_launch(void* const* d_in, const int* in_sizes, int n_in,
                              void* d_out, int out_size)
{
    const float* x      = (const float*)d_in[0];
    const int*   segpos = (const int*)d_in[1];
    const float* q_w    = (const float*)d_in[3];
    const float* kv_w   = (const float*)d_in[4];
    const float* out_w  = (const float*)d_in[5];
    float* out = (float*)d_out;

    void *wt, *owt, *xh, *xl, *ench, *encl, *qkv;
    void *qhb, *khb, *vhb;
    cudaGetSymbolAddress(&wt,   g_wt);
    cudaGetSymbolAddress(&owt,  g_owt);
    cudaGetSymbolAddress(&xh,   g_xh);
    cudaGetSymbolAddress(&xl,   g_xl);
    cudaGetSymbolAddress(&ench, g_ench);
    cudaGetSymbolAddress(&encl, g_encl);
    cudaGetSymbolAddress(&qkv,  g_qkv);
    cudaGetSymbolAddress(&qhb,  g_qh);
    cudaGetSymbolAddress(&khb,  g_kh);
    cudaGetSymbolAddress(&vhb,  g_vh);

    float* qkvf = (float*)qkv;

    cudaFuncSetAttribute(gemm_mma, cudaFuncAttributeMaxDynamicSharedMemorySize, GSMEM);
    cudaFuncSetAttribute(attn_mma, cudaFuncAttributeMaxDynamicSharedMemorySize, ASMEM);

    /* prep */
    ts_kernel<<<1, 128>>>();
    sc_kernel<<<MTOT * 128 / 256, 256>>>(segpos);
    trans_qkv_w<<<dim3(8192 / 32, DD / 32), 256>>>(q_w, kv_w);
    trans_ow<<<dim3(DD / 32, 4096 / 32), 256>>>(out_w);
    {
        int n4 = MTOT * DD / 4;
        convert_split<<<(n4 + 255) / 256, 256>>>((const float4*)x, (ushort4*)xh, (ushort4*)xl, n4);
    }

    /* GEMM1: qkv = x @ [q_w | k_w | v_w]; V tiles fused to fp16 */
    gemm_mma<<<dim3(8192 / 128, MTOT / 256), 256, GSMEM>>>(
        (const __half*)xh, (const __half*)xl, DD,
        (const __half*)wt, DD,
        qkvf, QSTR, DD, (__half*)vhb);

    /* RoPE: Q single (scale folded), K single */
    {
        int totq = MTOT * NHE * 128;
        rope_single<<<totq / 256, 256>>>(qkvf, NHE, 0, SCALE_F,
                                         (unsigned short*)qhb, 4096, totq);
        int totk = MTOT * KHE * 128;
        rope_single<<<totk / 256, 256>>>(qkvf, KHE, 4096, 1.0f,
                                         (unsigned short*)khb, 2048, totk);
    }

    /* attention -> ench/encl */
    attn_mma<<<dim3(TT / AQ, KHE, BB), 256, ASMEM>>>(
        (const __half*)qhb, (const __half*)khb, (const __half*)vhb,
        segpos,
        (__half*)ench, (__half*)encl);

    /* GEMM2: out = enc @ out_w  (M=4096, N=3584, K=4096) */
    gemm_mma<<<dim3(DD / 128, MTOT / 256), 256, GSMEM>>>(
        (const __half*)ench, (const __half*)encl, 4096,
        (const __half*)owt, 4096,
        out, DD, 4096, (__half*)0);
}

// round 11
// speedup vs baseline: 9.8440x; 1.5762x over previous
#include <cuda_runtime.h>
#include <cuda_fp16.h>
#include <math.h>
#include <stdint.h>

#define BB 2
#define TT 2048
#define DD 3584
#define NHE 16
#define KHE 8
#define HDIM 256
#define WIN 1024
#define SCALE_F 0.0625f
#define MTOT (BB*TT)         /* 4096 */
#define QSTR 8192            /* row stride of fused qkv fp32 buffer */

/* ---------------- device globals (no allocations allowed) ---------------- */
__device__ __align__(128) __half g_wt[(size_t)8192 * DD];      /* single fp16 */
__device__ __align__(128) __half g_owt[(size_t)DD * 4096];     /* single fp16 */
__device__ __align__(128) __half g_xh[(size_t)MTOT * DD];      /* single */
__device__ __align__(128) __half g_ench[(size_t)MTOT * 4096];  /* single */
__device__ __align__(128) __half g_qh[(size_t)MTOT * 4096];    /* single */
__device__ __align__(128) __half g_kh[(size_t)MTOT * 2048];    /* single */
__device__ __align__(128) __half g_vh[(size_t)MTOT * 2048];    /* single */
__device__ __align__(128) float g_qkv[(size_t)MTOT * QSTR];
__device__ __align__(128) float2 g_sc[(size_t)MTOT * 128];
__device__ float g_ts[128];

/* ---------------- small helpers ---------------- */
__device__ __forceinline__ float rcp_fast(float x) {
    float r;
    asm("rcp.approx.f32 %0, %1;" : "=f"(r) : "f"(x));
    return r;
}
__device__ __forceinline__ float tanh_acc(float x) {
    float ax = fabsf(x);
    float e  = __expf(2.0f * ax);
    float r  = 1.0f - 2.0f * rcp_fast(e + 1.0f);   /* e=inf -> rcp=0 -> r=1 */
    return x < 0.0f ? -r : r;
}
__device__ __forceinline__ unsigned short h_rn(float f) {
    return __half_as_ushort(__float2half_rn(f));
}

__device__ __forceinline__ uint32_t smem_u32(const void* p) {
    uint32_t a;
    asm("{ .reg .u64 t; cvta.to.shared.u64 t, %1; cvt.u32.u64 %0, t; }" : "=r"(a) : "l"(p));
    return a;
}
__device__ __forceinline__ uint32_t swz(uint32_t off) {       /* SW128 */
    return off ^ ((off >> 3) & 0x70);
}
__device__ __forceinline__ void cp16(uint32_t saddr, const void* gaddr) {
    asm volatile("cp.async.cg.shared.global [%0], [%1], 16;" :: "r"(saddr), "l"(gaddr));
}
__device__ __forceinline__ void cp4(uint32_t saddr, const void* gaddr) {
    asm volatile("cp.async.ca.shared.global [%0], [%1], 4;" :: "r"(saddr), "l"(gaddr));
}
__device__ __forceinline__ void cp_commit() {
    asm volatile("cp.async.commit_group;" ::: "memory");
}
template <int N>
__device__ __forceinline__ void cp_wait() {
    asm volatile("cp.async.wait_group %0;" :: "n"(N) : "memory");
}
__device__ __forceinline__ void ldm4(uint32_t* r, uint32_t addr) {
    asm volatile("ldmatrix.sync.aligned.m8n8.x4.shared.b16 {%0,%1,%2,%3}, [%4];"
                 : "=r"(r[0]), "=r"(r[1]), "=r"(r[2]), "=r"(r[3]) : "r"(addr));
}
__device__ __forceinline__ void ldm4t(uint32_t* r, uint32_t addr) {
    asm volatile("ldmatrix.sync.aligned.m8n8.x4.trans.shared.b16 {%0,%1,%2,%3}, [%4];"
                 : "=r"(r[0]), "=r"(r[1]), "=r"(r[2]), "=r"(r[3]) : "r"(addr));
}
__device__ __forceinline__ void mma16816(float* d, const uint32_t* a,
                                         uint32_t b0, uint32_t b1) {
    asm volatile("mma.sync.aligned.m16n8k16.row.col.f32.f16.f16.f32 "
                 "{%0,%1,%2,%3}, {%4,%5,%6,%7}, {%8,%9}, {%0,%1,%2,%3};"
                 : "+f"(d[0]), "+f"(d[1]), "+f"(d[2]), "+f"(d[3])
                 : "r"(a[0]), "r"(a[1]), "r"(a[2]), "r"(a[3]), "r"(b0), "r"(b1));
}

/* ---------------- prep kernels ---------------- */
__global__ void ts_kernel() {
    int i = threadIdx.x;
    if (i < 128)
        g_ts[i] = (float)pow(10000.0, (double)i / 128.0);
}

__global__ void sc_kernel(const int* __restrict__ segpos) {
    int idx = blockIdx.x * 256 + threadIdx.x;          /* MTOT*128 */
    int bt = idx >> 7, i = idx & 127;
    int pos = segpos[bt];
    float ts = g_ts[i];
    float angf = __fdiv_rn((float)pos, ts);
    double sd, cd;
    sincos((double)angf, &sd, &cd);
    g_sc[idx] = make_float2((float)sd, (float)cd);
}

__global__ void __launch_bounds__(256) trans_qkv_w(const float* __restrict__ qw,
                                                   const float* __restrict__ kvw) {
    __shared__ float t[32][33];
    int c0 = blockIdx.x * 32, d0 = blockIdx.y * 32;
    int tx = threadIdx.x & 31, ty = threadIdx.x >> 5;
    int head = c0 >> 8, hb = c0 & 255;
    const float* src = (head < NHE) ? (qw + (size_t)head * DD * HDIM)
                                    : (kvw + (size_t)(head - NHE) * DD * HDIM);
#pragma unroll
    for (int i = 0; i < 4; i++)
        t[ty + 8 * i][tx] = src[(size_t)(d0 + ty + 8 * i) * HDIM + hb + tx];
    __syncthreads();
#pragma unroll
    for (int i = 0; i < 4; i++) {
        size_t o = (size_t)(c0 + ty + 8 * i) * DD + d0 + tx;
        ((unsigned short*)g_wt)[o] = h_rn(t[tx][ty + 8 * i]);
    }
}

__global__ void __launch_bounds__(256) trans_ow(const float* __restrict__ ow) {
    __shared__ float t[32][33];
    int c0 = blockIdx.x * 32, r0 = blockIdx.y * 32;
    int tx = threadIdx.x & 31, ty = threadIdx.x >> 5;
#pragma unroll
    for (int i = 0; i < 4; i++)
        t[ty + 8 * i][tx] = ow[(size_t)(r0 + ty + 8 * i) * DD + c0 + tx];
    __syncthreads();
#pragma unroll
    for (int i = 0; i < 4; i++) {
        size_t o = (size_t)(c0 + ty + 8 * i) * 4096 + r0 + tx;
        ((unsigned short*)g_owt)[o] = h_rn(t[tx][ty + 8 * i]);
    }
}

__global__ void convert_single(const float4* __restrict__ src, ushort4* __restrict__ h,
                               int n4) {
    int i = blockIdx.x * 256 + threadIdx.x;
    if (i >= n4) return;
    float4 v = src[i];
    ushort4 uh;
    uh.x = h_rn(v.x); uh.y = h_rn(v.y); uh.z = h_rn(v.z); uh.w = h_rn(v.w);
    h[i] = uh;
}

/* rope (table-driven), single-fp16 writeout (Q: scale folded; K: scale=1) */
__global__ void rope_single(const float* __restrict__ qkv, int heads, int colbase,
                            float scale, unsigned short* __restrict__ oh,
                            int ostride, int total) {
    int idx = blockIdx.x * 256 + threadIdx.x;
    if (idx >= total) return;
    int i = idx & 127;
    int rest = idx >> 7;
    int head = rest % heads;
    int bt = rest / heads;
    float2 sc = g_sc[(size_t)bt * 128 + i];
    float s = sc.x, c = sc.y;
    const float* p = qkv + (size_t)bt * QSTR + colbase + head * HDIM;
    float first = p[i], second = p[i + 128];
    size_t ob = (size_t)bt * ostride + head * HDIM;
    oh[ob + i]       = h_rn((first * c - second * s) * scale);
    oh[ob + i + 128] = h_rn((second * c + first * s) * scale);
}

/* ---------------- fp16 1-product GEMM, 256x128 tile ----------------
   C = A x B^T; both sides single fp16, fp32 accum.
   V-region tiles (col0 >= 6144 when Vout set) write fp16 directly. */
#define GK 64
#define G_AH 0u
#define G_BH 32768u
#define GSTAGE 49152u
#define GSMEM  98304

__device__ __forceinline__ void gemm_load(
    uint32_t sbase, int st, int k0, int row0, int col0,
    const __half* Ah, int lda, const __half* Bh, int ldb, int tid)
{
    uint32_t sb = sbase + (uint32_t)st * GSTAGE;
#pragma unroll
    for (int t = 0; t < 8; t++) {              /* A: 256 rows x 128B */
        int idx = t * 256 + tid;
        int r = idx >> 3, c8 = idx & 7;
        uint32_t so = swz((uint32_t)(r * 128 + c8 * 16));
        size_t g = (size_t)(row0 + r) * lda + k0 + c8 * 8;
        cp16(sb + G_AH + so, Ah + g);
    }
#pragma unroll
    for (int t = 0; t < 4; t++) {              /* B: 128 rows x 128B */
        int idx = t * 256 + tid;
        int r = idx >> 3, c8 = idx & 7;
        uint32_t so = swz((uint32_t)(r * 128 + c8 * 16));
        size_t g = (size_t)(col0 + r) * ldb + k0 + c8 * 8;
        cp16(sb + G_BH + so, Bh + g);
    }
}

__global__ void __launch_bounds__(256, 1) gemm_mma(
    const __half* __restrict__ Ah, int lda,
    const __half* __restrict__ Bh, int ldb,
    float* __restrict__ C, int ldc, int Kd,
    __half* __restrict__ Vout)
{
    extern __shared__ __align__(1024) char smem[];
    const uint32_t sbase = smem_u32(smem);
    const int tid = threadIdx.x;
    const int wid = tid >> 5, lid = tid & 31;
    const int wm = wid & 3, wn = wid >> 2;
    const int row0 = blockIdx.y * 256;
    const int col0 = blockIdx.x * 128;

    float acc[4][8][4];
#pragma unroll
    for (int i = 0; i < 4; i++)
#pragma unroll
        for (int j = 0; j < 8; j++)
#pragma unroll
            for (int kq = 0; kq < 4; kq++) acc[i][j][kq] = 0.0f;

    const int nch = Kd / GK;

    gemm_load(sbase, 0, 0, row0, col0, Ah, lda, Bh, ldb, tid);
    cp_commit();

    const int rAl = lid & 15;
    const int cA  = lid >> 4;
    const int rBl = (lid & 7) + ((lid >> 4) & 1) * 8;
    const int cB  = (lid >> 3) & 1;

    for (int c = 0; c < nch; c++) {
        const int st = c & 1;
        if (c + 1 < nch) {
            gemm_load(sbase, st ^ 1, (c + 1) * GK, row0, col0, Ah, lda, Bh, ldb, tid);
            cp_commit();
            cp_wait<1>();
        } else {
            cp_wait<0>();
        }
        __syncthreads();

        uint32_t sb = sbase + (uint32_t)st * GSTAGE;
#pragma unroll
        for (int ks = 0; ks < 4; ks++) {
            const int kc8 = ks * 2;
            uint32_t ah[4][4];
#pragma unroll
            for (int m4 = 0; m4 < 4; m4++) {
                uint32_t off = swz((uint32_t)((wm * 64 + m4 * 16 + rAl) * 128 + (kc8 + cA) * 16));
                ldm4(ah[m4], sb + G_AH + off);
            }
#pragma unroll
            for (int n16 = 0; n16 < 4; n16++) {
                uint32_t bh[4];
                uint32_t off = swz((uint32_t)((wn * 64 + n16 * 16 + rBl) * 128 + (kc8 + cB) * 16));
                ldm4(bh, sb + G_BH + off);
#pragma unroll
                for (int m4 = 0; m4 < 4; m4++)
#pragma unroll
                    for (int h = 0; h < 2; h++)
                        mma16816(acc[m4][n16 * 2 + h], ah[m4], bh[h * 2], bh[h * 2 + 1]);
            }
        }
        __syncthreads();
    }

    if (Vout != 0 && col0 >= 6144) {
        /* V tiles: fp16 direct to g_vh [bt][2048] */
#pragma unroll
        for (int m4 = 0; m4 < 4; m4++)
#pragma unroll
            for (int nt = 0; nt < 8; nt++) {
                int r = row0 + wm * 64 + m4 * 16 + (lid >> 2);
                int cc = (col0 - 6144) + wn * 64 + nt * 8 + (lid & 3) * 2;
                unsigned short a0 = h_rn(acc[m4][nt][0]);
                unsigned short a1 = h_rn(acc[m4][nt][1]);
                *(uint32_t*)((unsigned short*)Vout + (size_t)r * 2048 + cc)
                    = (uint32_t)a0 | ((uint32_t)a1 << 16);
                unsigned short b0 = h_rn(acc[m4][nt][2]);
                unsigned short b1 = h_rn(acc[m4][nt][3]);
                *(uint32_t*)((unsigned short*)Vout + (size_t)(r + 8) * 2048 + cc)
                    = (uint32_t)b0 | ((uint32_t)b1 << 16);
            }
    } else {
#pragma unroll
        for (int m4 = 0; m4 < 4; m4++)
#pragma unroll
            for (int nt = 0; nt < 8; nt++) {
                int r = row0 + wm * 64 + m4 * 16 + (lid >> 2);
                int cc = col0 + wn * 64 + nt * 8 + (lid & 3) * 2;
                float* p0 = C + (size_t)r * ldc + cc;
                p0[0] = acc[m4][nt][0];
                p0[1] = acc[m4][nt][1];
                float* p1 = C + (size_t)(r + 8) * ldc + cc;
                p1[0] = acc[m4][nt][2];
                p1[1] = acc[m4][nt][3];
            }
    }
}

/* ---------------- tensor-core flash attention (fp16, 1-product) -------------
   Q single, K single, P single, V single. 2 CTAs/SM. */
#define AQ 32
#define ABK 32
#define ASPAD 33

#define QHOFF   0u            /* 32KB  (64 rows x 256 dim fp16, 4 panels) */
#define KHOFF   32768u        /* 2 stages x 16KB */
#define VHOFF   65536u        /* 2 stages x 16KB */
#define SSOFF   98304u        /* 64*33*4 = 8448 */
#define PHOFF   106752u       /* 8KB */
#define POSQOFF 114944u
#define POSKOFF 115072u
#define MOFF    115328u
#define LOFF    115584u
#define CORROFF 115840u
#define ASMEM   116096

__device__ __forceinline__ void attn_load_stage(
    uint32_t sbase, int st, int s0, int b, int khead,
    const __half* kh, const __half* vh, const int* segpos, int tid)
{
    size_t gbase = ((size_t)(b * TT + s0)) * 2048 + khead * HDIM;
#pragma unroll
    for (int t = 0; t < 8; t++) {
        int idx = t * 256 + tid;                /* 0..2047: K then V, 1024 each */
        int isv = idx >> 10, rem = idx & 1023;
        int p = rem >> 8, r = (rem >> 3) & 31, ch = rem & 7;
        size_t g = gbase + (size_t)r * 2048 + p * 64 + ch * 8;
        uint32_t so = swz((uint32_t)(r * 128 + ch * 16));
        cp16(sbase + (isv ? VHOFF : KHOFF) + st * 16384 + p * 4096 + so,
             (isv ? vh : kh) + g);
    }
    if (tid < ABK)
        cp4(sbase + POSKOFF + st * 128 + tid * 4, segpos + b * TT + s0 + tid);
}

__global__ void __launch_bounds__(256, 2) attn_mma(
    const __half* __restrict__ qh,
    const __half* __restrict__ kh, const __half* __restrict__ vh,
    const int* __restrict__ segpos,
    __half* __restrict__ ench)
{
    extern __shared__ __align__(1024) char smemc[];
    const uint32_t sbase = smem_u32(smemc);
    const int tid = threadIdx.x;
    const int wid = tid >> 5, lid = tid & 31;
    const int tile = (int)(gridDim.x - 1) - (int)blockIdx.x;
    const int khead = blockIdx.y;
    const int b = blockIdx.z;
    const int tq0 = tile * AQ;

    float* s_s    = (float*)(smemc + SSOFF);
    int*   posq   = (int*)(smemc + POSQOFF);
    int*   posk   = (int*)(smemc + POSKOFF);
    float* m_sm   = (float*)(smemc + MOFF);
    float* l_sm   = (float*)(smemc + LOFF);
    float* corr_s = (float*)(smemc + CORROFF);

    int s_begin = tq0 - (WIN - 1);
    if (s_begin < 0) s_begin = 0;
    s_begin &= ~(ABK - 1);
    const int nit = (tq0 + AQ - s_begin) / ABK;

    {
#pragma unroll
        for (int t = 0; t < 8; t++) {           /* Q single: 2048 vectors */
            int idx = t * 256 + tid;
            int p = idx >> 9, r = (idx >> 3) & 63, ch = idx & 7;
            int tq = tq0 + (r & 31);
            int n = khead * 2 + (r >> 5);
            size_t g = ((size_t)(b * TT + tq)) * 4096 + n * HDIM + p * 64 + ch * 8;
            uint32_t so = swz((uint32_t)(r * 128 + ch * 16));
            cp16(sbase + QHOFF + p * 8192 + so, qh + g);
        }
        if (tid < AQ) cp4(sbase + POSQOFF + tid * 4, segpos + b * TT + tq0 + tid);
        attn_load_stage(sbase, 0, s_begin, b, khead, kh, vh, segpos, tid);
        cp_commit();
    }
    if (tid < 64) { m_sm[tid] = -1e30f; l_sm[tid] = 0.0f; }

    float acc_o[2][8][4];
#pragma unroll
    for (int mt = 0; mt < 2; mt++)
#pragma unroll
        for (int nt = 0; nt < 8; nt++)
#pragma unroll
            for (int q = 0; q < 4; q++) acc_o[mt][nt][q] = 0.0f;

    const int wm = wid & 3, wn = wid >> 2;
    const int rA = wm * 16 + (lid & 15);
    const int cA = lid >> 4;
    const int rB = wn * 16 + (lid & 7) + ((lid >> 4) & 1) * 8;
    const int cB = (lid >> 3) & 1;
    const int wm2 = wid & 1, wn2 = wid >> 1;

    for (int it = 0; it < nit; it++) {
        const int st = it & 1;
        const int s0 = s_begin + it * ABK;
        cp_wait<0>();
        __syncthreads();

        if (it + 1 < nit) {
            attn_load_stage(sbase, st ^ 1, s0 + ABK, b, khead, kh, vh, segpos, tid);
            cp_commit();
        }

        /* ---- QK: Q*K, 1 product ---- */
        {
            float acc_s[2][4] = {{0,0,0,0},{0,0,0,0}};
            uint32_t khb = sbase + KHOFF + st * 16384;
#pragma unroll
            for (int ks = 0; ks < 16; ks++) {
                int p = ks >> 2, c2 = (ks & 3) * 2;
                uint32_t ah[4], bh[4];
                uint32_t ao = swz((uint32_t)(rA * 128 + (c2 + cA) * 16));
                ldm4(ah, sbase + QHOFF + p * 8192 + ao);
                uint32_t bo = swz((uint32_t)(rB * 128 + (c2 + cB) * 16));
                ldm4(bh, khb + p * 4096 + bo);
                mma16816(acc_s[0], ah, bh[0], bh[1]);
                mma16816(acc_s[1], ah, bh[2], bh[3]);
            }
            int sr = wm * 16 + (lid >> 2);
            int sc = wn * 16 + (lid & 3) * 2;
#pragma unroll
            for (int nt = 0; nt < 2; nt++) {
                s_s[sr * ASPAD + sc + nt * 8]       = acc_s[nt][0];
                s_s[sr * ASPAD + sc + nt * 8 + 1]   = acc_s[nt][1];
                s_s[(sr + 8) * ASPAD + sc + nt * 8]     = acc_s[nt][2];
                s_s[(sr + 8) * ASPAD + sc + nt * 8 + 1] = acc_s[nt][3];
            }
        }
        __syncthreads();

        /* ---- softmax ---- */
        {
            int row = tid >> 2, qq = tid & 3;
            int ti = tq0 + (row & 31);
            int pq = posq[row & 31];
            const int* pks = posk + st * 32;
            float sc[8];
            float bmax = -1e30f;
#pragma unroll
            for (int j = 0; j < 8; j++) {
                int col = qq * 8 + j;
                float raw = s_s[row * ASPAD + col];
                float cap = tanh_acc(raw * 0.02f) * 50.0f;
                int si = s0 + col;
                int pk = pks[col];
                bool valid = (si <= ti) && (pk > pq - WIN) && (pk < pq + WIN);
                sc[j] = valid ? cap : -1e30f;
                bmax = fmaxf(bmax, sc[j]);
            }
            bmax = fmaxf(bmax, __shfl_xor_sync(0xffffffffu, bmax, 1));
            bmax = fmaxf(bmax, __shfl_xor_sync(0xffffffffu, bmax, 2));
            float m_old = m_sm[row];
            float m_new = fmaxf(m_old, bmax);
            float corr = __expf(m_old - m_new);
            float psum = 0.0f;
#pragma unroll
            for (int jp = 0; jp < 4; jp++) {
                float p0 = (sc[jp*2]   < -1e29f) ? 0.0f : __expf(sc[jp*2]   - m_new);
                float p1 = (sc[jp*2+1] < -1e29f) ? 0.0f : __expf(sc[jp*2+1] - m_new);
                psum += p0 + p1;
                uint32_t byteoff = (uint32_t)(row * 128 + (qq * 8 + jp * 2) * 2);
                uint32_t sw = byteoff ^ ((byteoff >> 3) & 0x70);
                *(uint32_t*)(smemc + PHOFF + sw)
                    = (uint32_t)h_rn(p0) | ((uint32_t)h_rn(p1) << 16);
            }
            psum += __shfl_xor_sync(0xffffffffu, psum, 1);
            psum += __shfl_xor_sync(0xffffffffu, psum, 2);
            if ((tid & 3) == 0) {
                l_sm[row] = l_sm[row] * corr + psum;
                m_sm[row] = m_new;
                corr_s[row] = corr;
            }
        }
        __syncthreads();

        /* ---- rescale + PV: P*V, 1 product ---- */
        {
#pragma unroll
            for (int mt = 0; mt < 2; mt++) {
                int r0 = wm2 * 32 + mt * 16 + (lid >> 2);
                float c0 = corr_s[r0], c1 = corr_s[r0 + 8];
#pragma unroll
                for (int nt = 0; nt < 8; nt++) {
                    acc_o[mt][nt][0] *= c0; acc_o[mt][nt][1] *= c0;
                    acc_o[mt][nt][2] *= c1; acc_o[mt][nt][3] *= c1;
                }
            }
            uint32_t vhb = sbase + VHOFF + st * 16384 + wn2 * 4096;
#pragma unroll
            for (int ks2 = 0; ks2 < 2; ks2++) {
                uint32_t pa_h[2][4];
#pragma unroll
                for (int mt = 0; mt < 2; mt++) {
                    int rA2 = wm2 * 32 + mt * 16 + (lid & 15);
                    uint32_t bo = swz((uint32_t)(rA2 * 128 + (ks2 * 2 + (lid >> 4)) * 16));
                    ldm4(pa_h[mt], sbase + PHOFF + bo);
                }
#pragma unroll
                for (int nn = 0; nn < 4; nn++) {
                    int tl = lid >> 3;
                    int srow = (tl & 1) * 8 + (lid & 7) + ks2 * 16;
                    uint32_t bo = swz((uint32_t)(srow * 128 + (nn * 16 + (tl >> 1) * 8) * 2));
                    uint32_t bvh[4];
                    ldm4t(bvh, vhb + bo);
#pragma unroll
                    for (int mt = 0; mt < 2; mt++)
#pragma unroll
                        for (int h = 0; h < 2; h++)
                            mma16816(acc_o[mt][nn * 2 + h], pa_h[mt],
                                     bvh[h * 2], bvh[h * 2 + 1]);
                }
            }
        }
    }
    __syncthreads();

    /* ---- epilogue: normalize, single-fp16 store ---- */
#pragma unroll
    for (int mt = 0; mt < 2; mt++) {
        int rb = wm2 * 32 + mt * 16 + (lid >> 2);
#pragma unroll
        for (int sub = 0; sub < 2; sub++) {
            int r = rb + sub * 8;
            float inv = 1.0f / l_sm[r];
            int tq = tq0 + (r & 31);
            int n = khead * 2 + (r >> 5);
            size_t base = ((size_t)(b * TT + tq)) * 4096 + n * HDIM
                        + wn2 * 64 + (lid & 3) * 2;
#pragma unroll
            for (int nt = 0; nt < 8; nt++) {
                float o0 = acc_o[mt][nt][sub * 2 + 0] * inv;
                float o1 = acc_o[mt][nt][sub * 2 + 1] * inv;
                *(uint32_t*)(ench + base + nt * 8)
                    = (uint32_t)h_rn(o0) | ((uint32_t)h_rn(o1) << 16);
            }
        }
    }
}

/* ---------------- host launcher ---------------- */
extern "C" void kernel_launch(void* const* d_in, const int* in_sizes, int n_in,
                              void* d_out, int out_size)
{
    const float* x      = (const float*)d_in[0];
    const int*   segpos = (const int*)d_in[1];
    const float* q_w    = (const float*)d_in[3];
    const float* kv_w   = (const float*)d_in[4];
    const float* out_w  = (const float*)d_in[5];
    float* out = (float*)d_out;

    void *wt, *owt, *xh, *ench, *qkv;
    void *qhb, *khb, *vhb;
    cudaGetSymbolAddress(&wt,   g_wt);
    cudaGetSymbolAddress(&owt,  g_owt);
    cudaGetSymbolAddress(&xh,   g_xh);
    cudaGetSymbolAddress(&ench, g_ench);
    cudaGetSymbolAddress(&qkv,  g_qkv);
    cudaGetSymbolAddress(&qhb,  g_qh);
    cudaGetSymbolAddress(&khb,  g_kh);
    cudaGetSymbolAddress(&vhb,  g_vh);

    float* qkvf = (float*)qkv;

    cudaFuncSetAttribute(gemm_mma, cudaFuncAttributeMaxDynamicSharedMemorySize, GSMEM);
    cudaFuncSetAttribute(attn_mma, cudaFuncAttributeMaxDynamicSharedMemorySize, ASMEM);

    /* prep */
    ts_kernel<<<1, 128>>>();
    sc_kernel<<<MTOT * 128 / 256, 256>>>(segpos);
    trans_qkv_w<<<dim3(8192 / 32, DD / 32), 256>>>(q_w, kv_w);
    trans_ow<<<dim3(DD / 32, 4096 / 32), 256>>>(out_w);
    {
        int n4 = MTOT * DD / 4;
        convert_single<<<(n4 + 255) / 256, 256>>>((const float4*)x, (ushort4*)xh, n4);
    }

    /* GEMM1: qkv = x @ [q_w | k_w | v_w]; V tiles fused to fp16 */
    gemm_mma<<<dim3(8192 / 128, MTOT / 256), 256, GSMEM>>>(
        (const __half*)xh, DD,
        (const __half*)wt, DD,
        qkvf, QSTR, DD, (__half*)vhb);

    /* RoPE: Q single (scale folded), K single */
    {
        int totq = MTOT * NHE * 128;
        rope_single<<<totq / 256, 256>>>(qkvf, NHE, 0, SCALE_F,
                                         (unsigned short*)qhb, 4096, totq);
        int totk = MTOT * KHE * 128;
        rope_single<<<totk / 256, 256>>>(qkvf, KHE, 4096, 1.0f,
                                         (unsigned short*)khb, 2048, totk);
    }

    /* attention -> ench */
    attn_mma<<<dim3(TT / AQ, KHE, BB), 256, ASMEM>>>(
        (const __half*)qhb, (const __half*)khb, (const __half*)vhb,
        segpos,
        (__half*)ench);

    /* GEMM2: out = enc @ out_w  (M=4096, N=3584, K=4096) */
    gemm_mma<<<dim3(DD / 128, MTOT / 256), 256, GSMEM>>>(
        (const __half*)ench, 4096,
        (const __half*)owt, 4096,
        out, DD, 4096, (__half*)0);
}

// round 12
// speedup vs baseline: 10.4972x; 1.0664x over previous
#include <cuda_runtime.h>
#include <cuda_fp16.h>
#include <math.h>
#include <stdint.h>

#define BB 2
#define TT 2048
#define DD 3584
#define NHE 16
#define KHE 8
#define HDIM 256
#define WIN 1024
#define SCALE_F 0.0625f
#define MTOT (BB*TT)         /* 4096 */
#define QSTR 8192            /* row stride of fused qkv fp32 buffer */

/* ---------------- device globals (no allocations allowed) ---------------- */
__device__ __align__(128) __half g_wt[(size_t)8192 * DD];      /* single fp16 */
__device__ __align__(128) __half g_owt[(size_t)DD * 4096];     /* single fp16 */
__device__ __align__(128) __half g_xh[(size_t)MTOT * DD];      /* single */
__device__ __align__(128) __half g_ench[(size_t)MTOT * 4096];  /* single */
__device__ __align__(128) __half g_qh[(size_t)MTOT * 4096];    /* single */
__device__ __align__(128) __half g_kh[(size_t)MTOT * 2048];    /* single */
__device__ __align__(128) __half g_vh[(size_t)MTOT * 2048];    /* single */
__device__ __align__(128) float g_qkv[(size_t)MTOT * QSTR];
__device__ __align__(128) float2 g_sc[(size_t)MTOT * 128];
__device__ float g_ts[128];

/* ---------------- small helpers ---------------- */
__device__ __forceinline__ float rcp_fast(float x) {
    float r;
    asm("rcp.approx.f32 %0, %1;" : "=f"(r) : "f"(x));
    return r;
}
__device__ __forceinline__ float tanh_acc(float x) {
    float ax = fabsf(x);
    float e  = __expf(2.0f * ax);
    float r  = 1.0f - 2.0f * rcp_fast(e + 1.0f);   /* e=inf -> rcp=0 -> r=1 */
    return x < 0.0f ? -r : r;
}
__device__ __forceinline__ unsigned short h_rn(float f) {
    return __half_as_ushort(__float2half_rn(f));
}

__device__ __forceinline__ uint32_t smem_u32(const void* p) {
    uint32_t a;
    asm("{ .reg .u64 t; cvta.to.shared.u64 t, %1; cvt.u32.u64 %0, t; }" : "=r"(a) : "l"(p));
    return a;
}
__device__ __forceinline__ uint32_t swz(uint32_t off) {       /* SW128 */
    return off ^ ((off >> 3) & 0x70);
}
__device__ __forceinline__ void cp16(uint32_t saddr, const void* gaddr) {
    asm volatile("cp.async.cg.shared.global [%0], [%1], 16;" :: "r"(saddr), "l"(gaddr));
}
__device__ __forceinline__ void cp4(uint32_t saddr, const void* gaddr) {
    asm volatile("cp.async.ca.shared.global [%0], [%1], 4;" :: "r"(saddr), "l"(gaddr));
}
__device__ __forceinline__ void cp_commit() {
    asm volatile("cp.async.commit_group;" ::: "memory");
}
template <int N>
__device__ __forceinline__ void cp_wait() {
    asm volatile("cp.async.wait_group %0;" :: "n"(N) : "memory");
}
__device__ __forceinline__ void ldm4(uint32_t* r, uint32_t addr) {
    asm volatile("ldmatrix.sync.aligned.m8n8.x4.shared.b16 {%0,%1,%2,%3}, [%4];"
                 : "=r"(r[0]), "=r"(r[1]), "=r"(r[2]), "=r"(r[3]) : "r"(addr));
}
__device__ __forceinline__ void ldm4t(uint32_t* r, uint32_t addr) {
    asm volatile("ldmatrix.sync.aligned.m8n8.x4.trans.shared.b16 {%0,%1,%2,%3}, [%4];"
                 : "=r"(r[0]), "=r"(r[1]), "=r"(r[2]), "=r"(r[3]) : "r"(addr));
}
__device__ __forceinline__ void mma16816(float* d, const uint32_t* a,
                                         uint32_t b0, uint32_t b1) {
    asm volatile("mma.sync.aligned.m16n8k16.row.col.f32.f16.f16.f32 "
                 "{%0,%1,%2,%3}, {%4,%5,%6,%7}, {%8,%9}, {%0,%1,%2,%3};"
                 : "+f"(d[0]), "+f"(d[1]), "+f"(d[2]), "+f"(d[3])
                 : "r"(a[0]), "r"(a[1]), "r"(a[2]), "r"(a[3]), "r"(b0), "r"(b1));
}

/* ---------------- prep kernels ---------------- */
__global__ void ts_kernel() {
    int i = threadIdx.x;
    if (i < 128)
        g_ts[i] = (float)pow(10000.0, (double)i / 128.0);
}

__global__ void sc_kernel(const int* __restrict__ segpos) {
    int idx = blockIdx.x * 256 + threadIdx.x;          /* MTOT*128 */
    int bt = idx >> 7, i = idx & 127;
    int pos = segpos[bt];
    float ts = g_ts[i];
    float angf = __fdiv_rn((float)pos, ts);
    double sd, cd;
    sincos((double)angf, &sd, &cd);
    g_sc[idx] = make_float2((float)sd, (float)cd);
}

__global__ void __launch_bounds__(256) trans_qkv_w(const float* __restrict__ qw,
                                                   const float* __restrict__ kvw) {
    __shared__ float t[32][33];
    int c0 = blockIdx.x * 32, d0 = blockIdx.y * 32;
    int tx = threadIdx.x & 31, ty = threadIdx.x >> 5;
    int head = c0 >> 8, hb = c0 & 255;
    const float* src = (head < NHE) ? (qw + (size_t)head * DD * HDIM)
                                    : (kvw + (size_t)(head - NHE) * DD * HDIM);
#pragma unroll
    for (int i = 0; i < 4; i++)
        t[ty + 8 * i][tx] = src[(size_t)(d0 + ty + 8 * i) * HDIM + hb + tx];
    __syncthreads();
#pragma unroll
    for (int i = 0; i < 4; i++) {
        size_t o = (size_t)(c0 + ty + 8 * i) * DD + d0 + tx;
        ((unsigned short*)g_wt)[o] = h_rn(t[tx][ty + 8 * i]);
    }
}

__global__ void __launch_bounds__(256) trans_ow(const float* __restrict__ ow) {
    __shared__ float t[32][33];
    int c0 = blockIdx.x * 32, r0 = blockIdx.y * 32;
    int tx = threadIdx.x & 31, ty = threadIdx.x >> 5;
#pragma unroll
    for (int i = 0; i < 4; i++)
        t[ty + 8 * i][tx] = ow[(size_t)(r0 + ty + 8 * i) * DD + c0 + tx];
    __syncthreads();
#pragma unroll
    for (int i = 0; i < 4; i++) {
        size_t o = (size_t)(c0 + ty + 8 * i) * 4096 + r0 + tx;
        ((unsigned short*)g_owt)[o] = h_rn(t[tx][ty + 8 * i]);
    }
}

__global__ void convert_single(const float4* __restrict__ src, ushort4* __restrict__ h,
                               int n4) {
    int i = blockIdx.x * 256 + threadIdx.x;
    if (i >= n4) return;
    float4 v = src[i];
    ushort4 uh;
    uh.x = h_rn(v.x); uh.y = h_rn(v.y); uh.z = h_rn(v.z); uh.w = h_rn(v.w);
    h[i] = uh;
}

/* rope (table-driven), single-fp16 writeout (Q: scale folded; K: scale=1) */
__global__ void rope_single(const float* __restrict__ qkv, int heads, int colbase,
                            float scale, unsigned short* __restrict__ oh,
                            int ostride, int total) {
    int idx = blockIdx.x * 256 + threadIdx.x;
    if (idx >= total) return;
    int i = idx & 127;
    int rest = idx >> 7;
    int head = rest % heads;
    int bt = rest / heads;
    float2 sc = g_sc[(size_t)bt * 128 + i];
    float s = sc.x, c = sc.y;
    const float* p = qkv + (size_t)bt * QSTR + colbase + head * HDIM;
    float first = p[i], second = p[i + 128];
    size_t ob = (size_t)bt * ostride + head * HDIM;
    oh[ob + i]       = h_rn((first * c - second * s) * scale);
    oh[ob + i + 128] = h_rn((second * c + first * s) * scale);
}

/* ---------------- fp16 1-product GEMM, 256x128 tile ---------------- */
#define GK 64
#define G_AH 0u
#define G_BH 32768u
#define GSTAGE 49152u
#define GSMEM  98304

__device__ __forceinline__ void gemm_load(
    uint32_t sbase, int st, int k0, int row0, int col0,
    const __half* Ah, int lda, const __half* Bh, int ldb, int tid)
{
    uint32_t sb = sbase + (uint32_t)st * GSTAGE;
#pragma unroll
    for (int t = 0; t < 8; t++) {
        int idx = t * 256 + tid;
        int r = idx >> 3, c8 = idx & 7;
        uint32_t so = swz((uint32_t)(r * 128 + c8 * 16));
        size_t g = (size_t)(row0 + r) * lda + k0 + c8 * 8;
        cp16(sb + G_AH + so, Ah + g);
    }
#pragma unroll
    for (int t = 0; t < 4; t++) {
        int idx = t * 256 + tid;
        int r = idx >> 3, c8 = idx & 7;
        uint32_t so = swz((uint32_t)(r * 128 + c8 * 16));
        size_t g = (size_t)(col0 + r) * ldb + k0 + c8 * 8;
        cp16(sb + G_BH + so, Bh + g);
    }
}

__global__ void __launch_bounds__(256, 1) gemm_mma(
    const __half* __restrict__ Ah, int lda,
    const __half* __restrict__ Bh, int ldb,
    float* __restrict__ C, int ldc, int Kd,
    __half* __restrict__ Vout)
{
    extern __shared__ __align__(1024) char smem[];
    const uint32_t sbase = smem_u32(smem);
    const int tid = threadIdx.x;
    const int wid = tid >> 5, lid = tid & 31;
    const int wm = wid & 3, wn = wid >> 2;
    const int row0 = blockIdx.y * 256;
    const int col0 = blockIdx.x * 128;

    float acc[4][8][4];
#pragma unroll
    for (int i = 0; i < 4; i++)
#pragma unroll
        for (int j = 0; j < 8; j++)
#pragma unroll
            for (int kq = 0; kq < 4; kq++) acc[i][j][kq] = 0.0f;

    const int nch = Kd / GK;

    gemm_load(sbase, 0, 0, row0, col0, Ah, lda, Bh, ldb, tid);
    cp_commit();

    const int rAl = lid & 15;
    const int cA  = lid >> 4;
    const int rBl = (lid & 7) + ((lid >> 4) & 1) * 8;
    const int cB  = (lid >> 3) & 1;

    for (int c = 0; c < nch; c++) {
        const int st = c & 1;
        if (c + 1 < nch) {
            gemm_load(sbase, st ^ 1, (c + 1) * GK, row0, col0, Ah, lda, Bh, ldb, tid);
            cp_commit();
            cp_wait<1>();
        } else {
            cp_wait<0>();
        }
        __syncthreads();

        uint32_t sb = sbase + (uint32_t)st * GSTAGE;
#pragma unroll
        for (int ks = 0; ks < 4; ks++) {
            const int kc8 = ks * 2;
            uint32_t ah[4][4];
#pragma unroll
            for (int m4 = 0; m4 < 4; m4++) {
                uint32_t off = swz((uint32_t)((wm * 64 + m4 * 16 + rAl) * 128 + (kc8 + cA) * 16));
                ldm4(ah[m4], sb + G_AH + off);
            }
#pragma unroll
            for (int n16 = 0; n16 < 4; n16++) {
                uint32_t bh[4];
                uint32_t off = swz((uint32_t)((wn * 64 + n16 * 16 + rBl) * 128 + (kc8 + cB) * 16));
                ldm4(bh, sb + G_BH + off);
#pragma unroll
                for (int m4 = 0; m4 < 4; m4++)
#pragma unroll
                    for (int h = 0; h < 2; h++)
                        mma16816(acc[m4][n16 * 2 + h], ah[m4], bh[h * 2], bh[h * 2 + 1]);
            }
        }
        __syncthreads();
    }

    if (Vout != 0 && col0 >= 6144) {
#pragma unroll
        for (int m4 = 0; m4 < 4; m4++)
#pragma unroll
            for (int nt = 0; nt < 8; nt++) {
                int r = row0 + wm * 64 + m4 * 16 + (lid >> 2);
                int cc = (col0 - 6144) + wn * 64 + nt * 8 + (lid & 3) * 2;
                unsigned short a0 = h_rn(acc[m4][nt][0]);
                unsigned short a1 = h_rn(acc[m4][nt][1]);
                *(uint32_t*)((unsigned short*)Vout + (size_t)r * 2048 + cc)
                    = (uint32_t)a0 | ((uint32_t)a1 << 16);
                unsigned short b0 = h_rn(acc[m4][nt][2]);
                unsigned short b1 = h_rn(acc[m4][nt][3]);
                *(uint32_t*)((unsigned short*)Vout + (size_t)(r + 8) * 2048 + cc)
                    = (uint32_t)b0 | ((uint32_t)b1 << 16);
            }
    } else {
#pragma unroll
        for (int m4 = 0; m4 < 4; m4++)
#pragma unroll
            for (int nt = 0; nt < 8; nt++) {
                int r = row0 + wm * 64 + m4 * 16 + (lid >> 2);
                int cc = col0 + wn * 64 + nt * 8 + (lid & 3) * 2;
                float* p0 = C + (size_t)r * ldc + cc;
                p0[0] = acc[m4][nt][0];
                p0[1] = acc[m4][nt][1];
                float* p1 = C + (size_t)(r + 8) * ldc + cc;
                p1[0] = acc[m4][nt][2];
                p1[1] = acc[m4][nt][3];
            }
    }
}

/* ---------------- tensor-core flash attention (register softmax) ------------
   Q/K/P/V single fp16; scores stay in MMA fragments; cross-warp row
   reduction via tiny mpart/spart partials; m double-buffered by iter parity. */
#define AQ 32
#define ABK 32

#define QHOFF   0u            /* 32KB */
#define KHOFF   32768u        /* 2 stages x 16KB */
#define VHOFF   65536u        /* 2 stages x 16KB */
#define PHOFF   98304u        /* 8KB */
#define POSQOFF 106496u       /* 128B */
#define POSKOFF 106624u       /* 256B */
#define MPARTOFF 106880u      /* 2x64 f32 = 512B */
#define SPARTOFF 107392u      /* 512B */
#define MOFF    107904u       /* 2x64 f32 = 512B (iter-parity double buffer) */
#define LOFF    108416u       /* 256B */
#define ASMEM   108672

__device__ __forceinline__ void attn_load_stage(
    uint32_t sbase, int st, int s0, int b, int khead,
    const __half* kh, const __half* vh, const int* segpos, int tid)
{
    size_t gbase = ((size_t)(b * TT + s0)) * 2048 + khead * HDIM;
#pragma unroll
    for (int t = 0; t < 8; t++) {
        int idx = t * 256 + tid;                /* 0..2047: K then V, 1024 each */
        int isv = idx >> 10, rem = idx & 1023;
        int p = rem >> 8, r = (rem >> 3) & 31, ch = rem & 7;
        size_t g = gbase + (size_t)r * 2048 + p * 64 + ch * 8;
        uint32_t so = swz((uint32_t)(r * 128 + ch * 16));
        cp16(sbase + (isv ? VHOFF : KHOFF) + st * 16384 + p * 4096 + so,
             (isv ? vh : kh) + g);
    }
    if (tid < ABK)
        cp4(sbase + POSKOFF + st * 128 + tid * 4, segpos + b * TT + s0 + tid);
}

__global__ void __launch_bounds__(256, 2) attn_mma(
    const __half* __restrict__ qh,
    const __half* __restrict__ kh, const __half* __restrict__ vh,
    const int* __restrict__ segpos,
    __half* __restrict__ ench)
{
    extern __shared__ __align__(1024) char smemc[];
    const uint32_t sbase = smem_u32(smemc);
    const int tid = threadIdx.x;
    const int wid = tid >> 5, lid = tid & 31;
    const int tile = (int)(gridDim.x - 1) - (int)blockIdx.x;
    const int khead = blockIdx.y;
    const int b = blockIdx.z;
    const int tq0 = tile * AQ;

    int*   posq  = (int*)(smemc + POSQOFF);
    int*   posk  = (int*)(smemc + POSKOFF);
    float* mpart = (float*)(smemc + MPARTOFF);
    float* spart = (float*)(smemc + SPARTOFF);
    float* m_sm  = (float*)(smemc + MOFF);
    float* l_sm  = (float*)(smemc + LOFF);

    int s_begin = tq0 - (WIN - 1);
    if (s_begin < 0) s_begin = 0;
    s_begin &= ~(ABK - 1);
    const int nit = (tq0 + AQ - s_begin) / ABK;

    {
#pragma unroll
        for (int t = 0; t < 8; t++) {           /* Q single: 2048 vectors */
            int idx = t * 256 + tid;
            int p = idx >> 9, r = (idx >> 3) & 63, ch = idx & 7;
            int tq = tq0 + (r & 31);
            int n = khead * 2 + (r >> 5);
            size_t g = ((size_t)(b * TT + tq)) * 4096 + n * HDIM + p * 64 + ch * 8;
            uint32_t so = swz((uint32_t)(r * 128 + ch * 16));
            cp16(sbase + QHOFF + p * 8192 + so, qh + g);
        }
        if (tid < AQ) cp4(sbase + POSQOFF + tid * 4, segpos + b * TT + tq0 + tid);
        attn_load_stage(sbase, 0, s_begin, b, khead, kh, vh, segpos, tid);
        cp_commit();
    }
    if (tid < 64) { m_sm[tid] = -1e30f; l_sm[tid] = 0.0f; }

    float acc_o[2][8][4];
#pragma unroll
    for (int mt = 0; mt < 2; mt++)
#pragma unroll
        for (int nt = 0; nt < 8; nt++)
#pragma unroll
            for (int q = 0; q < 4; q++) acc_o[mt][nt][q] = 0.0f;

    const int wm = wid & 3, wn = wid >> 2;
    const int rA = wm * 16 + (lid & 15);
    const int cA = lid >> 4;
    const int rB = wn * 16 + (lid & 7) + ((lid >> 4) & 1) * 8;
    const int cB = (lid >> 3) & 1;
    const int wm2 = wid & 1, wn2 = wid >> 1;
    const int r0 = wm * 16 + (lid >> 2);       /* QK fragment rows r0, r0+8 */
    const int c0 = wn * 16 + (lid & 3) * 2;    /* QK fragment cols c0(+1), c0+8(+9) */

    for (int it = 0; it < nit; it++) {
        const int st = it & 1;
        const int s0 = s_begin + it * ABK;
        const int mcur = (it & 1) * 64, mnxt = 64 - mcur;
        cp_wait<0>();
        __syncthreads();                                        /* sync A */

        if (it + 1 < nit) {
            attn_load_stage(sbase, st ^ 1, s0 + ABK, b, khead, kh, vh, segpos, tid);
            cp_commit();
        }

        /* ---- QK in registers ---- */
        float acc_s[2][4] = {{0,0,0,0},{0,0,0,0}};
        {
            uint32_t khb = sbase + KHOFF + st * 16384;
#pragma unroll
            for (int ks = 0; ks < 16; ks++) {
                int p = ks >> 2, c2 = (ks & 3) * 2;
                uint32_t ah[4], bh[4];
                uint32_t ao = swz((uint32_t)(rA * 128 + (c2 + cA) * 16));
                ldm4(ah, sbase + QHOFF + p * 8192 + ao);
                uint32_t bo = swz((uint32_t)(rB * 128 + (c2 + cB) * 16));
                ldm4(bh, khb + p * 4096 + bo);
                mma16816(acc_s[0], ah, bh[0], bh[1]);
                mma16816(acc_s[1], ah, bh[2], bh[3]);
            }
        }

        /* ---- cap + mask + warp row-max, all in registers ---- */
        {
            int ti0 = tq0 + (r0 & 31), ti1 = ti0 + 8;   /* r0 in 0..55, r0+8 row */
            int pq0 = posq[r0 & 31], pq1 = posq[(r0 + 8) & 31];
            const int* pks = posk + st * 32;
            int pkc[4];
            pkc[0] = pks[c0];     pkc[1] = pks[c0 + 1];
            pkc[2] = pks[c0 + 8]; pkc[3] = pks[c0 + 9];
            float sc[2][4];
#pragma unroll
            for (int nt = 0; nt < 2; nt++)
#pragma unroll
                for (int e = 0; e < 4; e++) {
                    int col = c0 + nt * 8 + (e & 1);
                    int row_hi = e >> 1;                /* 0: r0, 1: r0+8 */
                    float cap = tanh_acc(acc_s[nt][e] * 0.02f) * 50.0f;
                    int si = s0 + col;
                    int ti = row_hi ? ti1 : ti0;
                    int pq = row_hi ? pq1 : pq0;
                    int pk = pkc[nt * 2 + (e & 1)];
                    bool valid = (si <= ti) && (pk > pq - WIN) && (pk < pq + WIN);
                    sc[nt][e] = valid ? cap : -1e30f;
                }
            float m0 = fmaxf(fmaxf(sc[0][0], sc[0][1]), fmaxf(sc[1][0], sc[1][1]));
            float m1 = fmaxf(fmaxf(sc[0][2], sc[0][3]), fmaxf(sc[1][2], sc[1][3]));
            m0 = fmaxf(m0, __shfl_xor_sync(0xffffffffu, m0, 1));
            m0 = fmaxf(m0, __shfl_xor_sync(0xffffffffu, m0, 2));
            m1 = fmaxf(m1, __shfl_xor_sync(0xffffffffu, m1, 1));
            m1 = fmaxf(m1, __shfl_xor_sync(0xffffffffu, m1, 2));
            if ((lid & 3) == 0) {
                mpart[wn * 64 + r0]     = m0;
                mpart[wn * 64 + r0 + 8] = m1;
            }
            __syncthreads();                                    /* sync 1 */

            float mo0 = m_sm[mcur + r0], mo1 = m_sm[mcur + r0 + 8];
            float mn0 = fmaxf(mo0, fmaxf(mpart[r0], mpart[64 + r0]));
            float mn1 = fmaxf(mo1, fmaxf(mpart[r0 + 8], mpart[64 + r0 + 8]));
            float p00 = (sc[0][0] < -1e29f) ? 0.0f : __expf(sc[0][0] - mn0);
            float p01 = (sc[0][1] < -1e29f) ? 0.0f : __expf(sc[0][1] - mn0);
            float p10 = (sc[1][0] < -1e29f) ? 0.0f : __expf(sc[1][0] - mn0);
            float p11 = (sc[1][1] < -1e29f) ? 0.0f : __expf(sc[1][1] - mn0);
            float q00 = (sc[0][2] < -1e29f) ? 0.0f : __expf(sc[0][2] - mn1);
            float q01 = (sc[0][3] < -1e29f) ? 0.0f : __expf(sc[0][3] - mn1);
            float q10 = (sc[1][2] < -1e29f) ? 0.0f : __expf(sc[1][2] - mn1);
            float q11 = (sc[1][3] < -1e29f) ? 0.0f : __expf(sc[1][3] - mn1);
            /* P writes (swizzled fp16 pairs) */
            {
                uint32_t bo;
                bo = (uint32_t)(r0 * 128 + c0 * 2);
                *(uint32_t*)(smemc + PHOFF + (bo ^ ((bo >> 3) & 0x70)))
                    = (uint32_t)h_rn(p00) | ((uint32_t)h_rn(p01) << 16);
                bo = (uint32_t)(r0 * 128 + (c0 + 8) * 2);
                *(uint32_t*)(smemc + PHOFF + (bo ^ ((bo >> 3) & 0x70)))
                    = (uint32_t)h_rn(p10) | ((uint32_t)h_rn(p11) << 16);
                bo = (uint32_t)((r0 + 8) * 128 + c0 * 2);
                *(uint32_t*)(smemc + PHOFF + (bo ^ ((bo >> 3) & 0x70)))
                    = (uint32_t)h_rn(q00) | ((uint32_t)h_rn(q01) << 16);
                bo = (uint32_t)((r0 + 8) * 128 + (c0 + 8) * 2);
                *(uint32_t*)(smemc + PHOFF + (bo ^ ((bo >> 3) & 0x70)))
                    = (uint32_t)h_rn(q10) | ((uint32_t)h_rn(q11) << 16);
            }
            float ps0 = p00 + p01 + p10 + p11;
            float ps1 = q00 + q01 + q10 + q11;
            ps0 += __shfl_xor_sync(0xffffffffu, ps0, 1);
            ps0 += __shfl_xor_sync(0xffffffffu, ps0, 2);
            ps1 += __shfl_xor_sync(0xffffffffu, ps1, 1);
            ps1 += __shfl_xor_sync(0xffffffffu, ps1, 2);
            if ((lid & 3) == 0) {
                spart[wn * 64 + r0]     = ps0;
                spart[wn * 64 + r0 + 8] = ps1;
            }
            __syncthreads();                                    /* sync 2 */

            if (wn == 0 && (lid & 3) == 0) {
                l_sm[r0] = l_sm[r0] * __expf(mo0 - mn0)
                         + spart[r0] + spart[64 + r0];
                l_sm[r0 + 8] = l_sm[r0 + 8] * __expf(mo1 - mn1)
                             + spart[r0 + 8] + spart[64 + r0 + 8];
                m_sm[mnxt + r0]     = mn0;
                m_sm[mnxt + r0 + 8] = mn1;
            }
        }

        /* ---- rescale + PV ---- */
        {
#pragma unroll
            for (int mt = 0; mt < 2; mt++) {
                int rp = wm2 * 32 + mt * 16 + (lid >> 2);
#pragma unroll
                for (int sub = 0; sub < 2; sub++) {
                    int r = rp + sub * 8;
                    float mo = m_sm[mcur + r];
                    float mn = fmaxf(mo, fmaxf(mpart[r], mpart[64 + r]));
                    float corr = __expf(mo - mn);
#pragma unroll
                    for (int nt = 0; nt < 8; nt++) {
                        acc_o[mt][nt][sub * 2 + 0] *= corr;
                        acc_o[mt][nt][sub * 2 + 1] *= corr;
                    }
                }
            }
            uint32_t vhb = sbase + VHOFF + st * 16384 + wn2 * 4096;
#pragma unroll
            for (int ks2 = 0; ks2 < 2; ks2++) {
                uint32_t pa_h[2][4];
#pragma unroll
                for (int mt = 0; mt < 2; mt++) {
                    int rA2 = wm2 * 32 + mt * 16 + (lid & 15);
                    uint32_t bo = swz((uint32_t)(rA2 * 128 + (ks2 * 2 + (lid >> 4)) * 16));
                    ldm4(pa_h[mt], sbase + PHOFF + bo);
                }
#pragma unroll
                for (int nn = 0; nn < 4; nn++) {
                    int tl = lid >> 3;
                    int srow = (tl & 1) * 8 + (lid & 7) + ks2 * 16;
                    uint32_t bo = swz((uint32_t)(srow * 128 + (nn * 16 + (tl >> 1) * 8) * 2));
                    uint32_t bvh[4];
                    ldm4t(bvh, vhb + bo);
#pragma unroll
                    for (int mt = 0; mt < 2; mt++)
#pragma unroll
                        for (int h = 0; h < 2; h++)
                            mma16816(acc_o[mt][nn * 2 + h], pa_h[mt],
                                     bvh[h * 2], bvh[h * 2 + 1]);
                }
            }
        }
    }
    __syncthreads();

    /* ---- epilogue: normalize, single-fp16 store ---- */
#pragma unroll
    for (int mt = 0; mt < 2; mt++) {
        int rb = wm2 * 32 + mt * 16 + (lid >> 2);
#pragma unroll
        for (int sub = 0; sub < 2; sub++) {
            int r = rb + sub * 8;
            float inv = 1.0f / l_sm[r];
            int tq = tq0 + (r & 31);
            int n = khead * 2 + (r >> 5);
            size_t base = ((size_t)(b * TT + tq)) * 4096 + n * HDIM
                        + wn2 * 64 + (lid & 3) * 2;
#pragma unroll
            for (int nt = 0; nt < 8; nt++) {
                float o0 = acc_o[mt][nt][sub * 2 + 0] * inv;
                float o1 = acc_o[mt][nt][sub * 2 + 1] * inv;
                *(uint32_t*)(ench + base + nt * 8)
                    = (uint32_t)h_rn(o0) | ((uint32_t)h_rn(o1) << 16);
            }
        }
    }
}

/* ---------------- host launcher ---------------- */
extern "C" void kernel_launch(void* const* d_in, const int* in_sizes, int n_in,
                              void* d_out, int out_size)
{
    const float* x      = (const float*)d_in[0];
    const int*   segpos = (const int*)d_in[1];
    const float* q_w    = (const float*)d_in[3];
    const float* kv_w   = (const float*)d_in[4];
    const float* out_w  = (const float*)d_in[5];
    float* out = (float*)d_out;

    void *wt, *owt, *xh, *ench, *qkv;
    void *qhb, *khb, *vhb;
    cudaGetSymbolAddress(&wt,   g_wt);
    cudaGetSymbolAddress(&owt,  g_owt);
    cudaGetSymbolAddress(&xh,   g_xh);
    cudaGetSymbolAddress(&ench, g_ench);
    cudaGetSymbolAddress(&qkv,  g_qkv);
    cudaGetSymbolAddress(&qhb,  g_qh);
    cudaGetSymbolAddress(&khb,  g_kh);
    cudaGetSymbolAddress(&vhb,  g_vh);

    float* qkvf = (float*)qkv;

    cudaFuncSetAttribute(gemm_mma, cudaFuncAttributeMaxDynamicSharedMemorySize, GSMEM);
    cudaFuncSetAttribute(attn_mma, cudaFuncAttributeMaxDynamicSharedMemorySize, ASMEM);

    /* prep */
    ts_kernel<<<1, 128>>>();
    sc_kernel<<<MTOT * 128 / 256, 256>>>(segpos);
    trans_qkv_w<<<dim3(8192 / 32, DD / 32), 256>>>(q_w, kv_w);
    trans_ow<<<dim3(DD / 32, 4096 / 32), 256>>>(out_w);
    {
        int n4 = MTOT * DD / 4;
        convert_single<<<(n4 + 255) / 256, 256>>>((const float4*)x, (ushort4*)xh, n4);
    }

    /* GEMM1: qkv = x @ [q_w | k_w | v_w]; V tiles fused to fp16 */
    gemm_mma<<<dim3(8192 / 128, MTOT / 256), 256, GSMEM>>>(
        (const __half*)xh, DD,
        (const __half*)wt, DD,
        qkvf, QSTR, DD, (__half*)vhb);

    /* RoPE: Q single (scale folded), K single */
    {
        int totq = MTOT * NHE * 128;
        rope_single<<<totq / 256, 256>>>(qkvf, NHE, 0, SCALE_F,
                                         (unsigned short*)qhb, 4096, totq);
        int totk = MTOT * KHE * 128;
        rope_single<<<totk / 256, 256>>>(qkvf, KHE, 4096, 1.0f,
                                         (unsigned short*)khb, 2048, totk);
    }

    /* attention -> ench */
    attn_mma<<<dim3(TT / AQ, KHE, BB), 256, ASMEM>>>(
        (const __half*)qhb, (const __half*)khb, (const __half*)vhb,
        segpos,
        (__half*)ench);

    /* GEMM2: out = enc @ out_w  (M=4096, N=3584, K=4096) */
    gemm_mma<<<dim3(DD / 128, MTOT / 256), 256, GSMEM>>>(
        (const __half*)ench, 4096,
        (const __half*)owt, 4096,
        out, DD, 4096, (__half*)0);
}

// round 13
// speedup vs baseline: 10.5702x; 1.0070x over previous
#include <cuda_runtime.h>
#include <cuda_fp16.h>
#include <math.h>
#include <stdint.h>

#define BB 2
#define TT 2048
#define DD 3584
#define NHE 16
#define KHE 8
#define HDIM 256
#define WIN 1024
#define SCALE_F 0.0625f
#define MTOT (BB*TT)         /* 4096 */

/* ---------------- device globals (no allocations allowed) ---------------- */
__device__ __align__(128) __half g_wt[(size_t)8192 * DD];      /* single fp16 */
__device__ __align__(128) __half g_owt[(size_t)DD * 4096];     /* single fp16 */
__device__ __align__(128) __half g_xh[(size_t)MTOT * DD];      /* single */
__device__ __align__(128) __half g_ench[(size_t)MTOT * 4096];  /* single */
__device__ __align__(128) __half g_qkvh[(size_t)MTOT * 6144];  /* pre-rope Q|K fp16 */
__device__ __align__(128) __half g_qh[(size_t)MTOT * 4096];    /* single */
__device__ __align__(128) __half g_kh[(size_t)MTOT * 2048];    /* single */
__device__ __align__(128) __half g_vh[(size_t)MTOT * 2048];    /* single */
__device__ __align__(128) float2 g_sc[(size_t)MTOT * 128];
__device__ float g_ts[128];

/* ---------------- small helpers ---------------- */
__device__ __forceinline__ float rcp_fast(float x) {
    float r;
    asm("rcp.approx.f32 %0, %1;" : "=f"(r) : "f"(x));
    return r;
}
__device__ __forceinline__ float tanh_acc(float x) {
    float ax = fabsf(x);
    float e  = __expf(2.0f * ax);
    float r  = 1.0f - 2.0f * rcp_fast(e + 1.0f);   /* e=inf -> rcp=0 -> r=1 */
    return x < 0.0f ? -r : r;
}
__device__ __forceinline__ unsigned short h_rn(float f) {
    return __half_as_ushort(__float2half_rn(f));
}

__device__ __forceinline__ uint32_t smem_u32(const void* p) {
    uint32_t a;
    asm("{ .reg .u64 t; cvta.to.shared.u64 t, %1; cvt.u32.u64 %0, t; }" : "=r"(a) : "l"(p));
    return a;
}
__device__ __forceinline__ uint32_t swz(uint32_t off) {       /* SW128 */
    return off ^ ((off >> 3) & 0x70);
}
__device__ __forceinline__ void cp16(uint32_t saddr, const void* gaddr) {
    asm volatile("cp.async.cg.shared.global [%0], [%1], 16;" :: "r"(saddr), "l"(gaddr));
}
__device__ __forceinline__ void cp4(uint32_t saddr, const void* gaddr) {
    asm volatile("cp.async.ca.shared.global [%0], [%1], 4;" :: "r"(saddr), "l"(gaddr));
}
__device__ __forceinline__ void cp_commit() {
    asm volatile("cp.async.commit_group;" ::: "memory");
}
template <int N>
__device__ __forceinline__ void cp_wait() {
    asm volatile("cp.async.wait_group %0;" :: "n"(N) : "memory");
}
__device__ __forceinline__ void ldm4(uint32_t* r, uint32_t addr) {
    asm volatile("ldmatrix.sync.aligned.m8n8.x4.shared.b16 {%0,%1,%2,%3}, [%4];"
                 : "=r"(r[0]), "=r"(r[1]), "=r"(r[2]), "=r"(r[3]) : "r"(addr));
}
__device__ __forceinline__ void ldm4t(uint32_t* r, uint32_t addr) {
    asm volatile("ldmatrix.sync.aligned.m8n8.x4.trans.shared.b16 {%0,%1,%2,%3}, [%4];"
                 : "=r"(r[0]), "=r"(r[1]), "=r"(r[2]), "=r"(r[3]) : "r"(addr));
}
__device__ __forceinline__ void mma16816(float* d, const uint32_t* a,
                                         uint32_t b0, uint32_t b1) {
    asm volatile("mma.sync.aligned.m16n8k16.row.col.f32.f16.f16.f32 "
                 "{%0,%1,%2,%3}, {%4,%5,%6,%7}, {%8,%9}, {%0,%1,%2,%3};"
                 : "+f"(d[0]), "+f"(d[1]), "+f"(d[2]), "+f"(d[3])
                 : "r"(a[0]), "r"(a[1]), "r"(a[2]), "r"(a[3]), "r"(b0), "r"(b1));
}

/* ---------------- prep kernels ---------------- */
__global__ void ts_kernel() {
    int i = threadIdx.x;
    if (i < 128)
        g_ts[i] = (float)pow(10000.0, (double)i / 128.0);
}

__global__ void sc_kernel(const int* __restrict__ segpos) {
    int idx = blockIdx.x * 256 + threadIdx.x;          /* MTOT*128 */
    int bt = idx >> 7, i = idx & 127;
    int pos = segpos[bt];
    float ts = g_ts[i];
    float angf = __fdiv_rn((float)pos, ts);
    double sd, cd;
    sincos((double)angf, &sd, &cd);
    g_sc[idx] = make_float2((float)sd, (float)cd);
}

__global__ void __launch_bounds__(256) trans_qkv_w(const float* __restrict__ qw,
                                                   const float* __restrict__ kvw) {
    __shared__ float t[32][33];
    int c0 = blockIdx.x * 32, d0 = blockIdx.y * 32;
    int tx = threadIdx.x & 31, ty = threadIdx.x >> 5;
    int head = c0 >> 8, hb = c0 & 255;
    const float* src = (head < NHE) ? (qw + (size_t)head * DD * HDIM)
                                    : (kvw + (size_t)(head - NHE) * DD * HDIM);
#pragma unroll
    for (int i = 0; i < 4; i++)
        t[ty + 8 * i][tx] = src[(size_t)(d0 + ty + 8 * i) * HDIM + hb + tx];
    __syncthreads();
#pragma unroll
    for (int i = 0; i < 4; i++) {
        size_t o = (size_t)(c0 + ty + 8 * i) * DD + d0 + tx;
        ((unsigned short*)g_wt)[o] = h_rn(t[tx][ty + 8 * i]);
    }
}

__global__ void __launch_bounds__(256) trans_ow(const float* __restrict__ ow) {
    __shared__ float t[32][33];
    int c0 = blockIdx.x * 32, r0 = blockIdx.y * 32;
    int tx = threadIdx.x & 31, ty = threadIdx.x >> 5;
#pragma unroll
    for (int i = 0; i < 4; i++)
        t[ty + 8 * i][tx] = ow[(size_t)(r0 + ty + 8 * i) * DD + c0 + tx];
    __syncthreads();
#pragma unroll
    for (int i = 0; i < 4; i++) {
        size_t o = (size_t)(c0 + ty + 8 * i) * 4096 + r0 + tx;
        ((unsigned short*)g_owt)[o] = h_rn(t[tx][ty + 8 * i]);
    }
}

__global__ void convert_single(const float4* __restrict__ src, ushort4* __restrict__ h,
                               int n4) {
    int i = blockIdx.x * 256 + threadIdx.x;
    if (i >= n4) return;
    float4 v = src[i];
    ushort4 uh;
    uh.x = h_rn(v.x); uh.y = h_rn(v.y); uh.z = h_rn(v.z); uh.w = h_rn(v.w);
    h[i] = uh;
}

/* fused rope for Q and K (table-driven), fp16 in -> fp16 out */
__global__ void rope_fused(const __half* __restrict__ qkvh,
                           unsigned short* __restrict__ qout,
                           unsigned short* __restrict__ kout, int totq, int total) {
    int idx = blockIdx.x * 256 + threadIdx.x;
    if (idx >= total) return;
    int heads, colbase, ostride, local;
    float scale;
    unsigned short* oh;
    if (idx < totq) {
        heads = NHE; colbase = 0; scale = SCALE_F; oh = qout; ostride = 4096;
        local = idx;
    } else {
        heads = KHE; colbase = 4096; scale = 1.0f; oh = kout; ostride = 2048;
        local = idx - totq;
    }
    int i = local & 127;
    int rest = local >> 7;
    int head = rest % heads;
    int bt = rest / heads;
    float2 sc = g_sc[(size_t)bt * 128 + i];
    float s = sc.x, c = sc.y;
    const __half* p = qkvh + (size_t)bt * 6144 + colbase + head * HDIM;
    float first = __half2float(p[i]), second = __half2float(p[i + 128]);
    size_t ob = (size_t)bt * ostride + head * HDIM;
    oh[ob + i]       = h_rn((first * c - second * s) * scale);
    oh[ob + i + 128] = h_rn((second * c + first * s) * scale);
}

/* ---------------- fp16 1-product GEMM, 256x128 tile ----------------
   C = A x B^T. GEMM1 (Hout set): all outputs fp16 — Q|K region to Hout
   (stride 6144), V region to Vout (stride 2048). GEMM2: fp32 C. */
#define GK 64
#define G_AH 0u
#define G_BH 32768u
#define GSTAGE 49152u
#define GSMEM  98304

__device__ __forceinline__ void gemm_load(
    uint32_t sbase, int st, int k0, int row0, int col0,
    const __half* Ah, int lda, const __half* Bh, int ldb, int tid)
{
    uint32_t sb = sbase + (uint32_t)st * GSTAGE;
#pragma unroll
    for (int t = 0; t < 8; t++) {
        int idx = t * 256 + tid;
        int r = idx >> 3, c8 = idx & 7;
        uint32_t so = swz((uint32_t)(r * 128 + c8 * 16));
        size_t g = (size_t)(row0 + r) * lda + k0 + c8 * 8;
        cp16(sb + G_AH + so, Ah + g);
    }
#pragma unroll
    for (int t = 0; t < 4; t++) {
        int idx = t * 256 + tid;
        int r = idx >> 3, c8 = idx & 7;
        uint32_t so = swz((uint32_t)(r * 128 + c8 * 16));
        size_t g = (size_t)(col0 + r) * ldb + k0 + c8 * 8;
        cp16(sb + G_BH + so, Bh + g);
    }
}

__global__ void __launch_bounds__(256, 1) gemm_mma(
    const __half* __restrict__ Ah, int lda,
    const __half* __restrict__ Bh, int ldb,
    float* __restrict__ C, int ldc, int Kd,
    __half* __restrict__ Hout, __half* __restrict__ Vout)
{
    extern __shared__ __align__(1024) char smem[];
    const uint32_t sbase = smem_u32(smem);
    const int tid = threadIdx.x;
    const int wid = tid >> 5, lid = tid & 31;
    const int wm = wid & 3, wn = wid >> 2;
    const int row0 = blockIdx.y * 256;
    const int col0 = blockIdx.x * 128;

    float acc[4][8][4];
#pragma unroll
    for (int i = 0; i < 4; i++)
#pragma unroll
        for (int j = 0; j < 8; j++)
#pragma unroll
            for (int kq = 0; kq < 4; kq++) acc[i][j][kq] = 0.0f;

    const int nch = Kd / GK;

    gemm_load(sbase, 0, 0, row0, col0, Ah, lda, Bh, ldb, tid);
    cp_commit();

    const int rAl = lid & 15;
    const int cA  = lid >> 4;
    const int rBl = (lid & 7) + ((lid >> 4) & 1) * 8;
    const int cB  = (lid >> 3) & 1;

    for (int c = 0; c < nch; c++) {
        const int st = c & 1;
        if (c + 1 < nch) {
            gemm_load(sbase, st ^ 1, (c + 1) * GK, row0, col0, Ah, lda, Bh, ldb, tid);
            cp_commit();
            cp_wait<1>();
        } else {
            cp_wait<0>();
        }
        __syncthreads();

        uint32_t sb = sbase + (uint32_t)st * GSTAGE;
#pragma unroll
        for (int ks = 0; ks < 4; ks++) {
            const int kc8 = ks * 2;
            uint32_t ah[4][4];
#pragma unroll
            for (int m4 = 0; m4 < 4; m4++) {
                uint32_t off = swz((uint32_t)((wm * 64 + m4 * 16 + rAl) * 128 + (kc8 + cA) * 16));
                ldm4(ah[m4], sb + G_AH + off);
            }
#pragma unroll
            for (int n16 = 0; n16 < 4; n16++) {
                uint32_t bh[4];
                uint32_t off = swz((uint32_t)((wn * 64 + n16 * 16 + rBl) * 128 + (kc8 + cB) * 16));
                ldm4(bh, sb + G_BH + off);
#pragma unroll
                for (int m4 = 0; m4 < 4; m4++)
#pragma unroll
                    for (int h = 0; h < 2; h++)
                        mma16816(acc[m4][n16 * 2 + h], ah[m4], bh[h * 2], bh[h * 2 + 1]);
            }
        }
        __syncthreads();
    }

    if (Hout != 0) {
        unsigned short* dst;
        int ldd, cbase;
        if (col0 < 6144) { dst = (unsigned short*)Hout; ldd = 6144; cbase = col0; }
        else             { dst = (unsigned short*)Vout; ldd = 2048; cbase = col0 - 6144; }
#pragma unroll
        for (int m4 = 0; m4 < 4; m4++)
#pragma unroll
            for (int nt = 0; nt < 8; nt++) {
                int r = row0 + wm * 64 + m4 * 16 + (lid >> 2);
                int cc = cbase + wn * 64 + nt * 8 + (lid & 3) * 2;
                unsigned short a0 = h_rn(acc[m4][nt][0]);
                unsigned short a1 = h_rn(acc[m4][nt][1]);
                *(uint32_t*)(dst + (size_t)r * ldd + cc)
                    = (uint32_t)a0 | ((uint32_t)a1 << 16);
                unsigned short b0 = h_rn(acc[m4][nt][2]);
                unsigned short b1 = h_rn(acc[m4][nt][3]);
                *(uint32_t*)(dst + (size_t)(r + 8) * ldd + cc)
                    = (uint32_t)b0 | ((uint32_t)b1 << 16);
            }
    } else {
#pragma unroll
        for (int m4 = 0; m4 < 4; m4++)
#pragma unroll
            for (int nt = 0; nt < 8; nt++) {
                int r = row0 + wm * 64 + m4 * 16 + (lid >> 2);
                int cc = col0 + wn * 64 + nt * 8 + (lid & 3) * 2;
                float* p0 = C + (size_t)r * ldc + cc;
                p0[0] = acc[m4][nt][0];
                p0[1] = acc[m4][nt][1];
                float* p1 = C + (size_t)(r + 8) * ldc + cc;
                p1[0] = acc[m4][nt][2];
                p1[1] = acc[m4][nt][3];
            }
    }
}

/* ---------------- tensor-core flash attention (register softmax + reg l) ---- */
#define AQ 32
#define ABK 32

#define QHOFF   0u            /* 32KB */
#define KHOFF   32768u        /* 2 stages x 16KB */
#define VHOFF   65536u        /* 2 stages x 16KB */
#define PHOFF   98304u        /* 8KB */
#define POSQOFF 106496u       /* 128B */
#define POSKOFF 106624u       /* 256B */
#define MPARTOFF 106880u      /* 2x64 f32 = 512B */
#define SPARTOFF 107392u      /* 512B (final l exchange) */
#define MOFF    107904u       /* 2x64 f32 (iter-parity double buffer) */
#define ASMEM   108416

__device__ __forceinline__ void attn_load_stage(
    uint32_t sbase, int st, int s0, int b, int khead,
    const __half* kh, const __half* vh, const int* segpos, int tid)
{
    size_t gbase = ((size_t)(b * TT + s0)) * 2048 + khead * HDIM;
#pragma unroll
    for (int t = 0; t < 8; t++) {
        int idx = t * 256 + tid;                /* 0..2047: K then V, 1024 each */
        int isv = idx >> 10, rem = idx & 1023;
        int p = rem >> 8, r = (rem >> 3) & 31, ch = rem & 7;
        size_t g = gbase + (size_t)r * 2048 + p * 64 + ch * 8;
        uint32_t so = swz((uint32_t)(r * 128 + ch * 16));
        cp16(sbase + (isv ? VHOFF : KHOFF) + st * 16384 + p * 4096 + so,
             (isv ? vh : kh) + g);
    }
    if (tid < ABK)
        cp4(sbase + POSKOFF + st * 128 + tid * 4, segpos + b * TT + s0 + tid);
}

__global__ void __launch_bounds__(256, 2) attn_mma(
    const __half* __restrict__ qh,
    const __half* __restrict__ kh, const __half* __restrict__ vh,
    const int* __restrict__ segpos,
    __half* __restrict__ ench)
{
    extern __shared__ __align__(1024) char smemc[];
    const uint32_t sbase = smem_u32(smemc);
    const int tid = threadIdx.x;
    const int wid = tid >> 5, lid = tid & 31;
    const int tile = (int)(gridDim.x - 1) - (int)blockIdx.x;
    const int khead = blockIdx.y;
    const int b = blockIdx.z;
    const int tq0 = tile * AQ;

    int*   posq  = (int*)(smemc + POSQOFF);
    int*   posk  = (int*)(smemc + POSKOFF);
    float* mpart = (float*)(smemc + MPARTOFF);
    float* spart = (float*)(smemc + SPARTOFF);
    float* m_sm  = (float*)(smemc + MOFF);

    int s_begin = tq0 - (WIN - 1);
    if (s_begin < 0) s_begin = 0;
    s_begin &= ~(ABK - 1);
    const int nit = (tq0 + AQ - s_begin) / ABK;

    {
#pragma unroll
        for (int t = 0; t < 8; t++) {           /* Q single: 2048 vectors */
            int idx = t * 256 + tid;
            int p = idx >> 9, r = (idx >> 3) & 63, ch = idx & 7;
            int tq = tq0 + (r & 31);
            int n = khead * 2 + (r >> 5);
            size_t g = ((size_t)(b * TT + tq)) * 4096 + n * HDIM + p * 64 + ch * 8;
            uint32_t so = swz((uint32_t)(r * 128 + ch * 16));
            cp16(sbase + QHOFF + p * 8192 + so, qh + g);
        }
        if (tid < AQ) cp4(sbase + POSQOFF + tid * 4, segpos + b * TT + tq0 + tid);
        attn_load_stage(sbase, 0, s_begin, b, khead, kh, vh, segpos, tid);
        cp_commit();
    }
    if (tid < 64) m_sm[tid] = -1e30f;

    float acc_o[2][8][4];
#pragma unroll
    for (int mt = 0; mt < 2; mt++)
#pragma unroll
        for (int nt = 0; nt < 8; nt++)
#pragma unroll
            for (int q = 0; q < 4; q++) acc_o[mt][nt][q] = 0.0f;

    const int wm = wid & 3, wn = wid >> 2;
    const int rA = wm * 16 + (lid & 15);
    const int cA = lid >> 4;
    const int rB = wn * 16 + (lid & 7) + ((lid >> 4) & 1) * 8;
    const int cB = (lid >> 3) & 1;
    const int wm2 = wid & 1, wn2 = wid >> 1;
    const int r0 = wm * 16 + (lid >> 2);       /* QK fragment rows r0, r0+8 */
    const int c0 = wn * 16 + (lid & 3) * 2;    /* QK fragment cols */
    float lp0 = 0.0f, lp1 = 0.0f;              /* per-warp row l partials */

    for (int it = 0; it < nit; it++) {
        const int st = it & 1;
        const int s0 = s_begin + it * ABK;
        const int mcur = (it & 1) * 64, mnxt = 64 - mcur;
        cp_wait<0>();
        __syncthreads();                                        /* sync A */

        if (it + 1 < nit) {
            attn_load_stage(sbase, st ^ 1, s0 + ABK, b, khead, kh, vh, segpos, tid);
            cp_commit();
        }

        /* ---- QK in registers ---- */
        float acc_s[2][4] = {{0,0,0,0},{0,0,0,0}};
        {
            uint32_t khb = sbase + KHOFF + st * 16384;
#pragma unroll
            for (int ks = 0; ks < 16; ks++) {
                int p = ks >> 2, c2 = (ks & 3) * 2;
                uint32_t ah[4], bh[4];
                uint32_t ao = swz((uint32_t)(rA * 128 + (c2 + cA) * 16));
                ldm4(ah, sbase + QHOFF + p * 8192 + ao);
                uint32_t bo = swz((uint32_t)(rB * 128 + (c2 + cB) * 16));
                ldm4(bh, khb + p * 4096 + bo);
                mma16816(acc_s[0], ah, bh[0], bh[1]);
                mma16816(acc_s[1], ah, bh[2], bh[3]);
            }
        }

        /* ---- cap + mask + warp row-max ---- */
        {
            int ti0 = tq0 + (r0 & 31), ti1 = ti0 + 8;
            int pq0 = posq[r0 & 31], pq1 = posq[(r0 + 8) & 31];
            const int* pks = posk + st * 32;
            int pkc[4];
            pkc[0] = pks[c0];     pkc[1] = pks[c0 + 1];
            pkc[2] = pks[c0 + 8]; pkc[3] = pks[c0 + 9];
            float sc[2][4];
#pragma unroll
            for (int nt = 0; nt < 2; nt++)
#pragma unroll
                for (int e = 0; e < 4; e++) {
                    int col = c0 + nt * 8 + (e & 1);
                    int row_hi = e >> 1;
                    float cap = tanh_acc(acc_s[nt][e] * 0.02f) * 50.0f;
                    int si = s0 + col;
                    int ti = row_hi ? ti1 : ti0;
                    int pq = row_hi ? pq1 : pq0;
                    int pk = pkc[nt * 2 + (e & 1)];
                    bool valid = (si <= ti) && (pk > pq - WIN) && (pk < pq + WIN);
                    sc[nt][e] = valid ? cap : -1e30f;
                }
            float m0 = fmaxf(fmaxf(sc[0][0], sc[0][1]), fmaxf(sc[1][0], sc[1][1]));
            float m1 = fmaxf(fmaxf(sc[0][2], sc[0][3]), fmaxf(sc[1][2], sc[1][3]));
            m0 = fmaxf(m0, __shfl_xor_sync(0xffffffffu, m0, 1));
            m0 = fmaxf(m0, __shfl_xor_sync(0xffffffffu, m0, 2));
            m1 = fmaxf(m1, __shfl_xor_sync(0xffffffffu, m1, 1));
            m1 = fmaxf(m1, __shfl_xor_sync(0xffffffffu, m1, 2));
            if ((lid & 3) == 0) {
                mpart[wn * 64 + r0]     = m0;
                mpart[wn * 64 + r0 + 8] = m1;
            }
            __syncthreads();                                    /* sync 1 */

            float mo0 = m_sm[mcur + r0], mo1 = m_sm[mcur + r0 + 8];
            float mn0 = fmaxf(mo0, fmaxf(mpart[r0], mpart[64 + r0]));
            float mn1 = fmaxf(mo1, fmaxf(mpart[r0 + 8], mpart[64 + r0 + 8]));
            float p00 = (sc[0][0] < -1e29f) ? 0.0f : __expf(sc[0][0] - mn0);
            float p01 = (sc[0][1] < -1e29f) ? 0.0f : __expf(sc[0][1] - mn0);
            float p10 = (sc[1][0] < -1e29f) ? 0.0f : __expf(sc[1][0] - mn0);
            float p11 = (sc[1][1] < -1e29f) ? 0.0f : __expf(sc[1][1] - mn0);
            float q00 = (sc[0][2] < -1e29f) ? 0.0f : __expf(sc[0][2] - mn1);
            float q01 = (sc[0][3] < -1e29f) ? 0.0f : __expf(sc[0][3] - mn1);
            float q10 = (sc[1][2] < -1e29f) ? 0.0f : __expf(sc[1][2] - mn1);
            float q11 = (sc[1][3] < -1e29f) ? 0.0f : __expf(sc[1][3] - mn1);
            {
                uint32_t bo;
                bo = (uint32_t)(r0 * 128 + c0 * 2);
                *(uint32_t*)(smemc + PHOFF + (bo ^ ((bo >> 3) & 0x70)))
                    = (uint32_t)h_rn(p00) | ((uint32_t)h_rn(p01) << 16);
                bo = (uint32_t)(r0 * 128 + (c0 + 8) * 2);
                *(uint32_t*)(smemc + PHOFF + (bo ^ ((bo >> 3) & 0x70)))
                    = (uint32_t)h_rn(p10) | ((uint32_t)h_rn(p11) << 16);
                bo = (uint32_t)((r0 + 8) * 128 + c0 * 2);
                *(uint32_t*)(smemc + PHOFF + (bo ^ ((bo >> 3) & 0x70)))
                    = (uint32_t)h_rn(q00) | ((uint32_t)h_rn(q01) << 16);
                bo = (uint32_t)((r0 + 8) * 128 + (c0 + 8) * 2);
                *(uint32_t*)(smemc + PHOFF + (bo ^ ((bo >> 3) & 0x70)))
                    = (uint32_t)h_rn(q10) | ((uint32_t)h_rn(q11) << 16);
            }
            float ps0 = p00 + p01 + p10 + p11;
            float ps1 = q00 + q01 + q10 + q11;
            ps0 += __shfl_xor_sync(0xffffffffu, ps0, 1);
            ps0 += __shfl_xor_sync(0xffffffffu, ps0, 2);
            ps1 += __shfl_xor_sync(0xffffffffu, ps1, 1);
            ps1 += __shfl_xor_sync(0xffffffffu, ps1, 2);
            lp0 = lp0 * __expf(mo0 - mn0) + ps0;
            lp1 = lp1 * __expf(mo1 - mn1) + ps1;
            if (wn == 0 && (lid & 3) == 0) {
                m_sm[mnxt + r0]     = mn0;
                m_sm[mnxt + r0 + 8] = mn1;
            }
        }
        __syncthreads();                                        /* sync 2 */

        /* ---- rescale + PV ---- */
        {
#pragma unroll
            for (int mt = 0; mt < 2; mt++) {
                int rp = wm2 * 32 + mt * 16 + (lid >> 2);
#pragma unroll
                for (int sub = 0; sub < 2; sub++) {
                    int r = rp + sub * 8;
                    float mo = m_sm[mcur + r];
                    float mn = fmaxf(mo, fmaxf(mpart[r], mpart[64 + r]));
                    float corr = __expf(mo - mn);
#pragma unroll
                    for (int nt = 0; nt < 8; nt++) {
                        acc_o[mt][nt][sub * 2 + 0] *= corr;
                        acc_o[mt][nt][sub * 2 + 1] *= corr;
                    }
                }
            }
            uint32_t vhb = sbase + VHOFF + st * 16384 + wn2 * 4096;
#pragma unroll
            for (int ks2 = 0; ks2 < 2; ks2++) {
                uint32_t pa_h[2][4];
#pragma unroll
                for (int mt = 0; mt < 2; mt++) {
                    int rA2 = wm2 * 32 + mt * 16 + (lid & 15);
                    uint32_t bo = swz((uint32_t)(rA2 * 128 + (ks2 * 2 + (lid >> 4)) * 16));
                    ldm4(pa_h[mt], sbase + PHOFF + bo);
                }
#pragma unroll
                for (int nn = 0; nn < 4; nn++) {
                    int tl = lid >> 3;
                    int srow = (tl & 1) * 8 + (lid & 7) + ks2 * 16;
                    uint32_t bo = swz((uint32_t)(srow * 128 + (nn * 16 + (tl >> 1) * 8) * 2));
                    uint32_t bvh[4];
                    ldm4t(bvh, vhb + bo);
#pragma unroll
                    for (int mt = 0; mt < 2; mt++)
#pragma unroll
                        for (int h = 0; h < 2; h++)
                            mma16816(acc_o[mt][nn * 2 + h], pa_h[mt],
                                     bvh[h * 2], bvh[h * 2 + 1]);
                }
            }
        }
    }

    /* final l exchange: both warp groups' partials -> spart */
    if ((lid & 3) == 0) {
        spart[wn * 64 + r0]     = lp0;
        spart[wn * 64 + r0 + 8] = lp1;
    }
    __syncthreads();

    /* ---- epilogue: normalize, single-fp16 store ---- */
#pragma unroll
    for (int mt = 0; mt < 2; mt++) {
        int rb = wm2 * 32 + mt * 16 + (lid >> 2);
#pragma unroll
        for (int sub = 0; sub < 2; sub++) {
            int r = rb + sub * 8;
            float inv = 1.0f / (spart[r] + spart[64 + r]);
            int tq = tq0 + (r & 31);
            int n = khead * 2 + (r >> 5);
            size_t base = ((size_t)(b * TT + tq)) * 4096 + n * HDIM
                        + wn2 * 64 + (lid & 3) * 2;
#pragma unroll
            for (int nt = 0; nt < 8; nt++) {
                float o0 = acc_o[mt][nt][sub * 2 + 0] * inv;
                float o1 = acc_o[mt][nt][sub * 2 + 1] * inv;
                *(uint32_t*)(ench + base + nt * 8)
                    = (uint32_t)h_rn(o0) | ((uint32_t)h_rn(o1) << 16);
            }
        }
    }
}

/* ---------------- host launcher ---------------- */
extern "C" void kernel_launch(void* const* d_in, const int* in_sizes, int n_in,
                              void* d_out, int out_size)
{
    const float* x      = (const float*)d_in[0];
    const int*   segpos = (const int*)d_in[1];
    const float* q_w    = (const float*)d_in[3];
    const float* kv_w   = (const float*)d_in[4];
    const float* out_w  = (const float*)d_in[5];
    float* out = (float*)d_out;

    void *wt, *owt, *xh, *ench, *qkvh;
    void *qhb, *khb, *vhb;
    cudaGetSymbolAddress(&wt,    g_wt);
    cudaGetSymbolAddress(&owt,   g_owt);
    cudaGetSymbolAddress(&xh,    g_xh);
    cudaGetSymbolAddress(&ench,  g_ench);
    cudaGetSymbolAddress(&qkvh,  g_qkvh);
    cudaGetSymbolAddress(&qhb,   g_qh);
    cudaGetSymbolAddress(&khb,   g_kh);
    cudaGetSymbolAddress(&vhb,   g_vh);

    cudaFuncSetAttribute(gemm_mma, cudaFuncAttributeMaxDynamicSharedMemorySize, GSMEM);
    cudaFuncSetAttribute(attn_mma, cudaFuncAttributeMaxDynamicSharedMemorySize, ASMEM);

    /* prep (ordered so gemm_mma is the 6th launch for ncu -s 5) */
    trans_qkv_w<<<dim3(8192 / 32, DD / 32), 256>>>(q_w, kv_w);        /* 1 */
    trans_ow<<<dim3(DD / 32, 4096 / 32), 256>>>(out_w);               /* 2 */
    {
        int n4 = MTOT * DD / 4;
        convert_single<<<(n4 + 255) / 256, 256>>>((const float4*)x,
                                                  (ushort4*)xh, n4);  /* 3 */
    }
    ts_kernel<<<1, 128>>>();                                          /* 4 */
    sc_kernel<<<MTOT * 128 / 256, 256>>>(segpos);                     /* 5 */

    /* GEMM1: [Q|K] fp16 -> g_qkvh, V fp16 -> g_vh */
    gemm_mma<<<dim3(8192 / 128, MTOT / 256), 256, GSMEM>>>(           /* 6 */
        (const __half*)xh, DD,
        (const __half*)wt, DD,
        (float*)0, 0, DD, (__half*)qkvh, (__half*)vhb);

    /* fused RoPE: Q (scale folded) + K */
    {
        int totq = MTOT * NHE * 128;
        int totk = MTOT * KHE * 128;
        int total = totq + totk;
        rope_fused<<<(total + 255) / 256, 256>>>(
            (const __half*)qkvh, (unsigned short*)qhb, (unsigned short*)khb,
            totq, total);                                             /* 7 */
    }

    /* attention -> ench */
    attn_mma<<<dim3(TT / AQ, KHE, BB), 256, ASMEM>>>(                 /* 8 */
        (const __half*)qhb, (const __half*)khb, (const __half*)vhb,
        segpos,
        (__half*)ench);

    /* GEMM2: out = enc @ out_w  (M=4096, N=3584, K=4096) */
    gemm_mma<<<dim3(DD / 128, MTOT / 256), 256, GSMEM>>>(             /* 9 */
        (const __half*)ench, 4096,
        (const __half*)owt, 4096,
        out, DD, 4096, (__half*)0, (__half*)0);
}

// round 15
// speedup vs baseline: 10.6773x; 1.0101x over previous
#include <cuda_runtime.h>
#include <cuda_fp16.h>
#include <math.h>
#include <stdint.h>

#define BB 2
#define TT 2048
#define DD 3584
#define NHE 16
#define KHE 8
#define HDIM 256
#define WIN 1024
#define SCALE_F 0.0625f
#define MTOT (BB*TT)         /* 4096 */

/* ---------------- device globals (no allocations allowed) ---------------- */
__device__ __align__(128) __half g_wt[(size_t)8192 * DD];      /* single fp16 */
__device__ __align__(128) __half g_owt[(size_t)DD * 4096];     /* single fp16 */
__device__ __align__(128) __half g_xh[(size_t)MTOT * DD];      /* single */
__device__ __align__(128) __half g_ench[(size_t)MTOT * 4096];  /* single */
__device__ __align__(128) __half g_qkvh[(size_t)MTOT * 6144];  /* pre-rope Q|K fp16 */
__device__ __align__(128) __half g_kh[(size_t)MTOT * 2048];    /* roped K */
__device__ __align__(128) __half g_vh[(size_t)MTOT * 2048];    /* V */
__device__ __align__(128) float2 g_sc[(size_t)MTOT * 128];
__device__ float g_ts[128];

/* ---------------- small helpers ---------------- */
__device__ __forceinline__ float rcp_fast(float x) {
    float r;
    asm("rcp.approx.f32 %0, %1;" : "=f"(r) : "f"(x));
    return r;
}
__device__ __forceinline__ float tanh_acc(float x) {
    float ax = fabsf(x);
    float e  = __expf(2.0f * ax);
    float r  = 1.0f - 2.0f * rcp_fast(e + 1.0f);   /* e=inf -> rcp=0 -> r=1 */
    return x < 0.0f ? -r : r;
}
__device__ __forceinline__ unsigned short h_rn(float f) {
    return __half_as_ushort(__float2half_rn(f));
}

__device__ __forceinline__ uint32_t smem_u32(const void* p) {
    uint32_t a;
    asm("{ .reg .u64 t; cvta.to.shared.u64 t, %1; cvt.u32.u64 %0, t; }" : "=r"(a) : "l"(p));
    return a;
}
__device__ __forceinline__ uint32_t swz(uint32_t off) {       /* SW128 */
    return off ^ ((off >> 3) & 0x70);
}
__device__ __forceinline__ void cp16(uint32_t saddr, const void* gaddr) {
    asm volatile("cp.async.cg.shared.global [%0], [%1], 16;" :: "r"(saddr), "l"(gaddr));
}
__device__ __forceinline__ void cp4(uint32_t saddr, const void* gaddr) {
    asm volatile("cp.async.ca.shared.global [%0], [%1], 4;" :: "r"(saddr), "l"(gaddr));
}
__device__ __forceinline__ void cp_commit() {
    asm volatile("cp.async.commit_group;" ::: "memory");
}
template <int N>
__device__ __forceinline__ void cp_wait() {
    asm volatile("cp.async.wait_group %0;" :: "n"(N) : "memory");
}
__device__ __forceinline__ void ldm4(uint32_t* r, uint32_t addr) {
    asm volatile("ldmatrix.sync.aligned.m8n8.x4.shared.b16 {%0,%1,%2,%3}, [%4];"
                 : "=r"(r[0]), "=r"(r[1]), "=r"(r[2]), "=r"(r[3]) : "r"(addr));
}
__device__ __forceinline__ void ldm4t(uint32_t* r, uint32_t addr) {
    asm volatile("ldmatrix.sync.aligned.m8n8.x4.trans.shared.b16 {%0,%1,%2,%3}, [%4];"
                 : "=r"(r[0]), "=r"(r[1]), "=r"(r[2]), "=r"(r[3]) : "r"(addr));
}
__device__ __forceinline__ void mma16816(float* d, const uint32_t* a,
                                         uint32_t b0, uint32_t b1) {
    asm volatile("mma.sync.aligned.m16n8k16.row.col.f32.f16.f16.f32 "
                 "{%0,%1,%2,%3}, {%4,%5,%6,%7}, {%8,%9}, {%0,%1,%2,%3};"
                 : "+f"(d[0]), "+f"(d[1]), "+f"(d[2]), "+f"(d[3])
                 : "r"(a[0]), "r"(a[1]), "r"(a[2]), "r"(a[3]), "r"(b0), "r"(b1));
}

/* ---------------- prep kernels ---------------- */
__global__ void ts_kernel() {
    int i = threadIdx.x;
    if (i < 128)
        g_ts[i] = (float)pow(10000.0, (double)i / 128.0);
}

__global__ void sc_kernel(const int* __restrict__ segpos) {
    int idx = blockIdx.x * 256 + threadIdx.x;          /* MTOT*128 */
    int bt = idx >> 7, i = idx & 127;
    int pos = segpos[bt];
    float ts = g_ts[i];
    float angf = __fdiv_rn((float)pos, ts);
    double sd, cd;
    sincos((double)angf, &sd, &cd);
    g_sc[idx] = make_float2((float)sd, (float)cd);
}

__global__ void __launch_bounds__(256) trans_qkv_w(const float* __restrict__ qw,
                                                   const float* __restrict__ kvw) {
    __shared__ float t[32][33];
    int c0 = blockIdx.x * 32, d0 = blockIdx.y * 32;
    int tx = threadIdx.x & 31, ty = threadIdx.x >> 5;
    int head = c0 >> 8, hb = c0 & 255;
    const float* src = (head < NHE) ? (qw + (size_t)head * DD * HDIM)
                                    : (kvw + (size_t)(head - NHE) * DD * HDIM);
#pragma unroll
    for (int i = 0; i < 4; i++)
        t[ty + 8 * i][tx] = src[(size_t)(d0 + ty + 8 * i) * HDIM + hb + tx];
    __syncthreads();
    /* vectorized store: each thread packs 2 adjacent d into one u32 */
    int cl = threadIdx.x >> 4;            /* 0..15 */
    int d2 = (threadIdx.x & 15) * 2;      /* 0..30 even */
#pragma unroll
    for (int pass = 0; pass < 2; pass++) {
        int c = cl + pass * 16;
        uint32_t v = (uint32_t)h_rn(t[d2][c]) | ((uint32_t)h_rn(t[d2 + 1][c]) << 16);
        *(uint32_t*)((unsigned short*)g_wt + (size_t)(c0 + c) * DD + d0 + d2) = v;
    }
}

__global__ void __launch_bounds__(256) trans_ow(const float* __restrict__ ow) {
    __shared__ float t[32][33];
    int c0 = blockIdx.x * 32, r0 = blockIdx.y * 32;
    int tx = threadIdx.x & 31, ty = threadIdx.x >> 5;
#pragma unroll
    for (int i = 0; i < 4; i++)
        t[ty + 8 * i][tx] = ow[(size_t)(r0 + ty + 8 * i) * DD + c0 + tx];
    __syncthreads();
    int cl = threadIdx.x >> 4;
    int d2 = (threadIdx.x & 15) * 2;
#pragma unroll
    for (int pass = 0; pass < 2; pass++) {
        int c = cl + pass * 16;
        uint32_t v = (uint32_t)h_rn(t[d2][c]) | ((uint32_t)h_rn(t[d2 + 1][c]) << 16);
        *(uint32_t*)((unsigned short*)g_owt + (size_t)(c0 + c) * 4096 + r0 + d2) = v;
    }
}

__global__ void convert_single(const float4* __restrict__ src, ushort4* __restrict__ h,
                               int n4) {
    int i = blockIdx.x * 256 + threadIdx.x;
    if (i >= n4) return;
    float4 v = src[i];
    ushort4 uh;
    uh.x = h_rn(v.x); uh.y = h_rn(v.y); uh.z = h_rn(v.z); uh.w = h_rn(v.w);
    h[i] = uh;
}

/* rope for K only (Q is roped inside attention prologue) */
__global__ void rope_k(const __half* __restrict__ qkvh,
                       unsigned short* __restrict__ kout, int total) {
    int idx = blockIdx.x * 256 + threadIdx.x;
    if (idx >= total) return;
    int i = idx & 127;
    int rest = idx >> 7;
    int head = rest % KHE;
    int bt = rest / KHE;
    float2 sc = g_sc[(size_t)bt * 128 + i];
    float s = sc.x, c = sc.y;
    const __half* p = qkvh + (size_t)bt * 6144 + 4096 + head * HDIM;
    float first = __half2float(p[i]), second = __half2float(p[i + 128]);
    size_t ob = (size_t)bt * 2048 + head * HDIM;
    kout[ob + i]       = h_rn(first * c - second * s);
    kout[ob + i + 128] = h_rn(second * c + first * s);
}

/* ---------------- fp16 1-product GEMM, 256x128 tile, 3-stage pipe ----------
   C = A x B^T. GEMM1 (Hout set): Q|K fp16 -> Hout (stride 6144),
   V fp16 -> Vout (stride 2048). GEMM2: fp32 C. One barrier per K-chunk. */
#define GK 64
#define G_AH 0u
#define G_BH 32768u
#define GSTAGE 49152u
#define GSMEM  147456          /* 3 stages */

__device__ __forceinline__ void gemm_load(
    uint32_t sbase, int st, int k0, int row0, int col0,
    const __half* Ah, int lda, const __half* Bh, int ldb, int tid)
{
    uint32_t sb = sbase + (uint32_t)st * GSTAGE;
#pragma unroll
    for (int t = 0; t < 8; t++) {
        int idx = t * 256 + tid;
        int r = idx >> 3, c8 = idx & 7;
        uint32_t so = swz((uint32_t)(r * 128 + c8 * 16));
        size_t g = (size_t)(row0 + r) * lda + k0 + c8 * 8;
        cp16(sb + G_AH + so, Ah + g);
    }
#pragma unroll
    for (int t = 0; t < 4; t++) {
        int idx = t * 256 + tid;
        int r = idx >> 3, c8 = idx & 7;
        uint32_t so = swz((uint32_t)(r * 128 + c8 * 16));
        size_t g = (size_t)(col0 + r) * ldb + k0 + c8 * 8;
        cp16(sb + G_BH + so, Bh + g);
    }
}

__global__ void __launch_bounds__(256, 1) gemm_mma(
    const __half* __restrict__ Ah, int lda,
    const __half* __restrict__ Bh, int ldb,
    float* __restrict__ C, int ldc, int Kd,
    __half* __restrict__ Hout, __half* __restrict__ Vout)
{
    extern __shared__ __align__(1024) char smem[];
    const uint32_t sbase = smem_u32(smem);
    const int tid = threadIdx.x;
    const int wid = tid >> 5, lid = tid & 31;
    const int wm = wid & 3, wn = wid >> 2;
    const int row0 = blockIdx.y * 256;
    const int col0 = blockIdx.x * 128;

    float acc[4][8][4];
#pragma unroll
    for (int i = 0; i < 4; i++)
#pragma unroll
        for (int j = 0; j < 8; j++)
#pragma unroll
            for (int kq = 0; kq < 4; kq++) acc[i][j][kq] = 0.0f;

    const int nch = Kd / GK;

    gemm_load(sbase, 0, 0, row0, col0, Ah, lda, Bh, ldb, tid);
    cp_commit();
    gemm_load(sbase, 1, GK, row0, col0, Ah, lda, Bh, ldb, tid);
    cp_commit();

    const int rAl = lid & 15;
    const int cA  = lid >> 4;
    const int rBl = (lid & 7) + ((lid >> 4) & 1) * 8;
    const int cB  = (lid >> 3) & 1;

    int st = 0, pst = 2;
    for (int c = 0; c < nch; c++) {
        if (c + 1 < nch) cp_wait<1>();
        else             cp_wait<0>();
        __syncthreads();                     /* only barrier per chunk */
        if (c + 2 < nch) {
            gemm_load(sbase, pst, (c + 2) * GK, row0, col0, Ah, lda, Bh, ldb, tid);
            cp_commit();
        }

        uint32_t sb = sbase + (uint32_t)st * GSTAGE;
#pragma unroll
        for (int ks = 0; ks < 4; ks++) {
            const int kc8 = ks * 2;
            uint32_t ah[4][4];
#pragma unroll
            for (int m4 = 0; m4 < 4; m4++) {
                uint32_t off = swz((uint32_t)((wm * 64 + m4 * 16 + rAl) * 128 + (kc8 + cA) * 16));
                ldm4(ah[m4], sb + G_AH + off);
            }
#pragma unroll
            for (int n16 = 0; n16 < 4; n16++) {
                uint32_t bh[4];
                uint32_t off = swz((uint32_t)((wn * 64 + n16 * 16 + rBl) * 128 + (kc8 + cB) * 16));
                ldm4(bh, sb + G_BH + off);
#pragma unroll
                for (int m4 = 0; m4 < 4; m4++)
#pragma unroll
                    for (int h = 0; h < 2; h++)
                        mma16816(acc[m4][n16 * 2 + h], ah[m4], bh[h * 2], bh[h * 2 + 1]);
            }
        }
        st = (st == 2) ? 0 : st + 1;
        pst = (pst == 2) ? 0 : pst + 1;
    }

    if (Hout != 0) {
        unsigned short* dst;
        int ldd, cbase;
        if (col0 < 6144) { dst = (unsigned short*)Hout; ldd = 6144; cbase = col0; }
        else             { dst = (unsigned short*)Vout; ldd = 2048; cbase = col0 - 6144; }
#pragma unroll
        for (int m4 = 0; m4 < 4; m4++)
#pragma unroll
            for (int nt = 0; nt < 8; nt++) {
                int r = row0 + wm * 64 + m4 * 16 + (lid >> 2);
                int cc = cbase + wn * 64 + nt * 8 + (lid & 3) * 2;
                unsigned short a0 = h_rn(acc[m4][nt][0]);
                unsigned short a1 = h_rn(acc[m4][nt][1]);
                *(uint32_t*)(dst + (size_t)r * ldd + cc)
                    = (uint32_t)a0 | ((uint32_t)a1 << 16);
                unsigned short b0 = h_rn(acc[m4][nt][2]);
                unsigned short b1 = h_rn(acc[m4][nt][3]);
                *(uint32_t*)(dst + (size_t)(r + 8) * ldd + cc)
                    = (uint32_t)b0 | ((uint32_t)b1 << 16);
            }
    } else {
#pragma unroll
        for (int m4 = 0; m4 < 4; m4++)
#pragma unroll
            for (int nt = 0; nt < 8; nt++) {
                int r = row0 + wm * 64 + m4 * 16 + (lid >> 2);
                int cc = col0 + wn * 64 + nt * 8 + (lid & 3) * 2;
                float* p0 = C + (size_t)r * ldc + cc;
                p0[0] = acc[m4][nt][0];
                p0[1] = acc[m4][nt][1];
                float* p1 = C + (size_t)(r + 8) * ldc + cc;
                p1[0] = acc[m4][nt][2];
                p1[1] = acc[m4][nt][3];
            }
    }
}

/* ---------------- tensor-core flash attention (register softmax + reg l,
   fused Q-RoPE in prologue) ---- */
#define AQ 32
#define ABK 32

#define QHOFF   0u            /* 32KB */
#define KHOFF   32768u        /* 2 stages x 16KB */
#define VHOFF   65536u        /* 2 stages x 16KB */
#define PHOFF   98304u        /* 8KB */
#define POSQOFF 106496u       /* 128B */
#define POSKOFF 106624u       /* 256B */
#define MPARTOFF 106880u      /* 2x64 f32 = 512B */
#define SPARTOFF 107392u      /* 512B (final l exchange) */
#define MOFF    107904u       /* 2x64 f32 (iter-parity double buffer) */
#define ASMEM   108416

__device__ __forceinline__ void attn_load_stage(
    uint32_t sbase, int st, int s0, int b, int khead,
    const __half* kh, const __half* vh, const int* segpos, int tid)
{
    size_t gbase = ((size_t)(b * TT + s0)) * 2048 + khead * HDIM;
#pragma unroll
    for (int t = 0; t < 8; t++) {
        int idx = t * 256 + tid;                /* 0..2047: K then V, 1024 each */
        int isv = idx >> 10, rem = idx & 1023;
        int p = rem >> 8, r = (rem >> 3) & 31, ch = rem & 7;
        size_t g = gbase + (size_t)r * 2048 + p * 64 + ch * 8;
        uint32_t so = swz((uint32_t)(r * 128 + ch * 16));
        cp16(sbase + (isv ? VHOFF : KHOFF) + st * 16384 + p * 4096 + so,
             (isv ? vh : kh) + g);
    }
    if (tid < ABK)
        cp4(sbase + POSKOFF + st * 128 + tid * 4, segpos + b * TT + s0 + tid);
}

__global__ void __launch_bounds__(256, 2) attn_mma(
    const __half* __restrict__ qsrc,       /* pre-rope Q in g_qkvh (stride 6144) */
    const __half* __restrict__ kh, const __half* __restrict__ vh,
    const int* __restrict__ segpos,
    __half* __restrict__ ench)
{
    extern __shared__ __align__(1024) char smemc[];
    const uint32_t sbase = smem_u32(smemc);
    const int tid = threadIdx.x;
    const int wid = tid >> 5, lid = tid & 31;
    const int tile = (int)(gridDim.x - 1) - (int)blockIdx.x;
    const int khead = blockIdx.y;
    const int b = blockIdx.z;
    const int tq0 = tile * AQ;

    int*   posq  = (int*)(smemc + POSQOFF);
    int*   posk  = (int*)(smemc + POSKOFF);
    float* mpart = (float*)(smemc + MPARTOFF);
    float* spart = (float*)(smemc + SPARTOFF);
    float* m_sm  = (float*)(smemc + MOFF);

    int s_begin = tq0 - (WIN - 1);
    if (s_begin < 0) s_begin = 0;
    s_begin &= ~(ABK - 1);
    const int nit = (tq0 + AQ - s_begin) / ABK;

    {
#pragma unroll
        for (int t = 0; t < 8; t++) {           /* Q (pre-rope): 2048 vectors */
            int idx = t * 256 + tid;
            int p = idx >> 9, r = (idx >> 3) & 63, ch = idx & 7;
            int tq = tq0 + (r & 31);
            int n = khead * 2 + (r >> 5);
            size_t g = ((size_t)(b * TT + tq)) * 6144 + n * HDIM + p * 64 + ch * 8;
            uint32_t so = swz((uint32_t)(r * 128 + ch * 16));
            cp16(sbase + QHOFF + p * 8192 + so, qsrc + g);
        }
        if (tid < AQ) cp4(sbase + POSQOFF + tid * 4, segpos + b * TT + tq0 + tid);
        attn_load_stage(sbase, 0, s_begin, b, khead, kh, vh, segpos, tid);
        cp_commit();
    }
    if (tid < 64) m_sm[tid] = -1e30f;

    /* ---- fused Q-RoPE in smem (scale folded) ---- */
    cp_wait<0>();
    __syncthreads();
    {
        size_t bt0 = (size_t)(b * TT + tq0);
        for (int idx = tid; idx < 64 * 128; idx += 256) {
            int r = idx >> 7, i = idx & 127;
            float2 sc = g_sc[(bt0 + (r & 31)) * 128 + i];
            int p = i >> 6, cw = i & 63;
            uint32_t so = swz((uint32_t)(r * 128 + cw * 2));
            __half* a1 = (__half*)(smemc + QHOFF + p * 8192 + so);
            __half* a2 = (__half*)(smemc + QHOFF + (p + 2) * 8192 + so);
            float first = __half2float(*a1), second = __half2float(*a2);
            *a1 = __float2half_rn((first * sc.y - second * sc.x) * SCALE_F);
            *a2 = __float2half_rn((second * sc.y + first * sc.x) * SCALE_F);
        }
    }

    float acc_o[2][8][4];
#pragma unroll
    for (int mt = 0; mt < 2; mt++)
#pragma unroll
        for (int nt = 0; nt < 8; nt++)
#pragma unroll
            for (int q = 0; q < 4; q++) acc_o[mt][nt][q] = 0.0f;

    const int wm = wid & 3, wn = wid >> 2;
    const int rA = wm * 16 + (lid & 15);
    const int cA = lid >> 4;
    const int rB = wn * 16 + (lid & 7) + ((lid >> 4) & 1) * 8;
    const int cB = (lid >> 3) & 1;
    const int wm2 = wid & 1, wn2 = wid >> 1;
    const int r0 = wm * 16 + (lid >> 2);       /* QK fragment rows r0, r0+8 */
    const int c0 = wn * 16 + (lid & 3) * 2;    /* QK fragment cols */
    float lp0 = 0.0f, lp1 = 0.0f;              /* per-warp row l partials */

    for (int it = 0; it < nit; it++) {
        const int st = it & 1;
        const int s0 = s_begin + it * ABK;
        const int mcur = (it & 1) * 64, mnxt = 64 - mcur;
        cp_wait<0>();
        __syncthreads();                                        /* sync A */

        if (it + 1 < nit) {
            attn_load_stage(sbase, st ^ 1, s0 + ABK, b, khead, kh, vh, segpos, tid);
            cp_commit();
        }

        /* ---- QK in registers ---- */
        float acc_s[2][4] = {{0,0,0,0},{0,0,0,0}};
        {
            uint32_t khb = sbase + KHOFF + st * 16384;
#pragma unroll
            for (int ks = 0; ks < 16; ks++) {
                int p = ks >> 2, c2 = (ks & 3) * 2;
                uint32_t ah[4], bh[4];
                uint32_t ao = swz((uint32_t)(rA * 128 + (c2 + cA) * 16));
                ldm4(ah, sbase + QHOFF + p * 8192 + ao);
                uint32_t bo = swz((uint32_t)(rB * 128 + (c2 + cB) * 16));
                ldm4(bh, khb + p * 4096 + bo);
                mma16816(acc_s[0], ah, bh[0], bh[1]);
                mma16816(acc_s[1], ah, bh[2], bh[3]);
            }
        }

        /* ---- cap + mask + warp row-max ---- */
        {
            int ti0 = tq0 + (r0 & 31), ti1 = ti0 + 8;
            int pq0 = posq[r0 & 31], pq1 = posq[(r0 + 8) & 31];
            const int* pks = posk + st * 32;
            int pkc[4];
            pkc[0] = pks[c0];     pkc[1] = pks[c0 + 1];
            pkc[2] = pks[c0 + 8]; pkc[3] = pks[c0 + 9];
            float sc[2][4];
#pragma unroll
            for (int nt = 0; nt < 2; nt++)
#pragma unroll
                for (int e = 0; e < 4; e++) {
                    int col = c0 + nt * 8 + (e & 1);
                    int row_hi = e >> 1;
                    float cap = tanh_acc(acc_s[nt][e] * 0.02f) * 50.0f;
                    int si = s0 + col;
                    int ti = row_hi ? ti1 : ti0;
                    int pq = row_hi ? pq1 : pq0;
                    int pk = pkc[nt * 2 + (e & 1)];
                    bool valid = (si <= ti) && (pk > pq - WIN) && (pk < pq + WIN);
                    sc[nt][e] = valid ? cap : -1e30f;
                }
            float m0 = fmaxf(fmaxf(sc[0][0], sc[0][1]), fmaxf(sc[1][0], sc[1][1]));
            float m1 = fmaxf(fmaxf(sc[0][2], sc[0][3]), fmaxf(sc[1][2], sc[1][3]));
            m0 = fmaxf(m0, __shfl_xor_sync(0xffffffffu, m0, 1));
            m0 = fmaxf(m0, __shfl_xor_sync(0xffffffffu, m0, 2));
            m1 = fmaxf(m1, __shfl_xor_sync(0xffffffffu, m1, 1));
            m1 = fmaxf(m1, __shfl_xor_sync(0xffffffffu, m1, 2));
            if ((lid & 3) == 0) {
                mpart[wn * 64 + r0]     = m0;
                mpart[wn * 64 + r0 + 8] = m1;
            }
            __syncthreads();                                    /* sync 1 */

            float mo0 = m_sm[mcur + r0], mo1 = m_sm[mcur + r0 + 8];
            float mn0 = fmaxf(mo0, fmaxf(mpart[r0], mpart[64 + r0]));
            float mn1 = fmaxf(mo1, fmaxf(mpart[r0 + 8], mpart[64 + r0 + 8]));
            float p00 = (sc[0][0] < -1e29f) ? 0.0f : __expf(sc[0][0] - mn0);
            float p01 = (sc[0][1] < -1e29f) ? 0.0f : __expf(sc[0][1] - mn0);
            float p10 = (sc[1][0] < -1e29f) ? 0.0f : __expf(sc[1][0] - mn0);
            float p11 = (sc[1][1] < -1e29f) ? 0.0f : __expf(sc[1][1] - mn0);
            float q00 = (sc[0][2] < -1e29f) ? 0.0f : __expf(sc[0][2] - mn1);
            float q01 = (sc[0][3] < -1e29f) ? 0.0f : __expf(sc[0][3] - mn1);
            float q10 = (sc[1][2] < -1e29f) ? 0.0f : __expf(sc[1][2] - mn1);
            float q11 = (sc[1][3] < -1e29f) ? 0.0f : __expf(sc[1][3] - mn1);
            {
                uint32_t bo;
                bo = (uint32_t)(r0 * 128 + c0 * 2);
                *(uint32_t*)(smemc + PHOFF + (bo ^ ((bo >> 3) & 0x70)))
                    = (uint32_t)h_rn(p00) | ((uint32_t)h_rn(p01) << 16);
                bo = (uint32_t)(r0 * 128 + (c0 + 8) * 2);
                *(uint32_t*)(smemc + PHOFF + (bo ^ ((bo >> 3) & 0x70)))
                    = (uint32_t)h_rn(p10) | ((uint32_t)h_rn(p11) << 16);
                bo = (uint32_t)((r0 + 8) * 128 + c0 * 2);
                *(uint32_t*)(smemc + PHOFF + (bo ^ ((bo >> 3) & 0x70)))
                    = (uint32_t)h_rn(q00) | ((uint32_t)h_rn(q01) << 16);
                bo = (uint32_t)((r0 + 8) * 128 + (c0 + 8) * 2);
                *(uint32_t*)(smemc + PHOFF + (bo ^ ((bo >> 3) & 0x70)))
                    = (uint32_t)h_rn(q10) | ((uint32_t)h_rn(q11) << 16);
            }
            float ps0 = p00 + p01 + p10 + p11;
            float ps1 = q00 + q01 + q10 + q11;
            ps0 += __shfl_xor_sync(0xffffffffu, ps0, 1);
            ps0 += __shfl_xor_sync(0xffffffffu, ps0, 2);
            ps1 += __shfl_xor_sync(0xffffffffu, ps1, 1);
            ps1 += __shfl_xor_sync(0xffffffffu, ps1, 2);
            lp0 = lp0 * __expf(mo0 - mn0) + ps0;
            lp1 = lp1 * __expf(mo1 - mn1) + ps1;
            if (wn == 0 && (lid & 3) == 0) {
                m_sm[mnxt + r0]     = mn0;
                m_sm[mnxt + r0 + 8] = mn1;
            }
        }
        __syncthreads();                                        /* sync 2 */

        /* ---- rescale + PV ---- */
        {
#pragma unroll
            for (int mt = 0; mt < 2; mt++) {
                int rp = wm2 * 32 + mt * 16 + (lid >> 2);
#pragma unroll
                for (int sub = 0; sub < 2; sub++) {
                    int r = rp + sub * 8;
                    float mo = m_sm[mcur + r];
                    float mn = fmaxf(mo, fmaxf(mpart[r], mpart[64 + r]));
                    float corr = __expf(mo - mn);
#pragma unroll
                    for (int nt = 0; nt < 8; nt++) {
                        acc_o[mt][nt][sub * 2 + 0] *= corr;
                        acc_o[mt][nt][sub * 2 + 1] *= corr;
                    }
                }
            }
            uint32_t vhb = sbase + VHOFF + st * 16384 + wn2 * 4096;
#pragma unroll
            for (int ks2 = 0; ks2 < 2; ks2++) {
                uint32_t pa_h[2][4];
#pragma unroll
                for (int mt = 0; mt < 2; mt++) {
                    int rA2 = wm2 * 32 + mt * 16 + (lid & 15);
                    uint32_t bo = swz((uint32_t)(rA2 * 128 + (ks2 * 2 + (lid >> 4)) * 16));
                    ldm4(pa_h[mt], sbase + PHOFF + bo);
                }
#pragma unroll
                for (int nn = 0; nn < 4; nn++) {
                    int tl = lid >> 3;
                    int srow = (tl & 1) * 8 + (lid & 7) + ks2 * 16;
                    uint32_t bo = swz((uint32_t)(srow * 128 + (nn * 16 + (tl >> 1) * 8) * 2));
                    uint32_t bvh[4];
                    ldm4t(bvh, vhb + bo);
#pragma unroll
                    for (int mt = 0; mt < 2; mt++)
#pragma unroll
                        for (int h = 0; h < 2; h++)
                            mma16816(acc_o[mt][nn * 2 + h], pa_h[mt],
                                     bvh[h * 2], bvh[h * 2 + 1]);
                }
            }
        }
    }

    /* final l exchange: both warp groups' partials -> spart */
    if ((lid & 3) == 0) {
        spart[wn * 64 + r0]     = lp0;
        spart[wn * 64 + r0 + 8] = lp1;
    }
    __syncthreads();

    /* ---- epilogue: normalize, single-fp16 store ---- */
#pragma unroll
    for (int mt = 0; mt < 2; mt++) {
        int rb = wm2 * 32 + mt * 16 + (lid >> 2);
#pragma unroll
        for (int sub = 0; sub < 2; sub++) {
            int r = rb + sub * 8;
            float inv = 1.0f / (spart[r] + spart[64 + r]);
            int tq = tq0 + (r & 31);
            int n = khead * 2 + (r >> 5);
            size_t base = ((size_t)(b * TT + tq)) * 4096 + n * HDIM
                        + wn2 * 64 + (lid & 3) * 2;
#pragma unroll
            for (int nt = 0; nt < 8; nt++) {
                float o0 = acc_o[mt][nt][sub * 2 + 0] * inv;
                float o1 = acc_o[mt][nt][sub * 2 + 1] * inv;
                *(uint32_t*)(ench + base + nt * 8)
                    = (uint32_t)h_rn(o0) | ((uint32_t)h_rn(o1) << 16);
            }
        }
    }
}

/* ---------------- host launcher ---------------- */
extern "C" void kernel_launch(void* const* d_in, const int* in_sizes, int n_in,
                              void* d_out, int out_size)
{
    const float* x      = (const float*)d_in[0];
    const int*   segpos = (const int*)d_in[1];
    const float* q_w    = (const float*)d_in[3];
    const float* kv_w   = (const float*)d_in[4];
    const float* out_w  = (const float*)d_in[5];
    float* out = (float*)d_out;

    void *wt, *owt, *xh, *ench, *qkvh, *khb, *vhb;
    cudaGetSymbolAddress(&wt,    g_wt);
    cudaGetSymbolAddress(&owt,   g_owt);
    cudaGetSymbolAddress(&xh,    g_xh);
    cudaGetSymbolAddress(&ench,  g_ench);
    cudaGetSymbolAddress(&qkvh,  g_qkvh);
    cudaGetSymbolAddress(&khb,   g_kh);
    cudaGetSymbolAddress(&vhb,   g_vh);

    cudaFuncSetAttribute(gemm_mma, cudaFuncAttributeMaxDynamicSharedMemorySize, GSMEM);
    cudaFuncSetAttribute(attn_mma, cudaFuncAttributeMaxDynamicSharedMemorySize, ASMEM);

    /* prep */
    trans_qkv_w<<<dim3(8192 / 32, DD / 32), 256>>>(q_w, kv_w);
    trans_ow<<<dim3(DD / 32, 4096 / 32), 256>>>(out_w);
    {
        int n4 = MTOT * DD / 4;
        convert_single<<<(n4 + 255) / 256, 256>>>((const float4*)x, (ushort4*)xh, n4);
    }
    ts_kernel<<<1, 128>>>();
    sc_kernel<<<MTOT * 128 / 256, 256>>>(segpos);

    /* GEMM1: [Q|K] fp16 -> g_qkvh, V fp16 -> g_vh */
    gemm_mma<<<dim3(8192 / 128, MTOT / 256), 256, GSMEM>>>(
        (const __half*)xh, DD,
        (const __half*)wt, DD,
        (float*)0, 0, DD, (__half*)qkvh, (__half*)vhb);

    /* RoPE: K only (Q roped inside attention) */
    {
        int totk = MTOT * KHE * 128;
        rope_k<<<(totk + 255) / 256, 256>>>((const __half*)qkvh,
                                            (unsigned short*)khb, totk);
    }

    /* attention -> ench */
    attn_mma<<<dim3(TT / AQ, KHE, BB), 256, ASMEM>>>(
        (const __half*)qkvh, (const __half*)khb, (const __half*)vhb,
        segpos,
        (__half*)ench);

    /* GEMM2: out = enc @ out_w  (M=4096, N=3584, K=4096) */
    gemm_mma<<<dim3(DD / 128, MTOT / 256), 256, GSMEM>>>(
        (const __half*)ench, 4096,
        (const __half*)owt, 4096,
        out, DD, 4096, (__half*)0, (__half*)0);
}